// round 5
// baseline (speedup 1.0000x reference)
#include <cuda_runtime.h>
#include <math.h>
#include <stdint.h>

// Problem constants
#define LAYERS 4
#define S 2048
#define D 1024
#define HQ 16
#define KVH 4
#define HD 64
#define II 4096
#define VV 32000
#define EPSV 1e-6f

// ---------------- scratch (device globals; no allocations allowed) ----------
__device__ float g_h[S * D];            // residual stream
__device__ float g_x[S * D];            // normed activations
__device__ float g_q[S * HQ * HD];
__device__ float g_k[S * KVH * HD];
__device__ float g_v[S * KVH * HD];
__device__ float g_o[S * HQ * HD];
__device__ float g_gate[S * II];
__device__ float g_up[S * II];
__device__ float g_cos[S * 32];
__device__ float g_sin[S * 32];

// ---------------- RoPE table (double-precision trig: fast-math safe) --------
__global__ void rope_table_kernel() {
    int idx = blockIdx.x * blockDim.x + threadIdx.x;
    if (idx >= S * 32) return;
    int s = idx >> 5, i = idx & 31;
    double invf = exp(-((double)(2 * i) / (double)HD) * log(10000.0));
    float invf_f = (float)invf;
    float af = (float)s * invf_f;
    g_cos[idx] = (float)cos((double)af);
    g_sin[idx] = (float)sin((double)af);
}

// ---------------- embedding gather ------------------------------------------
__global__ void embed_kernel(const float* __restrict__ embed,
                             const int* __restrict__ ids) {
    int idx = blockIdx.x * blockDim.x + threadIdx.x;   // over S*D/4
    int s = idx / (D / 4);
    int c = idx % (D / 4);
    float4 v = ((const float4*)(embed + (size_t)ids[s] * D))[c];
    ((float4*)(g_h + (size_t)s * D))[c] = v;
}

// ---------------- RMSNorm ----------------------------------------------------
__global__ void rmsnorm_kernel(const float* __restrict__ X,
                               const float* __restrict__ w,
                               float* __restrict__ Y) {
    int row = blockIdx.x;
    const float* x = X + (size_t)row * D;
    float ss = 0.f;
    for (int i = threadIdx.x; i < D; i += blockDim.x) {
        float v = x[i];
        ss = fmaf(v, v, ss);
    }
    __shared__ float sred[32];
    #pragma unroll
    for (int off = 16; off; off >>= 1) ss += __shfl_xor_sync(0xffffffffu, ss, off);
    int wid = threadIdx.x >> 5, lid = threadIdx.x & 31;
    if (lid == 0) sred[wid] = ss;
    __syncthreads();
    if (wid == 0) {
        ss = (lid < (int)(blockDim.x >> 5)) ? sred[lid] : 0.f;
        #pragma unroll
        for (int off = 16; off; off >>= 1) ss += __shfl_xor_sync(0xffffffffu, ss, off);
        if (lid == 0) sred[0] = ss;
    }
    __syncthreads();
    float inv = rsqrtf(sred[0] / (float)D + EPSV);
    for (int i = threadIdx.x; i < D; i += blockDim.x)
        Y[(size_t)row * D + i] = w[i] * (x[i] * inv);
}

// ---------------- RoPE apply (in place) -------------------------------------
__global__ void rope_kernel(float* __restrict__ X, int nheads) {
    int idx = blockIdx.x * blockDim.x + threadIdx.x;
    int total = S * nheads * 32;
    if (idx >= total) return;
    int i = idx & 31;
    int h = (idx >> 5) % nheads;
    int s = idx / (32 * nheads);
    float c = g_cos[s * 32 + i], sn = g_sin[s * 32 + i];
    float* p = X + (size_t)s * nheads * HD + h * HD;
    float x1 = p[i], x2 = p[i + 32];
    p[i]      = x1 * c - x2 * sn;
    p[i + 32] = x2 * c + x1 * sn;
}

// ---------------- SiLU(gate) * up  (in place into g_gate) -------------------
__global__ void silu_mul_kernel() {
    int idx = blockIdx.x * blockDim.x + threadIdx.x;
    float4 g = ((const float4*)g_gate)[idx];
    float4 u = ((const float4*)g_up)[idx];
    g.x = g.x / (1.f + expf(-g.x)) * u.x;
    g.y = g.y / (1.f + expf(-g.y)) * u.y;
    g.z = g.z / (1.f + expf(-g.z)) * u.z;
    g.w = g.w / (1.f + expf(-g.w)) * u.w;
    ((float4*)g_gate)[idx] = g;
}

// ==================== 3xTF32 tensor-core GEMM ================================
// C[M,N] = A[M,K] @ B[K,N], row-major. mode 0: C = acc + bias; mode 1: C += acc
// hi/lo split at STS; product = hi*hi + hi*lo + lo*hi (fp32 accum).
// Block tile 128x128, 512 threads / 16 warps, warp tile 32x32, BK=16.

struct GemmSeg {
    const float* B;
    const float* bias;
    float* C;
    int N;
    int nx;   // number of block-columns for this segment
};

__device__ __forceinline__ uint32_t f2tf32(float f) {
    uint32_t u;
    asm("cvt.rna.tf32.f32 %0, %1;" : "=r"(u) : "f"(f));
    return u;
}

#define MMA_TF32(c, a, b)                                                     \
    asm volatile(                                                             \
        "mma.sync.aligned.m16n8k8.row.col.f32.tf32.tf32.f32 "                 \
        "{%0,%1,%2,%3},{%4,%5,%6,%7},{%8,%9},{%0,%1,%2,%3};"                  \
        : "+f"(c[0]), "+f"(c[1]), "+f"(c[2]), "+f"(c[3])                      \
        : "r"(a.x), "r"(a.y), "r"(a.z), "r"(a.w), "r"(b.x), "r"(b.y))

// A frag-layout offset (tile-local m in [0,128), k in [0,16))
__device__ __forceinline__ int offA(int m, int k) {
    int lane = ((m & 7) << 2) + (k & 3);
    int reg = ((m >> 3) & 1) + 2 * ((k >> 2) & 1);
    return ((k >> 3) * 8 + (m >> 4)) * 132 + lane * 4 + reg;
}
// B frag-layout offset (k in [0,16), tile-local n in [0,128))
__device__ __forceinline__ int offB(int k, int n) {
    int lane = ((n & 7) << 2) + (k & 3);
    int reg = (k >> 2) & 1;
    return ((k >> 3) * 16 + (n >> 3)) * 66 + lane * 2 + reg;
}

__global__ void __launch_bounds__(512, 1)
mm_kernel(const float* __restrict__ A, GemmSeg s0, GemmSeg s1, GemmSeg s2,
          int K, int mode) {
    constexpr int T = 512;
    constexpr int BN = 128;
    constexpr int BK = 16;
    constexpr int ASZ = 2112;   // uint32 per A buffer per precision (16 blk * 132)
    constexpr int BSZ = 2112;   // uint32 per B buffer per precision (32 blk * 66)

    extern __shared__ float sm[];
    uint32_t* smA = (uint32_t*)sm;                  // [buf2][prec2][ASZ]
    uint32_t* smB = (uint32_t*)(sm + 4 * ASZ);      // [buf2][prec2][BSZ]

    // segment select
    int bx = blockIdx.x;
    const float* Bp;
    const float* bias;
    float* Cp;
    int N;
    if (bx < s0.nx) {
        Bp = s0.B; bias = s0.bias; Cp = s0.C; N = s0.N;
    } else if (bx < s0.nx + s1.nx) {
        bx -= s0.nx;
        Bp = s1.B; bias = s1.bias; Cp = s1.C; N = s1.N;
    } else {
        bx -= s0.nx + s1.nx;
        Bp = s2.B; bias = s2.bias; Cp = s2.C; N = s2.N;
    }
    const int row0 = blockIdx.y * 128;
    const int col0 = bx * BN;

    const int tid = threadIdx.x;
    const int lane = tid & 31;
    const int warp = tid >> 5;     // 0..15
    const int wm = warp & 3;       // rows wm*32
    const int wn = warp >> 2;      // cols wn*32

    float acc[2][4][4];
    #pragma unroll
    for (int i = 0; i < 2; i++)
        #pragma unroll
        for (int j = 0; j < 4; j++)
            #pragma unroll
            for (int r = 0; r < 4; r++) acc[i][j][r] = 0.f;

    // per-thread LDG coords (1 float4 each for A and B)
    const int ar = tid >> 2, ac4 = (tid & 3) << 2;          // A: 128x16
    const int bk = tid >> 5, bn4 = (tid & 31) << 2;         // B: 16x128

    float4 av, bv;
    auto ldg_tile = [&](int k0) {
        av = *(const float4*)(A + (size_t)(row0 + ar) * K + k0 + ac4);
        bv = *(const float4*)(Bp + (size_t)(k0 + bk) * N + col0 + bn4);
    };
    auto sts_tile = [&](int buf) {
        uint32_t* a_hi = smA + buf * 2 * ASZ;
        uint32_t* a_lo = a_hi + ASZ;
        uint32_t* b_hi = smB + buf * 2 * BSZ;
        uint32_t* b_lo = b_hi + BSZ;
        const float af4[4] = {av.x, av.y, av.z, av.w};
        const float bf4[4] = {bv.x, bv.y, bv.z, bv.w};
        #pragma unroll
        for (int j = 0; j < 4; j++) {
            int oa = offA(ar, ac4 + j);
            uint32_t h = f2tf32(af4[j]);
            a_hi[oa] = h;
            a_lo[oa] = f2tf32(af4[j] - __uint_as_float(h));
            int ob = offB(bk, bn4 + j);
            uint32_t hb = f2tf32(bf4[j]);
            b_hi[ob] = hb;
            b_lo[ob] = f2tf32(bf4[j] - __uint_as_float(hb));
        }
    };

    const int ntiles = K / BK;
    ldg_tile(0);
    sts_tile(0);
    __syncthreads();

    int cur = 0;
    for (int it = 0; it < ntiles; it++) {
        bool has_next = (it + 1 < ntiles);
        if (has_next) ldg_tile((it + 1) * BK);

        const uint32_t* Ahi = smA + cur * 2 * ASZ;
        const uint32_t* Alo = Ahi + ASZ;
        const uint32_t* Bhi = smB + cur * 2 * BSZ;
        const uint32_t* Blo = Bhi + BSZ;
        #pragma unroll
        for (int ks = 0; ks < 2; ks++) {
            uint4 af[2];
            uint2 bf[4], bf2[4];
            #pragma unroll
            for (int mf = 0; mf < 2; mf++)
                af[mf] = *(const uint4*)&Ahi[(ks * 8 + wm * 2 + mf) * 132 + lane * 4];
            #pragma unroll
            for (int nf = 0; nf < 4; nf++)
                bf[nf] = *(const uint2*)&Bhi[(ks * 16 + wn * 4 + nf) * 66 + lane * 2];
            // pass 1: hi * hi
            #pragma unroll
            for (int mf = 0; mf < 2; mf++)
                #pragma unroll
                for (int nf = 0; nf < 4; nf++)
                    MMA_TF32(acc[mf][nf], af[mf], bf[nf]);
            // pass 2: hi * lo(B)
            #pragma unroll
            for (int nf = 0; nf < 4; nf++)
                bf2[nf] = *(const uint2*)&Blo[(ks * 16 + wn * 4 + nf) * 66 + lane * 2];
            #pragma unroll
            for (int mf = 0; mf < 2; mf++)
                #pragma unroll
                for (int nf = 0; nf < 4; nf++)
                    MMA_TF32(acc[mf][nf], af[mf], bf2[nf]);
            // pass 3: lo(A) * hi  (reuse af registers)
            #pragma unroll
            for (int mf = 0; mf < 2; mf++)
                af[mf] = *(const uint4*)&Alo[(ks * 8 + wm * 2 + mf) * 132 + lane * 4];
            #pragma unroll
            for (int mf = 0; mf < 2; mf++)
                #pragma unroll
                for (int nf = 0; nf < 4; nf++)
                    MMA_TF32(acc[mf][nf], af[mf], bf[nf]);
        }

        if (has_next) sts_tile(cur ^ 1);
        __syncthreads();
        cur ^= 1;
    }

    // epilogue
    const int g = lane >> 2, tg = lane & 3;
    #pragma unroll
    for (int nf = 0; nf < 4; nf++) {
        int cc = col0 + wn * 32 + nf * 8 + tg * 2;
        float b0 = 0.f, b1 = 0.f;
        if (mode == 0 && bias) { b0 = bias[cc]; b1 = bias[cc + 1]; }
        #pragma unroll
        for (int mf = 0; mf < 2; mf++) {
            int rr = row0 + wm * 32 + mf * 16 + g;
            float2* p0 = (float2*)&Cp[(size_t)rr * N + cc];
            float2* p1 = (float2*)&Cp[(size_t)(rr + 8) * N + cc];
            if (mode == 0) {
                *p0 = make_float2(acc[mf][nf][0] + b0, acc[mf][nf][1] + b1);
                *p1 = make_float2(acc[mf][nf][2] + b0, acc[mf][nf][3] + b1);
            } else {
                float2 o0 = *p0, o1 = *p1;
                o0.x += acc[mf][nf][0]; o0.y += acc[mf][nf][1];
                o1.x += acc[mf][nf][2]; o1.y += acc[mf][nf][3];
                *p0 = o0; *p1 = o1;
            }
        }
    }
}

// ---------------- Fused causal GQA attention (fp32 flash-style) -------------
#define AKV 64
__global__ void __launch_bounds__(128)
attn_kernel() {
    __shared__ float Ks[AKV][HD];
    __shared__ float Vs[AKV][HD];

    const int hq = blockIdx.y;
    const int kvh = hq >> 2;
    const int row = blockIdx.x * 128 + threadIdx.x;

    float qr[HD];
    #pragma unroll
    for (int d = 0; d < HD; d += 4) {
        float4 t = *(const float4*)&g_q[(size_t)row * (HQ * HD) + hq * HD + d];
        qr[d] = t.x; qr[d + 1] = t.y; qr[d + 2] = t.z; qr[d + 3] = t.w;
    }
    float o[HD];
    #pragma unroll
    for (int d = 0; d < HD; d++) o[d] = 0.f;
    float m = -INFINITY, l = 0.f;

    const int kend = (blockIdx.x + 1) * 128;
    for (int j0 = 0; j0 < kend; j0 += AKV) {
        __syncthreads();
        for (int t = threadIdx.x; t < AKV * (HD / 4); t += 128) {
            int r = t / (HD / 4);
            int c = (t % (HD / 4)) * 4;
            size_t gofs = (size_t)(j0 + r) * (KVH * HD) + kvh * HD + c;
            *(float4*)&Ks[r][c] = *(const float4*)&g_k[gofs];
            *(float4*)&Vs[r][c] = *(const float4*)&g_v[gofs];
        }
        __syncthreads();

        int jmax = row + 1 - j0;
        if (jmax > AKV) jmax = AKV;
        for (int j = 0; j < jmax; j++) {
            float s0 = 0.f, s1 = 0.f, s2 = 0.f, s3 = 0.f;
            #pragma unroll
            for (int d = 0; d < HD; d += 4) {
                float4 kk4 = *(const float4*)&Ks[j][d];
                s0 = fmaf(qr[d],     kk4.x, s0);
                s1 = fmaf(qr[d + 1], kk4.y, s1);
                s2 = fmaf(qr[d + 2], kk4.z, s2);
                s3 = fmaf(qr[d + 3], kk4.w, s3);
            }
            float s = ((s0 + s1) + (s2 + s3)) * 0.125f;
            if (s > m) {
                float corr = expf(m - s);
                l *= corr;
                #pragma unroll
                for (int d = 0; d < HD; d++) o[d] *= corr;
                m = s;
            }
            float p = expf(s - m);
            l += p;
            #pragma unroll
            for (int d = 0; d < HD; d += 4) {
                float4 vv = *(const float4*)&Vs[j][d];
                o[d]     = fmaf(p, vv.x, o[d]);
                o[d + 1] = fmaf(p, vv.y, o[d + 1]);
                o[d + 2] = fmaf(p, vv.z, o[d + 2]);
                o[d + 3] = fmaf(p, vv.w, o[d + 3]);
            }
        }
    }

    float inv = 1.f / l;
    #pragma unroll
    for (int d = 0; d < HD; d += 4) {
        float4 t = make_float4(o[d] * inv, o[d + 1] * inv, o[d + 2] * inv, o[d + 3] * inv);
        *(float4*)&g_o[(size_t)row * (HQ * HD) + hq * HD + d] = t;
    }
}

// ---------------- host side ---------------------------------------------------
static const int SMEMB = (4 * 2112 + 4 * 2112) * 4;   // 67584 B

static GemmSeg mkseg(const float* B, const float* bias, float* C, int N, int nx) {
    GemmSeg s; s.B = B; s.bias = bias; s.C = C; s.N = N; s.nx = nx; return s;
}

extern "C" void kernel_launch(void* const* d_in, const int* in_sizes, int n_in,
                              void* d_out, int out_size) {
    const float* embed  = (const float*)d_in[0];
    const float* ln1    = (const float*)d_in[1];
    const float* qw     = (const float*)d_in[2];
    const float* qb     = (const float*)d_in[3];
    const float* kw     = (const float*)d_in[4];
    const float* kb     = (const float*)d_in[5];
    const float* vw     = (const float*)d_in[6];
    const float* vb     = (const float*)d_in[7];
    const float* ow     = (const float*)d_in[8];
    const float* ln2    = (const float*)d_in[9];
    const float* gw     = (const float*)d_in[10];
    const float* uw     = (const float*)d_in[11];
    const float* dw     = (const float*)d_in[12];
    const float* norm_w = (const float*)d_in[13];
    const float* lm_w   = (const float*)d_in[14];
    const int*   ids    = (const int*)d_in[15];
    float* out = (float*)d_out;

    float *p_h, *p_x, *p_q, *p_k, *p_v, *p_o, *p_gate, *p_up;
    cudaGetSymbolAddress((void**)&p_h, g_h);
    cudaGetSymbolAddress((void**)&p_x, g_x);
    cudaGetSymbolAddress((void**)&p_q, g_q);
    cudaGetSymbolAddress((void**)&p_k, g_k);
    cudaGetSymbolAddress((void**)&p_v, g_v);
    cudaGetSymbolAddress((void**)&p_o, g_o);
    cudaGetSymbolAddress((void**)&p_gate, g_gate);
    cudaGetSymbolAddress((void**)&p_up, g_up);

    static bool attr_done = false;
    if (!attr_done) {
        cudaFuncSetAttribute(mm_kernel, cudaFuncAttributeMaxDynamicSharedMemorySize, SMEMB);
        attr_done = true;
    }

    GemmSeg z = mkseg(nullptr, nullptr, nullptr, 0, 0);

    rope_table_kernel<<<(S * 32 + 255) / 256, 256>>>();
    embed_kernel<<<(S * D / 4) / 256, 256>>>(embed, ids);

    for (int l = 0; l < LAYERS; l++) {
        rmsnorm_kernel<<<S, 256>>>(p_h, ln1 + (size_t)l * D, p_x);

        // fused QKV projection: Q=8 blocks, K=2, V=2 (N=256 each for K/V)
        {
            GemmSeg sq = mkseg(qw + (size_t)l * D * HQ * HD, qb + (size_t)l * HQ * HD, p_q, HQ * HD, 8);
            GemmSeg sk = mkseg(kw + (size_t)l * D * KVH * HD, kb + (size_t)l * KVH * HD, p_k, KVH * HD, 2);
            GemmSeg sv = mkseg(vw + (size_t)l * D * KVH * HD, vb + (size_t)l * KVH * HD, p_v, KVH * HD, 2);
            mm_kernel<<<dim3(12, 16), 512, SMEMB>>>(p_x, sq, sk, sv, D, 0);
        }
        rope_kernel<<<(S * HQ * 32) / 256, 256>>>(p_q, HQ);
        rope_kernel<<<(S * KVH * 32) / 256, 256>>>(p_k, KVH);
        attn_kernel<<<dim3(S / 128, HQ), 128>>>();

        // O projection: h += o @ ow
        {
            GemmSeg so = mkseg(ow + (size_t)l * HQ * HD * D, nullptr, p_h, D, 8);
            mm_kernel<<<dim3(8, 16), 512, SMEMB>>>(p_o, so, z, z, HQ * HD, 1);
        }
        rmsnorm_kernel<<<S, 256>>>(p_h, ln2 + (size_t)l * D, p_x);

        // fused gate+up
        {
            GemmSeg sg = mkseg(gw + (size_t)l * D * II, nullptr, p_gate, II, 32);
            GemmSeg su = mkseg(uw + (size_t)l * D * II, nullptr, p_up, II, 32);
            mm_kernel<<<dim3(64, 16), 512, SMEMB>>>(p_x, sg, su, z, D, 0);
        }
        silu_mul_kernel<<<(S * II / 4) / 256, 256>>>();

        // down projection: h += act @ dw
        {
            GemmSeg sd = mkseg(dw + (size_t)l * II * D, nullptr, p_h, D, 8);
            mm_kernel<<<dim3(8, 16), 512, SMEMB>>>(p_gate, sd, z, z, II, 1);
        }
    }

    rmsnorm_kernel<<<S, 256>>>(p_h, norm_w, p_x);
    {
        GemmSeg sl = mkseg(lm_w, nullptr, out, VV, 250);
        mm_kernel<<<dim3(250, 16), 512, SMEMB>>>(p_x, sl, z, z, D, 0);
    }
}

// round 6
// speedup vs baseline: 1.0004x; 1.0004x over previous
#include <cuda_runtime.h>
#include <math.h>
#include <stdint.h>

// Problem constants
#define LAYERS 4
#define S 2048
#define D 1024
#define HQ 16
#define KVH 4
#define HD 64
#define II 4096
#define VV 32000
#define EPSV 1e-6f

// ---------------- scratch (device globals; no allocations allowed) ----------
__device__ float g_h[S * D];            // residual stream
__device__ float g_x[S * D];            // normed activations
__device__ float g_q[S * HQ * HD];
__device__ float g_k[S * KVH * HD];
__device__ float g_v[S * KVH * HD];
__device__ float g_o[S * HQ * HD];
__device__ float g_gate[S * II];
__device__ float g_up[S * II];
__device__ float g_cos[S * 32];
__device__ float g_sin[S * 32];

// ---------------- RoPE table (double-precision trig: fast-math safe) --------
__global__ void rope_table_kernel() {
    int idx = blockIdx.x * blockDim.x + threadIdx.x;
    if (idx >= S * 32) return;
    int s = idx >> 5, i = idx & 31;
    double invf = exp(-((double)(2 * i) / (double)HD) * log(10000.0));
    float invf_f = (float)invf;
    float af = (float)s * invf_f;
    g_cos[idx] = (float)cos((double)af);
    g_sin[idx] = (float)sin((double)af);
}

// ---------------- embedding gather ------------------------------------------
__global__ void embed_kernel(const float* __restrict__ embed,
                             const int* __restrict__ ids) {
    int idx = blockIdx.x * blockDim.x + threadIdx.x;   // over S*D/4
    int s = idx / (D / 4);
    int c = idx % (D / 4);
    float4 v = ((const float4*)(embed + (size_t)ids[s] * D))[c];
    ((float4*)(g_h + (size_t)s * D))[c] = v;
}

// ---------------- RMSNorm ----------------------------------------------------
__global__ void rmsnorm_kernel(const float* __restrict__ X,
                               const float* __restrict__ w,
                               float* __restrict__ Y) {
    int row = blockIdx.x;
    const float* x = X + (size_t)row * D;
    float ss = 0.f;
    for (int i = threadIdx.x; i < D; i += blockDim.x) {
        float v = x[i];
        ss = fmaf(v, v, ss);
    }
    __shared__ float sred[32];
    #pragma unroll
    for (int off = 16; off; off >>= 1) ss += __shfl_xor_sync(0xffffffffu, ss, off);
    int wid = threadIdx.x >> 5, lid = threadIdx.x & 31;
    if (lid == 0) sred[wid] = ss;
    __syncthreads();
    if (wid == 0) {
        ss = (lid < (int)(blockDim.x >> 5)) ? sred[lid] : 0.f;
        #pragma unroll
        for (int off = 16; off; off >>= 1) ss += __shfl_xor_sync(0xffffffffu, ss, off);
        if (lid == 0) sred[0] = ss;
    }
    __syncthreads();
    float inv = rsqrtf(sred[0] / (float)D + EPSV);
    for (int i = threadIdx.x; i < D; i += blockDim.x)
        Y[(size_t)row * D + i] = w[i] * (x[i] * inv);
}

// ---------------- RoPE apply (in place) -------------------------------------
__global__ void rope_kernel(float* __restrict__ X, int nheads) {
    int idx = blockIdx.x * blockDim.x + threadIdx.x;
    int total = S * nheads * 32;
    if (idx >= total) return;
    int i = idx & 31;
    int h = (idx >> 5) % nheads;
    int s = idx / (32 * nheads);
    float c = g_cos[s * 32 + i], sn = g_sin[s * 32 + i];
    float* p = X + (size_t)s * nheads * HD + h * HD;
    float x1 = p[i], x2 = p[i + 32];
    p[i]      = x1 * c - x2 * sn;
    p[i + 32] = x2 * c + x1 * sn;
}

// ---------------- SiLU(gate) * up  (in place into g_gate) -------------------
__global__ void silu_mul_kernel() {
    int idx = blockIdx.x * blockDim.x + threadIdx.x;
    float4 g = ((const float4*)g_gate)[idx];
    float4 u = ((const float4*)g_up)[idx];
    g.x = g.x / (1.f + expf(-g.x)) * u.x;
    g.y = g.y / (1.f + expf(-g.y)) * u.y;
    g.z = g.z / (1.f + expf(-g.z)) * u.z;
    g.w = g.w / (1.f + expf(-g.w)) * u.w;
    ((float4*)g_gate)[idx] = g;
}

// ==================== 3xTF32 tensor-core GEMM ================================
// C[M,N] = A[M,K] @ B[K,N], row-major. mode 0: C = acc + bias; mode 1: C += acc
// hi/lo split at STS; product = hi*hi + hi*lo + lo*hi (fp32 accum).
// Block tile 128x128, 512 threads / 16 warps, warp tile 32x32, BK=16.

struct GemmSeg {
    const float* B;
    const float* bias;
    float* C;
    int N;
    int nx;   // number of block-columns for this segment
};

__device__ __forceinline__ uint32_t f2tf32(float f) {
    uint32_t u;
    asm("cvt.rna.tf32.f32 %0, %1;" : "=r"(u) : "f"(f));
    return u;
}

#define MMA_TF32(c, a, b)                                                     \
    asm volatile(                                                             \
        "mma.sync.aligned.m16n8k8.row.col.f32.tf32.tf32.f32 "                 \
        "{%0,%1,%2,%3},{%4,%5,%6,%7},{%8,%9},{%0,%1,%2,%3};"                  \
        : "+f"(c[0]), "+f"(c[1]), "+f"(c[2]), "+f"(c[3])                      \
        : "r"(a.x), "r"(a.y), "r"(a.z), "r"(a.w), "r"(b.x), "r"(b.y))

// A frag-layout offset (tile-local m in [0,128), k in [0,16))
__device__ __forceinline__ int offA(int m, int k) {
    int lane = ((m & 7) << 2) + (k & 3);
    int reg = ((m >> 3) & 1) + 2 * ((k >> 2) & 1);
    return ((k >> 3) * 8 + (m >> 4)) * 132 + lane * 4 + reg;
}
// B frag-layout offset (k in [0,16), tile-local n in [0,128))
__device__ __forceinline__ int offB(int k, int n) {
    int lane = ((n & 7) << 2) + (k & 3);
    int reg = (k >> 2) & 1;
    return ((k >> 3) * 16 + (n >> 3)) * 66 + lane * 2 + reg;
}

__global__ void __launch_bounds__(512, 1)
mm_kernel(const float* __restrict__ A, GemmSeg s0, GemmSeg s1, GemmSeg s2,
          int K, int mode) {
    constexpr int T = 512;
    constexpr int BN = 128;
    constexpr int BK = 16;
    constexpr int ASZ = 2112;   // uint32 per A buffer per precision (16 blk * 132)
    constexpr int BSZ = 2112;   // uint32 per B buffer per precision (32 blk * 66)

    extern __shared__ float sm[];
    uint32_t* smA = (uint32_t*)sm;                  // [buf2][prec2][ASZ]
    uint32_t* smB = (uint32_t*)(sm + 4 * ASZ);      // [buf2][prec2][BSZ]

    // segment select
    int bx = blockIdx.x;
    const float* Bp;
    const float* bias;
    float* Cp;
    int N;
    if (bx < s0.nx) {
        Bp = s0.B; bias = s0.bias; Cp = s0.C; N = s0.N;
    } else if (bx < s0.nx + s1.nx) {
        bx -= s0.nx;
        Bp = s1.B; bias = s1.bias; Cp = s1.C; N = s1.N;
    } else {
        bx -= s0.nx + s1.nx;
        Bp = s2.B; bias = s2.bias; Cp = s2.C; N = s2.N;
    }
    const int row0 = blockIdx.y * 128;
    const int col0 = bx * BN;

    const int tid = threadIdx.x;
    const int lane = tid & 31;
    const int warp = tid >> 5;     // 0..15
    const int wm = warp & 3;       // rows wm*32
    const int wn = warp >> 2;      // cols wn*32

    float acc[2][4][4];
    #pragma unroll
    for (int i = 0; i < 2; i++)
        #pragma unroll
        for (int j = 0; j < 4; j++)
            #pragma unroll
            for (int r = 0; r < 4; r++) acc[i][j][r] = 0.f;

    // per-thread LDG coords (1 float4 each for A and B)
    const int ar = tid >> 2, ac4 = (tid & 3) << 2;          // A: 128x16
    const int bk = tid >> 5, bn4 = (tid & 31) << 2;         // B: 16x128

    float4 av, bv;
    auto ldg_tile = [&](int k0) {
        av = *(const float4*)(A + (size_t)(row0 + ar) * K + k0 + ac4);
        bv = *(const float4*)(Bp + (size_t)(k0 + bk) * N + col0 + bn4);
    };
    auto sts_tile = [&](int buf) {
        uint32_t* a_hi = smA + buf * 2 * ASZ;
        uint32_t* a_lo = a_hi + ASZ;
        uint32_t* b_hi = smB + buf * 2 * BSZ;
        uint32_t* b_lo = b_hi + BSZ;
        const float af4[4] = {av.x, av.y, av.z, av.w};
        const float bf4[4] = {bv.x, bv.y, bv.z, bv.w};
        #pragma unroll
        for (int j = 0; j < 4; j++) {
            int oa = offA(ar, ac4 + j);
            uint32_t h = f2tf32(af4[j]);
            a_hi[oa] = h;
            a_lo[oa] = f2tf32(af4[j] - __uint_as_float(h));
            int ob = offB(bk, bn4 + j);
            uint32_t hb = f2tf32(bf4[j]);
            b_hi[ob] = hb;
            b_lo[ob] = f2tf32(bf4[j] - __uint_as_float(hb));
        }
    };

    const int ntiles = K / BK;
    ldg_tile(0);
    sts_tile(0);
    __syncthreads();

    int cur = 0;
    for (int it = 0; it < ntiles; it++) {
        bool has_next = (it + 1 < ntiles);
        if (has_next) ldg_tile((it + 1) * BK);

        const uint32_t* Ahi = smA + cur * 2 * ASZ;
        const uint32_t* Alo = Ahi + ASZ;
        const uint32_t* Bhi = smB + cur * 2 * BSZ;
        const uint32_t* Blo = Bhi + BSZ;
        #pragma unroll
        for (int ks = 0; ks < 2; ks++) {
            uint4 af[2];
            uint2 bf[4], bf2[4];
            #pragma unroll
            for (int mf = 0; mf < 2; mf++)
                af[mf] = *(const uint4*)&Ahi[(ks * 8 + wm * 2 + mf) * 132 + lane * 4];
            #pragma unroll
            for (int nf = 0; nf < 4; nf++)
                bf[nf] = *(const uint2*)&Bhi[(ks * 16 + wn * 4 + nf) * 66 + lane * 2];
            // pass 1: hi * hi
            #pragma unroll
            for (int mf = 0; mf < 2; mf++)
                #pragma unroll
                for (int nf = 0; nf < 4; nf++)
                    MMA_TF32(acc[mf][nf], af[mf], bf[nf]);
            // pass 2: hi * lo(B)
            #pragma unroll
            for (int nf = 0; nf < 4; nf++)
                bf2[nf] = *(const uint2*)&Blo[(ks * 16 + wn * 4 + nf) * 66 + lane * 2];
            #pragma unroll
            for (int mf = 0; mf < 2; mf++)
                #pragma unroll
                for (int nf = 0; nf < 4; nf++)
                    MMA_TF32(acc[mf][nf], af[mf], bf2[nf]);
            // pass 3: lo(A) * hi  (reuse af registers)
            #pragma unroll
            for (int mf = 0; mf < 2; mf++)
                af[mf] = *(const uint4*)&Alo[(ks * 8 + wm * 2 + mf) * 132 + lane * 4];
            #pragma unroll
            for (int mf = 0; mf < 2; mf++)
                #pragma unroll
                for (int nf = 0; nf < 4; nf++)
                    MMA_TF32(acc[mf][nf], af[mf], bf[nf]);
        }

        if (has_next) sts_tile(cur ^ 1);
        __syncthreads();
        cur ^= 1;
    }

    // epilogue
    const int g = lane >> 2, tg = lane & 3;
    #pragma unroll
    for (int nf = 0; nf < 4; nf++) {
        int cc = col0 + wn * 32 + nf * 8 + tg * 2;
        float b0 = 0.f, b1 = 0.f;
        if (mode == 0 && bias) { b0 = bias[cc]; b1 = bias[cc + 1]; }
        #pragma unroll
        for (int mf = 0; mf < 2; mf++) {
            int rr = row0 + wm * 32 + mf * 16 + g;
            float2* p0 = (float2*)&Cp[(size_t)rr * N + cc];
            float2* p1 = (float2*)&Cp[(size_t)(rr + 8) * N + cc];
            if (mode == 0) {
                *p0 = make_float2(acc[mf][nf][0] + b0, acc[mf][nf][1] + b1);
                *p1 = make_float2(acc[mf][nf][2] + b0, acc[mf][nf][3] + b1);
            } else {
                float2 o0 = *p0, o1 = *p1;
                o0.x += acc[mf][nf][0]; o0.y += acc[mf][nf][1];
                o1.x += acc[mf][nf][2]; o1.y += acc[mf][nf][3];
                *p0 = o0; *p1 = o1;
            }
        }
    }
}

// ---------------- Fused causal GQA attention (fp32 flash-style) -------------
#define AKV 64
__global__ void __launch_bounds__(128)
attn_kernel() {
    __shared__ float Ks[AKV][HD];
    __shared__ float Vs[AKV][HD];

    const int hq = blockIdx.y;
    const int kvh = hq >> 2;
    const int row = blockIdx.x * 128 + threadIdx.x;

    float qr[HD];
    #pragma unroll
    for (int d = 0; d < HD; d += 4) {
        float4 t = *(const float4*)&g_q[(size_t)row * (HQ * HD) + hq * HD + d];
        qr[d] = t.x; qr[d + 1] = t.y; qr[d + 2] = t.z; qr[d + 3] = t.w;
    }
    float o[HD];
    #pragma unroll
    for (int d = 0; d < HD; d++) o[d] = 0.f;
    float m = -INFINITY, l = 0.f;

    const int kend = (blockIdx.x + 1) * 128;
    for (int j0 = 0; j0 < kend; j0 += AKV) {
        __syncthreads();
        for (int t = threadIdx.x; t < AKV * (HD / 4); t += 128) {
            int r = t / (HD / 4);
            int c = (t % (HD / 4)) * 4;
            size_t gofs = (size_t)(j0 + r) * (KVH * HD) + kvh * HD + c;
            *(float4*)&Ks[r][c] = *(const float4*)&g_k[gofs];
            *(float4*)&Vs[r][c] = *(const float4*)&g_v[gofs];
        }
        __syncthreads();

        int jmax = row + 1 - j0;
        if (jmax > AKV) jmax = AKV;
        for (int j = 0; j < jmax; j++) {
            float s0 = 0.f, s1 = 0.f, s2 = 0.f, s3 = 0.f;
            #pragma unroll
            for (int d = 0; d < HD; d += 4) {
                float4 kk4 = *(const float4*)&Ks[j][d];
                s0 = fmaf(qr[d],     kk4.x, s0);
                s1 = fmaf(qr[d + 1], kk4.y, s1);
                s2 = fmaf(qr[d + 2], kk4.z, s2);
                s3 = fmaf(qr[d + 3], kk4.w, s3);
            }
            float s = ((s0 + s1) + (s2 + s3)) * 0.125f;
            if (s > m) {
                float corr = expf(m - s);
                l *= corr;
                #pragma unroll
                for (int d = 0; d < HD; d++) o[d] *= corr;
                m = s;
            }
            float p = expf(s - m);
            l += p;
            #pragma unroll
            for (int d = 0; d < HD; d += 4) {
                float4 vv = *(const float4*)&Vs[j][d];
                o[d]     = fmaf(p, vv.x, o[d]);
                o[d + 1] = fmaf(p, vv.y, o[d + 1]);
                o[d + 2] = fmaf(p, vv.z, o[d + 2]);
                o[d + 3] = fmaf(p, vv.w, o[d + 3]);
            }
        }
    }

    float inv = 1.f / l;
    #pragma unroll
    for (int d = 0; d < HD; d += 4) {
        float4 t = make_float4(o[d] * inv, o[d + 1] * inv, o[d + 2] * inv, o[d + 3] * inv);
        *(float4*)&g_o[(size_t)row * (HQ * HD) + hq * HD + d] = t;
    }
}

// ---------------- host side ---------------------------------------------------
static const int SMEMB = (4 * 2112 + 4 * 2112) * 4;   // 67584 B

static GemmSeg mkseg(const float* B, const float* bias, float* C, int N, int nx) {
    GemmSeg s; s.B = B; s.bias = bias; s.C = C; s.N = N; s.nx = nx; return s;
}

extern "C" void kernel_launch(void* const* d_in, const int* in_sizes, int n_in,
                              void* d_out, int out_size) {
    const float* embed  = (const float*)d_in[0];
    const float* ln1    = (const float*)d_in[1];
    const float* qw     = (const float*)d_in[2];
    const float* qb     = (const float*)d_in[3];
    const float* kw     = (const float*)d_in[4];
    const float* kb     = (const float*)d_in[5];
    const float* vw     = (const float*)d_in[6];
    const float* vb     = (const float*)d_in[7];
    const float* ow     = (const float*)d_in[8];
    const float* ln2    = (const float*)d_in[9];
    const float* gw     = (const float*)d_in[10];
    const float* uw     = (const float*)d_in[11];
    const float* dw     = (const float*)d_in[12];
    const float* norm_w = (const float*)d_in[13];
    const float* lm_w   = (const float*)d_in[14];
    const int*   ids    = (const int*)d_in[15];
    float* out = (float*)d_out;

    float *p_h, *p_x, *p_q, *p_k, *p_v, *p_o, *p_gate, *p_up;
    cudaGetSymbolAddress((void**)&p_h, g_h);
    cudaGetSymbolAddress((void**)&p_x, g_x);
    cudaGetSymbolAddress((void**)&p_q, g_q);
    cudaGetSymbolAddress((void**)&p_k, g_k);
    cudaGetSymbolAddress((void**)&p_v, g_v);
    cudaGetSymbolAddress((void**)&p_o, g_o);
    cudaGetSymbolAddress((void**)&p_gate, g_gate);
    cudaGetSymbolAddress((void**)&p_up, g_up);

    static bool attr_done = false;
    if (!attr_done) {
        cudaFuncSetAttribute(mm_kernel, cudaFuncAttributeMaxDynamicSharedMemorySize, SMEMB);
        attr_done = true;
    }

    GemmSeg z = mkseg(nullptr, nullptr, nullptr, 0, 0);

    rope_table_kernel<<<(S * 32 + 255) / 256, 256>>>();
    embed_kernel<<<(S * D / 4) / 256, 256>>>(embed, ids);

    for (int l = 0; l < LAYERS; l++) {
        rmsnorm_kernel<<<S, 256>>>(p_h, ln1 + (size_t)l * D, p_x);

        // fused QKV projection: Q=8 blocks, K=2, V=2 (N=256 each for K/V)
        {
            GemmSeg sq = mkseg(qw + (size_t)l * D * HQ * HD, qb + (size_t)l * HQ * HD, p_q, HQ * HD, 8);
            GemmSeg sk = mkseg(kw + (size_t)l * D * KVH * HD, kb + (size_t)l * KVH * HD, p_k, KVH * HD, 2);
            GemmSeg sv = mkseg(vw + (size_t)l * D * KVH * HD, vb + (size_t)l * KVH * HD, p_v, KVH * HD, 2);
            mm_kernel<<<dim3(12, 16), 512, SMEMB>>>(p_x, sq, sk, sv, D, 0);
        }
        rope_kernel<<<(S * HQ * 32) / 256, 256>>>(p_q, HQ);
        rope_kernel<<<(S * KVH * 32) / 256, 256>>>(p_k, KVH);
        attn_kernel<<<dim3(S / 128, HQ), 128>>>();

        // O projection: h += o @ ow
        {
            GemmSeg so = mkseg(ow + (size_t)l * HQ * HD * D, nullptr, p_h, D, 8);
            mm_kernel<<<dim3(8, 16), 512, SMEMB>>>(p_o, so, z, z, HQ * HD, 1);
        }
        rmsnorm_kernel<<<S, 256>>>(p_h, ln2 + (size_t)l * D, p_x);

        // fused gate+up
        {
            GemmSeg sg = mkseg(gw + (size_t)l * D * II, nullptr, p_gate, II, 32);
            GemmSeg su = mkseg(uw + (size_t)l * D * II, nullptr, p_up, II, 32);
            mm_kernel<<<dim3(64, 16), 512, SMEMB>>>(p_x, sg, su, z, D, 0);
        }
        silu_mul_kernel<<<(S * II / 4) / 256, 256>>>();

        // down projection: h += act @ dw
        {
            GemmSeg sd = mkseg(dw + (size_t)l * II * D, nullptr, p_h, D, 8);
            mm_kernel<<<dim3(8, 16), 512, SMEMB>>>(p_gate, sd, z, z, II, 1);
        }
    }

    rmsnorm_kernel<<<S, 256>>>(p_h, norm_w, p_x);
    {
        GemmSeg sl = mkseg(lm_w, nullptr, out, VV, 250);
        mm_kernel<<<dim3(250, 16), 512, SMEMB>>>(p_x, sl, z, z, D, 0);
    }
}

// round 8
// speedup vs baseline: 1.1683x; 1.1678x over previous
#include <cuda_runtime.h>
#include <math.h>
#include <stdint.h>

#define LAYERS 4
#define S 2048
#define D 1024
#define HQ 16
#define KVH 4
#define HD 64
#define II 4096
#define VV 32000
#define EPSV 1e-6f

__device__ float g_h[S * D];
__device__ float g_x[S * D];
__device__ float g_q[S * HQ * HD];
__device__ float g_k[S * KVH * HD];
__device__ float g_v[S * KVH * HD];
__device__ float g_o[S * HQ * HD];
__device__ float g_gate[S * II];
__device__ float g_up[S * II];
__device__ float g_cos[S * 32];
__device__ float g_sin[S * 32];

// weights in mma-frag layout, hi/lo tf32: [pan][kb][nb(16)][64]
#define OQW  0
#define OKW  1048576
#define OVW  1310720
#define OOW  1572864
#define OGW  2621440
#define OUW  6815744
#define ODW  11010048
#define LSZ  15204352
#define OLM  60817408
#define WTOT 93585408
__device__ uint32_t g_wt_hi[WTOT];
__device__ uint32_t g_wt_lo[WTOT];

// activations in mma-frag layout, hi/lo: [mt][kb][mb(8)][128]
#define AMAX (S * II)
__device__ uint32_t g_a_hi[AMAX];
__device__ uint32_t g_a_lo[AMAX];

__device__ __forceinline__ uint32_t f2tf32(float f) {
    uint32_t u; asm("cvt.rna.tf32.f32 %0, %1;" : "=r"(u) : "f"(f)); return u;
}
__device__ __forceinline__ uint32_t smem_u32(const void* p) {
    uint32_t a;
    asm("{ .reg .u64 t; cvta.to.shared.u64 t, %1; cvt.u32.u64 %0, t; }" : "=r"(a) : "l"(p));
    return a;
}
__device__ __forceinline__ void cp_async16(uint32_t dst, const void* src) {
    asm volatile("cp.async.cg.shared.global [%0], [%1], 16;" :: "r"(dst), "l"(src) : "memory");
}
__device__ __forceinline__ void cp_commit() {
    asm volatile("cp.async.commit_group;" ::: "memory");
}
template <int N>
__device__ __forceinline__ void cp_wait() {
    asm volatile("cp.async.wait_group %0;" :: "n"(N) : "memory");
}

#define MMA_TF32(c, a, b)                                                     \
    asm volatile(                                                             \
        "mma.sync.aligned.m16n8k8.row.col.f32.tf32.tf32.f32 "                 \
        "{%0,%1,%2,%3},{%4,%5,%6,%7},{%8,%9},{%0,%1,%2,%3};"                  \
        : "+f"(c[0]), "+f"(c[1]), "+f"(c[2]), "+f"(c[3])                      \
        : "r"(a.x), "r"(a.y), "r"(a.z), "r"(a.w), "r"(b.x), "r"(b.y))

// ---------------- misc kernels ------------------------------------------------
__global__ void rope_table_kernel() {
    int idx = blockIdx.x * blockDim.x + threadIdx.x;
    if (idx >= S * 32) return;
    int s = idx >> 5, i = idx & 31;
    double invf = exp(-((double)(2 * i) / (double)HD) * log(10000.0));
    float af = (float)s * (float)invf;
    g_cos[idx] = (float)cos((double)af);
    g_sin[idx] = (float)sin((double)af);
}

__global__ void embed_kernel(const float* __restrict__ embed, const int* __restrict__ ids) {
    int idx = blockIdx.x * blockDim.x + threadIdx.x;
    int s = idx / (D / 4), c = idx % (D / 4);
    ((float4*)(g_h + (size_t)s * D))[c] = ((const float4*)(embed + (size_t)ids[s] * D))[c];
}

__global__ void rmsnorm_kernel(const float* __restrict__ X, const float* __restrict__ w,
                               float* __restrict__ Y) {
    int row = blockIdx.x;
    const float* x = X + (size_t)row * D;
    float ss = 0.f;
    for (int i = threadIdx.x; i < D; i += blockDim.x) { float v = x[i]; ss = fmaf(v, v, ss); }
    __shared__ float sred[32];
    #pragma unroll
    for (int off = 16; off; off >>= 1) ss += __shfl_xor_sync(0xffffffffu, ss, off);
    int wid = threadIdx.x >> 5, lid = threadIdx.x & 31;
    if (lid == 0) sred[wid] = ss;
    __syncthreads();
    if (wid == 0) {
        ss = (lid < (int)(blockDim.x >> 5)) ? sred[lid] : 0.f;
        #pragma unroll
        for (int off = 16; off; off >>= 1) ss += __shfl_xor_sync(0xffffffffu, ss, off);
        if (lid == 0) sred[0] = ss;
    }
    __syncthreads();
    float inv = rsqrtf(sred[0] / (float)D + EPSV);
    for (int i = threadIdx.x; i < D; i += blockDim.x)
        Y[(size_t)row * D + i] = w[i] * (x[i] * inv);
}

__global__ void rope_kernel(float* __restrict__ X, int nheads) {
    int idx = blockIdx.x * blockDim.x + threadIdx.x;
    if (idx >= S * nheads * 32) return;
    int i = idx & 31, h = (idx >> 5) % nheads, s = idx / (32 * nheads);
    float c = g_cos[s * 32 + i], sn = g_sin[s * 32 + i];
    float* p = X + (size_t)s * nheads * HD + h * HD;
    float x1 = p[i], x2 = p[i + 32];
    p[i] = x1 * c - x2 * sn;
    p[i + 32] = x2 * c + x1 * sn;
}

__global__ void silu_mul_kernel() {
    int idx = blockIdx.x * blockDim.x + threadIdx.x;
    float4 g = ((const float4*)g_gate)[idx];
    float4 u = ((const float4*)g_up)[idx];
    g.x = g.x / (1.f + expf(-g.x)) * u.x;
    g.y = g.y / (1.f + expf(-g.y)) * u.y;
    g.z = g.z / (1.f + expf(-g.z)) * u.z;
    g.w = g.w / (1.f + expf(-g.w)) * u.w;
    ((float4*)g_gate)[idx] = g;
}

// ---------------- weight prep: W[K][N] -> frag layout hi/lo -------------------
// grid (N/128, K/8), block 256
__global__ void wprep_kernel(const float* __restrict__ W, uint32_t* __restrict__ hi,
                             uint32_t* __restrict__ lo, int K, int N) {
    int pan = blockIdx.x, kb = blockIdx.y;
    int r = threadIdx.x >> 5;              // k within 8-block
    int n0 = (threadIdx.x & 31) * 4;
    float4 v = *(const float4*)(W + (size_t)(kb * 8 + r) * N + pan * 128 + n0);
    uint32_t blk = (uint32_t)(pan * (K >> 3) + kb) * 16;
    float f[4] = {v.x, v.y, v.z, v.w};
    #pragma unroll
    for (int j = 0; j < 4; j++) {
        int n = n0 + j;
        int pos = ((((n & 7) << 2) + (r & 3)) << 1) + (r >> 2);
        uint32_t idx = (blk + (n >> 3)) * 64 + pos;
        uint32_t h = f2tf32(f[j]);
        hi[idx] = h;
        lo[idx] = f2tf32(f[j] - __uint_as_float(h));
    }
}

// ---------------- activation prep: A[M][K] -> frag layout hi/lo ---------------
// grid (M/128, K/8), block 256
__global__ void asplit_kernel(const float* __restrict__ A, int K) {
    int mt = blockIdx.x, kb = blockIdx.y;
    int m = threadIdx.x >> 1;
    int k0 = (threadIdx.x & 1) * 4;
    float4 v = *(const float4*)(A + (size_t)(mt * 128 + m) * K + kb * 8 + k0);
    uint32_t base = ((uint32_t)(mt * (K >> 3) + kb) * 8 + (m >> 4)) * 128;
    float f[4] = {v.x, v.y, v.z, v.w};
    #pragma unroll
    for (int j = 0; j < 4; j++) {
        int k = k0 + j;
        int lane = ((m & 7) << 2) + (k & 3);
        int reg = ((m >> 3) & 1) + 2 * ((k >> 2) & 1);
        uint32_t idx = base + lane * 4 + reg;
        uint32_t h = f2tf32(f[j]);
        g_a_hi[idx] = h;
        g_a_lo[idx] = f2tf32(f[j] - __uint_as_float(h));
    }
}

// ---------------- 3xTF32 GEMM, frag-native staged via cp.async ----------------
// block 128x128, BK=16, 256 thr / 8 warps, warp tile 64x32
struct GemmSeg {
    const uint32_t* Bhi; const uint32_t* Blo;
    const float* bias; float* C; int N; int nx;
};
// smem: 2 bufs x [Ahi 2048 | Alo 2048 | Bhi 2048 | Blo 2048] uint32 = 65536 B
#define SMEM7 65536

__global__ void __launch_bounds__(256, 1)
mm7_kernel(GemmSeg s0, GemmSeg s1, GemmSeg s2, int K, int mode) {
    extern __shared__ __align__(128) uint32_t sm[];

    int bx = blockIdx.x;
    const uint32_t *Bhi, *Blo;
    const float* bias; float* Cp; int N;
    if (bx < s0.nx) { Bhi = s0.Bhi; Blo = s0.Blo; bias = s0.bias; Cp = s0.C; N = s0.N; }
    else if (bx < s0.nx + s1.nx) { bx -= s0.nx; Bhi = s1.Bhi; Blo = s1.Blo; bias = s1.bias; Cp = s1.C; N = s1.N; }
    else { bx -= s0.nx + s1.nx; Bhi = s2.Bhi; Blo = s2.Blo; bias = s2.bias; Cp = s2.C; N = s2.N; }
    const int pan = bx;
    const int mt = blockIdx.y;

    const int tid = threadIdx.x;
    const int lane = tid & 31;
    const int warp = tid >> 5;
    const int wm = warp & 1;       // 64-row half
    const int wn = warp >> 1;      // 32-col quarter (0..3)

    const uint32_t smb = smem_u32(sm);
    const int KB8 = K >> 3;

    float acc[4][4][4];
    #pragma unroll
    for (int i = 0; i < 4; i++)
        #pragma unroll
        for (int j = 0; j < 4; j++)
            #pragma unroll
            for (int r = 0; r < 4; r++) acc[i][j][r] = 0.f;

    // tile copy: 4 sections x 2048 uint32; per thread 8 x cp.async 16B
    auto copy_tile = [&](int t, int buf) {
        const uint32_t* srcA_hi = g_a_hi + ((size_t)(mt * KB8 + 2 * t)) * 1024;
        const uint32_t* srcA_lo = g_a_lo + ((size_t)(mt * KB8 + 2 * t)) * 1024;
        const uint32_t* srcB_hi = Bhi + ((size_t)(pan * KB8 + 2 * t)) * 1024;
        const uint32_t* srcB_lo = Blo + ((size_t)(pan * KB8 + 2 * t)) * 1024;
        uint32_t dst = smb + buf * 32768;
        #pragma unroll
        for (int j = 0; j < 2; j++) {
            int e = (tid + j * 256) * 4;   // uint32 offset
            cp_async16(dst + e * 4,                srcA_hi + e);
            cp_async16(dst + 8192 + e * 4,         srcA_lo + e);
            cp_async16(dst + 16384 + e * 4,        srcB_hi + e);
            cp_async16(dst + 24576 + e * 4,        srcB_lo + e);
        }
        cp_commit();
    };

    const int ntiles = K >> 4;
    copy_tile(0, 0);

    for (int t = 0; t < ntiles; t++) {
        bool has_next = (t + 1 < ntiles);
        if (has_next) copy_tile(t + 1, (t + 1) & 1);
        if (has_next) cp_wait<1>(); else cp_wait<0>();
        __syncthreads();

        const uint32_t* buf = sm + (t & 1) * 8192;
        const uint32_t* Ahi_s = buf;
        const uint32_t* Alo_s = buf + 2048;
        const uint32_t* Bhi_s = buf + 4096;
        const uint32_t* Blo_s = buf + 6144;

        #pragma unroll
        for (int ks = 0; ks < 2; ks++) {
            uint4 af[4];
            uint2 bf[4], bl[4];
            #pragma unroll
            for (int mf = 0; mf < 4; mf++)
                af[mf] = *(const uint4*)&Ahi_s[((ks * 8) + wm * 4 + mf) * 128 + lane * 4];
            #pragma unroll
            for (int nf = 0; nf < 4; nf++)
                bf[nf] = *(const uint2*)&Bhi_s[((ks * 16) + wn * 4 + nf) * 64 + lane * 2];
            // pass 1: hi*hi
            #pragma unroll
            for (int mf = 0; mf < 4; mf++)
                #pragma unroll
                for (int nf = 0; nf < 4; nf++)
                    MMA_TF32(acc[mf][nf], af[mf], bf[nf]);
            // pass 2: hi*lo(B)
            #pragma unroll
            for (int nf = 0; nf < 4; nf++)
                bl[nf] = *(const uint2*)&Blo_s[((ks * 16) + wn * 4 + nf) * 64 + lane * 2];
            #pragma unroll
            for (int mf = 0; mf < 4; mf++)
                #pragma unroll
                for (int nf = 0; nf < 4; nf++)
                    MMA_TF32(acc[mf][nf], af[mf], bl[nf]);
            // pass 3: lo(A)*hi (reuse af regs)
            #pragma unroll
            for (int mf = 0; mf < 4; mf++)
                af[mf] = *(const uint4*)&Alo_s[((ks * 8) + wm * 4 + mf) * 128 + lane * 4];
            #pragma unroll
            for (int mf = 0; mf < 4; mf++)
                #pragma unroll
                for (int nf = 0; nf < 4; nf++)
                    MMA_TF32(acc[mf][nf], af[mf], bf[nf]);
        }
        __syncthreads();
    }

    // epilogue
    const int g = lane >> 2, tg = lane & 3;
    const int col0 = pan * 128;
    #pragma unroll
    for (int nf = 0; nf < 4; nf++) {
        int cc = col0 + wn * 32 + nf * 8 + tg * 2;
        float b0 = 0.f, b1 = 0.f;
        if (mode == 0 && bias) { b0 = bias[cc]; b1 = bias[cc + 1]; }
        #pragma unroll
        for (int mf = 0; mf < 4; mf++) {
            int rr = mt * 128 + wm * 64 + mf * 16 + g;
            float2* p0 = (float2*)&Cp[(size_t)rr * N + cc];
            float2* p1 = (float2*)&Cp[(size_t)(rr + 8) * N + cc];
            if (mode == 0) {
                *p0 = make_float2(acc[mf][nf][0] + b0, acc[mf][nf][1] + b1);
                *p1 = make_float2(acc[mf][nf][2] + b0, acc[mf][nf][3] + b1);
            } else {
                float2 o0 = *p0, o1 = *p1;
                o0.x += acc[mf][nf][0]; o0.y += acc[mf][nf][1];
                o1.x += acc[mf][nf][2]; o1.y += acc[mf][nf][3];
                *p0 = o0; *p1 = o1;
            }
        }
    }
}

// ---------------- attention (fp32 flash-style) -------------------------------
#define AKV 64
__global__ void __launch_bounds__(128)
attn_kernel() {
    __shared__ float Ks[AKV][HD];
    __shared__ float Vs[AKV][HD];
    const int hq = blockIdx.y;
    const int kvh = hq >> 2;
    const int row = blockIdx.x * 128 + threadIdx.x;

    float qr[HD];
    #pragma unroll
    for (int d = 0; d < HD; d += 4) {
        float4 t = *(const float4*)&g_q[(size_t)row * (HQ * HD) + hq * HD + d];
        qr[d] = t.x; qr[d + 1] = t.y; qr[d + 2] = t.z; qr[d + 3] = t.w;
    }
    float o[HD];
    #pragma unroll
    for (int d = 0; d < HD; d++) o[d] = 0.f;
    float m = -INFINITY, l = 0.f;

    const int kend = (blockIdx.x + 1) * 128;
    for (int j0 = 0; j0 < kend; j0 += AKV) {
        __syncthreads();
        for (int t = threadIdx.x; t < AKV * (HD / 4); t += 128) {
            int r = t / (HD / 4), c = (t % (HD / 4)) * 4;
            size_t g = (size_t)(j0 + r) * (KVH * HD) + kvh * HD + c;
            *(float4*)&Ks[r][c] = *(const float4*)&g_k[g];
            *(float4*)&Vs[r][c] = *(const float4*)&g_v[g];
        }
        __syncthreads();
        int jmax = row + 1 - j0;
        if (jmax > AKV) jmax = AKV;
        for (int j = 0; j < jmax; j++) {
            float s0 = 0.f, s1 = 0.f, s2 = 0.f, s3 = 0.f;
            #pragma unroll
            for (int d = 0; d < HD; d += 4) {
                float4 k4 = *(const float4*)&Ks[j][d];
                s0 = fmaf(qr[d], k4.x, s0);
                s1 = fmaf(qr[d + 1], k4.y, s1);
                s2 = fmaf(qr[d + 2], k4.z, s2);
                s3 = fmaf(qr[d + 3], k4.w, s3);
            }
            float s = ((s0 + s1) + (s2 + s3)) * 0.125f;
            if (s > m) {
                float corr = expf(m - s);
                l *= corr;
                #pragma unroll
                for (int d = 0; d < HD; d++) o[d] *= corr;
                m = s;
            }
            float p = expf(s - m);
            l += p;
            #pragma unroll
            for (int d = 0; d < HD; d += 4) {
                float4 vv = *(const float4*)&Vs[j][d];
                o[d] = fmaf(p, vv.x, o[d]);
                o[d + 1] = fmaf(p, vv.y, o[d + 1]);
                o[d + 2] = fmaf(p, vv.z, o[d + 2]);
                o[d + 3] = fmaf(p, vv.w, o[d + 3]);
            }
        }
    }
    float inv = 1.f / l;
    #pragma unroll
    for (int d = 0; d < HD; d += 4) {
        float4 t = make_float4(o[d] * inv, o[d + 1] * inv, o[d + 2] * inv, o[d + 3] * inv);
        *(float4*)&g_o[(size_t)row * (HQ * HD) + hq * HD + d] = t;
    }
}

// ---------------- host side ---------------------------------------------------
static GemmSeg mkseg(const uint32_t* bh, const uint32_t* bl, const float* bias,
                     float* C, int N, int nx) {
    GemmSeg s; s.Bhi = bh; s.Blo = bl; s.bias = bias; s.C = C; s.N = N; s.nx = nx; return s;
}

extern "C" void kernel_launch(void* const* d_in, const int* in_sizes, int n_in,
                              void* d_out, int out_size) {
    const float* embed  = (const float*)d_in[0];
    const float* ln1    = (const float*)d_in[1];
    const float* qw     = (const float*)d_in[2];
    const float* qb     = (const float*)d_in[3];
    const float* kw     = (const float*)d_in[4];
    const float* kb     = (const float*)d_in[5];
    const float* vw     = (const float*)d_in[6];
    const float* vb     = (const float*)d_in[7];
    const float* ow     = (const float*)d_in[8];
    const float* ln2    = (const float*)d_in[9];
    const float* gw     = (const float*)d_in[10];
    const float* uw     = (const float*)d_in[11];
    const float* dw     = (const float*)d_in[12];
    const float* norm_w = (const float*)d_in[13];
    const float* lm_w   = (const float*)d_in[14];
    const int*   ids    = (const int*)d_in[15];
    float* out = (float*)d_out;

    float *p_h, *p_x, *p_q, *p_k, *p_v, *p_o, *p_gate, *p_up;
    uint32_t *p_whi, *p_wlo;
    cudaGetSymbolAddress((void**)&p_h, g_h);
    cudaGetSymbolAddress((void**)&p_x, g_x);
    cudaGetSymbolAddress((void**)&p_q, g_q);
    cudaGetSymbolAddress((void**)&p_k, g_k);
    cudaGetSymbolAddress((void**)&p_v, g_v);
    cudaGetSymbolAddress((void**)&p_o, g_o);
    cudaGetSymbolAddress((void**)&p_gate, g_gate);
    cudaGetSymbolAddress((void**)&p_up, g_up);
    cudaGetSymbolAddress((void**)&p_whi, g_wt_hi);
    cudaGetSymbolAddress((void**)&p_wlo, g_wt_lo);

    static bool attr_done = false;
    if (!attr_done) {
        cudaFuncSetAttribute(mm7_kernel, cudaFuncAttributeMaxDynamicSharedMemorySize, SMEM7);
        attr_done = true;
    }

    // weight prep: frag layout + hi/lo split  (grid: (N/128, K/8))
    for (int l = 0; l < LAYERS; l++) {
        size_t lo = (size_t)l * LSZ;
        wprep_kernel<<<dim3(8, 128), 256>>>(qw + (size_t)l * 1048576, p_whi + lo + OQW, p_wlo + lo + OQW, 1024, 1024);
        wprep_kernel<<<dim3(2, 128), 256>>>(kw + (size_t)l * 262144, p_whi + lo + OKW, p_wlo + lo + OKW, 1024, 256);
        wprep_kernel<<<dim3(2, 128), 256>>>(vw + (size_t)l * 262144, p_whi + lo + OVW, p_wlo + lo + OVW, 1024, 256);
        wprep_kernel<<<dim3(8, 128), 256>>>(ow + (size_t)l * 1048576, p_whi + lo + OOW, p_wlo + lo + OOW, 1024, 1024);
        wprep_kernel<<<dim3(32, 128), 256>>>(gw + (size_t)l * 4194304, p_whi + lo + OGW, p_wlo + lo + OGW, 1024, 4096);
        wprep_kernel<<<dim3(32, 128), 256>>>(uw + (size_t)l * 4194304, p_whi + lo + OUW, p_wlo + lo + OUW, 1024, 4096);
        wprep_kernel<<<dim3(8, 512), 256>>>(dw + (size_t)l * 4194304, p_whi + lo + ODW, p_wlo + lo + ODW, 4096, 1024);
    }
    wprep_kernel<<<dim3(250, 128), 256>>>(lm_w, p_whi + OLM, p_wlo + OLM, 1024, 32000);

    GemmSeg z = mkseg(nullptr, nullptr, nullptr, nullptr, 0, 0);

    rope_table_kernel<<<(S * 32 + 255) / 256, 256>>>();
    embed_kernel<<<(S * D / 4) / 256, 256>>>(embed, ids);

    for (int l = 0; l < LAYERS; l++) {
        size_t lo = (size_t)l * LSZ;
        rmsnorm_kernel<<<S, 256>>>(p_h, ln1 + (size_t)l * D, p_x);
        asplit_kernel<<<dim3(16, 128), 256>>>(p_x, 1024);
        {
            GemmSeg sq = mkseg(p_whi + lo + OQW, p_wlo + lo + OQW, qb + (size_t)l * HQ * HD, p_q, HQ * HD, 8);
            GemmSeg sk = mkseg(p_whi + lo + OKW, p_wlo + lo + OKW, kb + (size_t)l * KVH * HD, p_k, KVH * HD, 2);
            GemmSeg sv = mkseg(p_whi + lo + OVW, p_wlo + lo + OVW, vb + (size_t)l * KVH * HD, p_v, KVH * HD, 2);
            mm7_kernel<<<dim3(12, 16), 256, SMEM7>>>(sq, sk, sv, D, 0);
        }
        rope_kernel<<<(S * HQ * 32) / 256, 256>>>(p_q, HQ);
        rope_kernel<<<(S * KVH * 32) / 256, 256>>>(p_k, KVH);
        attn_kernel<<<dim3(S / 128, HQ), 128>>>();
        asplit_kernel<<<dim3(16, 128), 256>>>(p_o, 1024);
        {
            GemmSeg so = mkseg(p_whi + lo + OOW, p_wlo + lo + OOW, nullptr, p_h, D, 8);
            mm7_kernel<<<dim3(8, 16), 256, SMEM7>>>(so, z, z, HQ * HD, 1);
        }
        rmsnorm_kernel<<<S, 256>>>(p_h, ln2 + (size_t)l * D, p_x);
        asplit_kernel<<<dim3(16, 128), 256>>>(p_x, 1024);
        {
            GemmSeg sg = mkseg(p_whi + lo + OGW, p_wlo + lo + OGW, nullptr, p_gate, II, 32);
            GemmSeg su = mkseg(p_whi + lo + OUW, p_wlo + lo + OUW, nullptr, p_up, II, 32);
            mm7_kernel<<<dim3(64, 16), 256, SMEM7>>>(sg, su, z, D, 0);
        }
        silu_mul_kernel<<<(S * II / 4) / 256, 256>>>();
        asplit_kernel<<<dim3(16, 512), 256>>>(p_gate, 4096);
        {
            GemmSeg sd = mkseg(p_whi + lo + ODW, p_wlo + lo + ODW, nullptr, p_h, D, 8);
            mm7_kernel<<<dim3(8, 16), 256, SMEM7>>>(sd, z, z, II, 1);
        }
    }

    rmsnorm_kernel<<<S, 256>>>(p_h, norm_w, p_x);
    asplit_kernel<<<dim3(16, 128), 256>>>(p_x, 1024);
    {
        GemmSeg sl = mkseg(p_whi + OLM, p_wlo + OLM, nullptr, out, VV, 250);
        mm7_kernel<<<dim3(250, 16), 256, SMEM7>>>(sl, z, z, D, 0);
    }
}

// round 9
// speedup vs baseline: 1.2597x; 1.0783x over previous
#include <cuda_runtime.h>
#include <math.h>
#include <stdint.h>

#define LAYERS 4
#define S 2048
#define D 1024
#define HQ 16
#define KVH 4
#define HD 64
#define II 4096
#define VV 32000
#define EPSV 1e-6f

__device__ float g_h[S * D];
__device__ float g_x[S * D];
__device__ float g_q[S * HQ * HD];
__device__ float g_k[S * KVH * HD];
__device__ float g_v[S * KVH * HD];
__device__ float g_o[S * HQ * HD];
__device__ float g_gate[S * II];
__device__ float g_up[S * II];
__device__ float g_cos[S * 32];
__device__ float g_sin[S * 32];

// weights in mma-frag layout, hi/lo tf32: [pan][kb][nb(16)][64]
#define OQW  0
#define OKW  1048576
#define OVW  1310720
#define OOW  1572864
#define OGW  2621440
#define OUW  6815744
#define ODW  11010048
#define LSZ  15204352
#define OLM  60817408
#define WTOT 93585408
__device__ uint32_t g_wt_hi[WTOT];
__device__ uint32_t g_wt_lo[WTOT];

// activations in mma-frag layout, hi/lo: [mt][kb][mb(8)][128]
#define AMAX (S * II)
__device__ uint32_t g_a_hi[AMAX];
__device__ uint32_t g_a_lo[AMAX];

__device__ __forceinline__ uint32_t f2tf32(float f) {
    uint32_t u; asm("cvt.rna.tf32.f32 %0, %1;" : "=r"(u) : "f"(f)); return u;
}
__device__ __forceinline__ uint32_t smem_u32(const void* p) {
    uint32_t a;
    asm("{ .reg .u64 t; cvta.to.shared.u64 t, %1; cvt.u32.u64 %0, t; }" : "=r"(a) : "l"(p));
    return a;
}
__device__ __forceinline__ void cp_async16(uint32_t dst, const void* src) {
    asm volatile("cp.async.cg.shared.global [%0], [%1], 16;" :: "r"(dst), "l"(src) : "memory");
}
__device__ __forceinline__ void cp_commit() {
    asm volatile("cp.async.commit_group;" ::: "memory");
}
template <int N>
__device__ __forceinline__ void cp_wait() {
    asm volatile("cp.async.wait_group %0;" :: "n"(N) : "memory");
}

#define MMA_TF32(c, a, b)                                                     \
    asm volatile(                                                             \
        "mma.sync.aligned.m16n8k8.row.col.f32.tf32.tf32.f32 "                 \
        "{%0,%1,%2,%3},{%4,%5,%6,%7},{%8,%9},{%0,%1,%2,%3};"                  \
        : "+f"(c[0]), "+f"(c[1]), "+f"(c[2]), "+f"(c[3])                      \
        : "r"(a.x), "r"(a.y), "r"(a.z), "r"(a.w), "r"(b.x), "r"(b.y))

// ---------------- misc kernels ------------------------------------------------
__global__ void rope_table_kernel() {
    int idx = blockIdx.x * blockDim.x + threadIdx.x;
    if (idx >= S * 32) return;
    int s = idx >> 5, i = idx & 31;
    double invf = exp(-((double)(2 * i) / (double)HD) * log(10000.0));
    float af = (float)s * (float)invf;
    g_cos[idx] = (float)cos((double)af);
    g_sin[idx] = (float)sin((double)af);
}

__global__ void embed_kernel(const float* __restrict__ embed, const int* __restrict__ ids) {
    int idx = blockIdx.x * blockDim.x + threadIdx.x;
    int s = idx / (D / 4), c = idx % (D / 4);
    ((float4*)(g_h + (size_t)s * D))[c] = ((const float4*)(embed + (size_t)ids[s] * D))[c];
}

__global__ void rmsnorm_kernel(const float* __restrict__ X, const float* __restrict__ w,
                               float* __restrict__ Y) {
    int row = blockIdx.x;
    const float* x = X + (size_t)row * D;
    float ss = 0.f;
    for (int i = threadIdx.x; i < D; i += blockDim.x) { float v = x[i]; ss = fmaf(v, v, ss); }
    __shared__ float sred[32];
    #pragma unroll
    for (int off = 16; off; off >>= 1) ss += __shfl_xor_sync(0xffffffffu, ss, off);
    int wid = threadIdx.x >> 5, lid = threadIdx.x & 31;
    if (lid == 0) sred[wid] = ss;
    __syncthreads();
    if (wid == 0) {
        ss = (lid < (int)(blockDim.x >> 5)) ? sred[lid] : 0.f;
        #pragma unroll
        for (int off = 16; off; off >>= 1) ss += __shfl_xor_sync(0xffffffffu, ss, off);
        if (lid == 0) sred[0] = ss;
    }
    __syncthreads();
    float inv = rsqrtf(sred[0] / (float)D + EPSV);
    for (int i = threadIdx.x; i < D; i += blockDim.x)
        Y[(size_t)row * D + i] = w[i] * (x[i] * inv);
}

__global__ void rope_kernel(float* __restrict__ X, int nheads) {
    int idx = blockIdx.x * blockDim.x + threadIdx.x;
    if (idx >= S * nheads * 32) return;
    int i = idx & 31, h = (idx >> 5) % nheads, s = idx / (32 * nheads);
    float c = g_cos[s * 32 + i], sn = g_sin[s * 32 + i];
    float* p = X + (size_t)s * nheads * HD + h * HD;
    float x1 = p[i], x2 = p[i + 32];
    p[i] = x1 * c - x2 * sn;
    p[i + 32] = x2 * c + x1 * sn;
}

__global__ void silu_mul_kernel() {
    int idx = blockIdx.x * blockDim.x + threadIdx.x;
    float4 g = ((const float4*)g_gate)[idx];
    float4 u = ((const float4*)g_up)[idx];
    g.x = g.x / (1.f + expf(-g.x)) * u.x;
    g.y = g.y / (1.f + expf(-g.y)) * u.y;
    g.z = g.z / (1.f + expf(-g.z)) * u.z;
    g.w = g.w / (1.f + expf(-g.w)) * u.w;
    ((float4*)g_gate)[idx] = g;
}

// ---------------- weight prep: W[K][N] -> frag layout hi/lo -------------------
// smem-staged: coalesced LDG, scatter-STS (<=4-way), linear uint4 STG.
// grid (N/128, K/8), block 256
__global__ void wprep_kernel(const float* __restrict__ W, uint32_t* __restrict__ hi,
                             uint32_t* __restrict__ lo, int K, int N) {
    __shared__ uint32_t sh[1024];
    __shared__ uint32_t sl[1024];
    int pan = blockIdx.x, kb = blockIdx.y;
    int r = threadIdx.x & 7;               // k within 8-block
    int n0 = (threadIdx.x >> 3) * 4;       // n within 128
    float4 v = *(const float4*)(W + (size_t)(kb * 8 + r) * N + pan * 128 + n0);
    float f[4] = {v.x, v.y, v.z, v.w};
    #pragma unroll
    for (int j = 0; j < 4; j++) {
        int n = n0 + j;
        int pos = ((n >> 3) << 6) + ((n & 7) << 3) + ((r & 3) << 1) + (r >> 2);
        uint32_t h = f2tf32(f[j]);
        sh[pos] = h;
        sl[pos] = f2tf32(f[j] - __uint_as_float(h));
    }
    __syncthreads();
    size_t base = (size_t)((uint32_t)(pan * (K >> 3) + kb)) * 1024;
    int e = threadIdx.x * 4;
    *(uint4*)(hi + base + e) = *(const uint4*)(sh + e);
    *(uint4*)(lo + base + e) = *(const uint4*)(sl + e);
}

// ---------------- activation prep: A[M][K] -> frag layout hi/lo ---------------
// smem-staged; grid (M/128, K/8), block 256
__global__ void asplit_kernel(const float* __restrict__ A, int K) {
    __shared__ uint32_t sh[1024];
    __shared__ uint32_t sl[1024];
    int mt = blockIdx.x, kb = blockIdx.y;
    int m = threadIdx.x >> 1;
    int k0 = (threadIdx.x & 1) * 4;
    float4 v = *(const float4*)(A + (size_t)(mt * 128 + m) * K + kb * 8 + k0);
    float f[4] = {v.x, v.y, v.z, v.w};
    #pragma unroll
    for (int j = 0; j < 4; j++) {
        int k = k0 + j;
        int lane = ((m & 7) << 2) + (k & 3);
        int reg = ((m >> 3) & 1) + 2 * ((k >> 2) & 1);
        int pos = ((m >> 4) << 7) + lane * 4 + reg;
        uint32_t h = f2tf32(f[j]);
        sh[pos] = h;
        sl[pos] = f2tf32(f[j] - __uint_as_float(h));
    }
    __syncthreads();
    size_t base = (size_t)((uint32_t)(mt * (K >> 3) + kb)) * 1024;
    int e = threadIdx.x * 4;
    *(uint4*)(g_a_hi + base + e) = *(const uint4*)(sh + e);
    *(uint4*)(g_a_lo + base + e) = *(const uint4*)(sl + e);
}

// ---------------- 3xTF32 GEMM, frag-native staged via cp.async ----------------
// block 128x128, BK=16, 256 thr / 8 warps, warp tile 64x32
struct GemmSeg {
    const uint32_t* Bhi; const uint32_t* Blo;
    const float* bias; float* C; int N; int nx;
};
// smem: 2 bufs x [Ahi 2048 | Alo 2048 | Bhi 2048 | Blo 2048] uint32 = 65536 B
#define SMEM7 65536

__global__ void __launch_bounds__(256, 1)
mm7_kernel(GemmSeg s0, GemmSeg s1, GemmSeg s2, int K, int mode) {
    extern __shared__ __align__(128) uint32_t sm[];

    int bx = blockIdx.x;
    const uint32_t *Bhi, *Blo;
    const float* bias; float* Cp; int N;
    if (bx < s0.nx) { Bhi = s0.Bhi; Blo = s0.Blo; bias = s0.bias; Cp = s0.C; N = s0.N; }
    else if (bx < s0.nx + s1.nx) { bx -= s0.nx; Bhi = s1.Bhi; Blo = s1.Blo; bias = s1.bias; Cp = s1.C; N = s1.N; }
    else { bx -= s0.nx + s1.nx; Bhi = s2.Bhi; Blo = s2.Blo; bias = s2.bias; Cp = s2.C; N = s2.N; }
    const int pan = bx;
    const int mt = blockIdx.y;

    const int tid = threadIdx.x;
    const int lane = tid & 31;
    const int warp = tid >> 5;
    const int wm = warp & 1;       // 64-row half
    const int wn = warp >> 1;      // 32-col quarter (0..3)

    const uint32_t smb = smem_u32(sm);
    const int KB8 = K >> 3;

    float acc[4][4][4];
    #pragma unroll
    for (int i = 0; i < 4; i++)
        #pragma unroll
        for (int j = 0; j < 4; j++)
            #pragma unroll
            for (int r = 0; r < 4; r++) acc[i][j][r] = 0.f;

    auto copy_tile = [&](int t, int buf) {
        const uint32_t* srcA_hi = g_a_hi + ((size_t)(mt * KB8 + 2 * t)) * 1024;
        const uint32_t* srcA_lo = g_a_lo + ((size_t)(mt * KB8 + 2 * t)) * 1024;
        const uint32_t* srcB_hi = Bhi + ((size_t)(pan * KB8 + 2 * t)) * 1024;
        const uint32_t* srcB_lo = Blo + ((size_t)(pan * KB8 + 2 * t)) * 1024;
        uint32_t dst = smb + buf * 32768;
        #pragma unroll
        for (int j = 0; j < 2; j++) {
            int e = (tid + j * 256) * 4;
            cp_async16(dst + e * 4,         srcA_hi + e);
            cp_async16(dst + 8192 + e * 4,  srcA_lo + e);
            cp_async16(dst + 16384 + e * 4, srcB_hi + e);
            cp_async16(dst + 24576 + e * 4, srcB_lo + e);
        }
        cp_commit();
    };

    const int ntiles = K >> 4;
    copy_tile(0, 0);

    for (int t = 0; t < ntiles; t++) {
        bool has_next = (t + 1 < ntiles);
        if (has_next) copy_tile(t + 1, (t + 1) & 1);
        if (has_next) cp_wait<1>(); else cp_wait<0>();
        __syncthreads();

        const uint32_t* buf = sm + (t & 1) * 8192;
        const uint32_t* Ahi_s = buf;
        const uint32_t* Alo_s = buf + 2048;
        const uint32_t* Bhi_s = buf + 4096;
        const uint32_t* Blo_s = buf + 6144;

        #pragma unroll
        for (int ks = 0; ks < 2; ks++) {
            uint4 af[4];
            uint2 bf[4], bl[4];
            #pragma unroll
            for (int mf = 0; mf < 4; mf++)
                af[mf] = *(const uint4*)&Ahi_s[((ks * 8) + wm * 4 + mf) * 128 + lane * 4];
            #pragma unroll
            for (int nf = 0; nf < 4; nf++)
                bf[nf] = *(const uint2*)&Bhi_s[((ks * 16) + wn * 4 + nf) * 64 + lane * 2];
            #pragma unroll
            for (int mf = 0; mf < 4; mf++)
                #pragma unroll
                for (int nf = 0; nf < 4; nf++)
                    MMA_TF32(acc[mf][nf], af[mf], bf[nf]);
            #pragma unroll
            for (int nf = 0; nf < 4; nf++)
                bl[nf] = *(const uint2*)&Blo_s[((ks * 16) + wn * 4 + nf) * 64 + lane * 2];
            #pragma unroll
            for (int mf = 0; mf < 4; mf++)
                #pragma unroll
                for (int nf = 0; nf < 4; nf++)
                    MMA_TF32(acc[mf][nf], af[mf], bl[nf]);
            #pragma unroll
            for (int mf = 0; mf < 4; mf++)
                af[mf] = *(const uint4*)&Alo_s[((ks * 8) + wm * 4 + mf) * 128 + lane * 4];
            #pragma unroll
            for (int mf = 0; mf < 4; mf++)
                #pragma unroll
                for (int nf = 0; nf < 4; nf++)
                    MMA_TF32(acc[mf][nf], af[mf], bf[nf]);
        }
        __syncthreads();
    }

    const int g = lane >> 2, tg = lane & 3;
    const int col0 = pan * 128;
    #pragma unroll
    for (int nf = 0; nf < 4; nf++) {
        int cc = col0 + wn * 32 + nf * 8 + tg * 2;
        float b0 = 0.f, b1 = 0.f;
        if (mode == 0 && bias) { b0 = bias[cc]; b1 = bias[cc + 1]; }
        #pragma unroll
        for (int mf = 0; mf < 4; mf++) {
            int rr = mt * 128 + wm * 64 + mf * 16 + g;
            float2* p0 = (float2*)&Cp[(size_t)rr * N + cc];
            float2* p1 = (float2*)&Cp[(size_t)(rr + 8) * N + cc];
            if (mode == 0) {
                *p0 = make_float2(acc[mf][nf][0] + b0, acc[mf][nf][1] + b1);
                *p1 = make_float2(acc[mf][nf][2] + b0, acc[mf][nf][3] + b1);
            } else {
                float2 o0 = *p0, o1 = *p1;
                o0.x += acc[mf][nf][0]; o0.y += acc[mf][nf][1];
                o1.x += acc[mf][nf][2]; o1.y += acc[mf][nf][3];
                *p0 = o0; *p1 = o1;
            }
        }
    }
}

// ---------------- attention (fp32 flash-style) -------------------------------
#define AKV 64
__global__ void __launch_bounds__(128)
attn_kernel() {
    __shared__ float Ks[AKV][HD];
    __shared__ float Vs[AKV][HD];
    const int hq = blockIdx.y;
    const int kvh = hq >> 2;
    const int row = blockIdx.x * 128 + threadIdx.x;

    float qr[HD];
    #pragma unroll
    for (int d = 0; d < HD; d += 4) {
        float4 t = *(const float4*)&g_q[(size_t)row * (HQ * HD) + hq * HD + d];
        qr[d] = t.x; qr[d + 1] = t.y; qr[d + 2] = t.z; qr[d + 3] = t.w;
    }
    float o[HD];
    #pragma unroll
    for (int d = 0; d < HD; d++) o[d] = 0.f;
    float m = -INFINITY, l = 0.f;

    const int kend = (blockIdx.x + 1) * 128;
    for (int j0 = 0; j0 < kend; j0 += AKV) {
        __syncthreads();
        for (int t = threadIdx.x; t < AKV * (HD / 4); t += 128) {
            int r = t / (HD / 4), c = (t % (HD / 4)) * 4;
            size_t g = (size_t)(j0 + r) * (KVH * HD) + kvh * HD + c;
            *(float4*)&Ks[r][c] = *(const float4*)&g_k[g];
            *(float4*)&Vs[r][c] = *(const float4*)&g_v[g];
        }
        __syncthreads();
        int jmax = row + 1 - j0;
        if (jmax > AKV) jmax = AKV;
        for (int j = 0; j < jmax; j++) {
            float s0 = 0.f, s1 = 0.f, s2 = 0.f, s3 = 0.f;
            #pragma unroll
            for (int d = 0; d < HD; d += 4) {
                float4 k4 = *(const float4*)&Ks[j][d];
                s0 = fmaf(qr[d], k4.x, s0);
                s1 = fmaf(qr[d + 1], k4.y, s1);
                s2 = fmaf(qr[d + 2], k4.z, s2);
                s3 = fmaf(qr[d + 3], k4.w, s3);
            }
            float s = ((s0 + s1) + (s2 + s3)) * 0.125f;
            if (s > m) {
                float corr = expf(m - s);
                l *= corr;
                #pragma unroll
                for (int d = 0; d < HD; d++) o[d] *= corr;
                m = s;
            }
            float p = expf(s - m);
            l += p;
            #pragma unroll
            for (int d = 0; d < HD; d += 4) {
                float4 vv = *(const float4*)&Vs[j][d];
                o[d] = fmaf(p, vv.x, o[d]);
                o[d + 1] = fmaf(p, vv.y, o[d + 1]);
                o[d + 2] = fmaf(p, vv.z, o[d + 2]);
                o[d + 3] = fmaf(p, vv.w, o[d + 3]);
            }
        }
    }
    float inv = 1.f / l;
    #pragma unroll
    for (int d = 0; d < HD; d += 4) {
        float4 t = make_float4(o[d] * inv, o[d + 1] * inv, o[d + 2] * inv, o[d + 3] * inv);
        *(float4*)&g_o[(size_t)row * (HQ * HD) + hq * HD + d] = t;
    }
}

// ---------------- host side ---------------------------------------------------
static GemmSeg mkseg(const uint32_t* bh, const uint32_t* bl, const float* bias,
                     float* C, int N, int nx) {
    GemmSeg s; s.Bhi = bh; s.Blo = bl; s.bias = bias; s.C = C; s.N = N; s.nx = nx; return s;
}

extern "C" void kernel_launch(void* const* d_in, const int* in_sizes, int n_in,
                              void* d_out, int out_size) {
    const float* embed  = (const float*)d_in[0];
    const float* ln1    = (const float*)d_in[1];
    const float* qw     = (const float*)d_in[2];
    const float* qb     = (const float*)d_in[3];
    const float* kw     = (const float*)d_in[4];
    const float* kb     = (const float*)d_in[5];
    const float* vw     = (const float*)d_in[6];
    const float* vb     = (const float*)d_in[7];
    const float* ow     = (const float*)d_in[8];
    const float* ln2    = (const float*)d_in[9];
    const float* gw     = (const float*)d_in[10];
    const float* uw     = (const float*)d_in[11];
    const float* dw     = (const float*)d_in[12];
    const float* norm_w = (const float*)d_in[13];
    const float* lm_w   = (const float*)d_in[14];
    const int*   ids    = (const int*)d_in[15];
    float* out = (float*)d_out;

    float *p_h, *p_x, *p_q, *p_k, *p_v, *p_o, *p_gate, *p_up;
    uint32_t *p_whi, *p_wlo;
    cudaGetSymbolAddress((void**)&p_h, g_h);
    cudaGetSymbolAddress((void**)&p_x, g_x);
    cudaGetSymbolAddress((void**)&p_q, g_q);
    cudaGetSymbolAddress((void**)&p_k, g_k);
    cudaGetSymbolAddress((void**)&p_v, g_v);
    cudaGetSymbolAddress((void**)&p_o, g_o);
    cudaGetSymbolAddress((void**)&p_gate, g_gate);
    cudaGetSymbolAddress((void**)&p_up, g_up);
    cudaGetSymbolAddress((void**)&p_whi, g_wt_hi);
    cudaGetSymbolAddress((void**)&p_wlo, g_wt_lo);

    static bool attr_done = false;
    if (!attr_done) {
        cudaFuncSetAttribute(mm7_kernel, cudaFuncAttributeMaxDynamicSharedMemorySize, SMEM7);
        attr_done = true;
    }

    // weight prep: frag layout + hi/lo split  (grid: (N/128, K/8))
    for (int l = 0; l < LAYERS; l++) {
        size_t lo = (size_t)l * LSZ;
        wprep_kernel<<<dim3(8, 128), 256>>>(qw + (size_t)l * 1048576, p_whi + lo + OQW, p_wlo + lo + OQW, 1024, 1024);
        wprep_kernel<<<dim3(2, 128), 256>>>(kw + (size_t)l * 262144, p_whi + lo + OKW, p_wlo + lo + OKW, 1024, 256);
        wprep_kernel<<<dim3(2, 128), 256>>>(vw + (size_t)l * 262144, p_whi + lo + OVW, p_wlo + lo + OVW, 1024, 256);
        wprep_kernel<<<dim3(8, 128), 256>>>(ow + (size_t)l * 1048576, p_whi + lo + OOW, p_wlo + lo + OOW, 1024, 1024);
        wprep_kernel<<<dim3(32, 128), 256>>>(gw + (size_t)l * 4194304, p_whi + lo + OGW, p_wlo + lo + OGW, 1024, 4096);
        wprep_kernel<<<dim3(32, 128), 256>>>(uw + (size_t)l * 4194304, p_whi + lo + OUW, p_wlo + lo + OUW, 1024, 4096);
        wprep_kernel<<<dim3(8, 512), 256>>>(dw + (size_t)l * 4194304, p_whi + lo + ODW, p_wlo + lo + ODW, 4096, 1024);
    }
    wprep_kernel<<<dim3(250, 128), 256>>>(lm_w, p_whi + OLM, p_wlo + OLM, 1024, 32000);

    GemmSeg z = mkseg(nullptr, nullptr, nullptr, nullptr, 0, 0);

    rope_table_kernel<<<(S * 32 + 255) / 256, 256>>>();
    embed_kernel<<<(S * D / 4) / 256, 256>>>(embed, ids);

    for (int l = 0; l < LAYERS; l++) {
        size_t lo = (size_t)l * LSZ;
        rmsnorm_kernel<<<S, 256>>>(p_h, ln1 + (size_t)l * D, p_x);
        asplit_kernel<<<dim3(16, 128), 256>>>(p_x, 1024);
        {
            GemmSeg sq = mkseg(p_whi + lo + OQW, p_wlo + lo + OQW, qb + (size_t)l * HQ * HD, p_q, HQ * HD, 8);
            GemmSeg sk = mkseg(p_whi + lo + OKW, p_wlo + lo + OKW, kb + (size_t)l * KVH * HD, p_k, KVH * HD, 2);
            GemmSeg sv = mkseg(p_whi + lo + OVW, p_wlo + lo + OVW, vb + (size_t)l * KVH * HD, p_v, KVH * HD, 2);
            mm7_kernel<<<dim3(12, 16), 256, SMEM7>>>(sq, sk, sv, D, 0);
        }
        rope_kernel<<<(S * HQ * 32) / 256, 256>>>(p_q, HQ);
        rope_kernel<<<(S * KVH * 32) / 256, 256>>>(p_k, KVH);
        attn_kernel<<<dim3(S / 128, HQ), 128>>>();
        asplit_kernel<<<dim3(16, 128), 256>>>(p_o, 1024);
        {
            GemmSeg so = mkseg(p_whi + lo + OOW, p_wlo + lo + OOW, nullptr, p_h, D, 8);
            mm7_kernel<<<dim3(8, 16), 256, SMEM7>>>(so, z, z, HQ * HD, 1);
        }
        rmsnorm_kernel<<<S, 256>>>(p_h, ln2 + (size_t)l * D, p_x);
        asplit_kernel<<<dim3(16, 128), 256>>>(p_x, 1024);
        {
            GemmSeg sg = mkseg(p_whi + lo + OGW, p_wlo + lo + OGW, nullptr, p_gate, II, 32);
            GemmSeg su = mkseg(p_whi + lo + OUW, p_wlo + lo + OUW, nullptr, p_up, II, 32);
            mm7_kernel<<<dim3(64, 16), 256, SMEM7>>>(sg, su, z, D, 0);
        }
        silu_mul_kernel<<<(S * II / 4) / 256, 256>>>();
        asplit_kernel<<<dim3(16, 512), 256>>>(p_gate, 4096);
        {
            GemmSeg sd = mkseg(p_whi + lo + ODW, p_wlo + lo + ODW, nullptr, p_h, D, 8);
            mm7_kernel<<<dim3(8, 16), 256, SMEM7>>>(sd, z, z, II, 1);
        }
    }

    rmsnorm_kernel<<<S, 256>>>(p_h, norm_w, p_x);
    asplit_kernel<<<dim3(16, 128), 256>>>(p_x, 1024);
    {
        GemmSeg sl = mkseg(p_whi + OLM, p_wlo + OLM, nullptr, out, VV, 250);
        mm7_kernel<<<dim3(250, 16), 256, SMEM7>>>(sl, z, z, D, 0);
    }
}

// round 10
// speedup vs baseline: 1.3348x; 1.0596x over previous
#include <cuda_runtime.h>
#include <math.h>
#include <stdint.h>

#define LAYERS 4
#define S 2048
#define D 1024
#define HQ 16
#define KVH 4
#define HD 64
#define II 4096
#define VV 32000
#define EPSV 1e-6f

__device__ float g_h[S * D];
__device__ float g_x[S * D];
__device__ float g_q[S * HQ * HD];
__device__ float g_k[S * KVH * HD];
__device__ float g_v[S * KVH * HD];
__device__ float g_o[S * HQ * HD];
__device__ float g_gate[S * II];
__device__ float g_up[S * II];
__device__ float g_cos[S * 32];
__device__ float g_sin[S * 32];

// weights in mma-frag layout, hi/lo tf32: [pan][kb][nb(16)][64]
#define OQW  0
#define OKW  1048576
#define OVW  1310720
#define OOW  1572864
#define OGW  2621440
#define OUW  6815744
#define ODW  11010048
#define LSZ  15204352
#define OLM  60817408
#define WTOT 93585408
__device__ uint32_t g_wt_hi[WTOT];
__device__ uint32_t g_wt_lo[WTOT];

// activations in mma-frag layout, hi/lo: [mt][kb][mb(8)][128]
#define AMAX (S * II)
__device__ uint32_t g_a_hi[AMAX];
__device__ uint32_t g_a_lo[AMAX];

__device__ __forceinline__ uint32_t f2tf32(float f) {
    uint32_t u; asm("cvt.rna.tf32.f32 %0, %1;" : "=r"(u) : "f"(f)); return u;
}
__device__ __forceinline__ uint32_t smem_u32(const void* p) {
    uint32_t a;
    asm("{ .reg .u64 t; cvta.to.shared.u64 t, %1; cvt.u32.u64 %0, t; }" : "=r"(a) : "l"(p));
    return a;
}
__device__ __forceinline__ void cp_async16(uint32_t dst, const void* src) {
    asm volatile("cp.async.cg.shared.global [%0], [%1], 16;" :: "r"(dst), "l"(src) : "memory");
}
__device__ __forceinline__ void cp_commit() {
    asm volatile("cp.async.commit_group;" ::: "memory");
}
template <int N>
__device__ __forceinline__ void cp_wait() {
    asm volatile("cp.async.wait_group %0;" :: "n"(N) : "memory");
}

#define MMA_TF32(c, a, b)                                                     \
    asm volatile(                                                             \
        "mma.sync.aligned.m16n8k8.row.col.f32.tf32.tf32.f32 "                 \
        "{%0,%1,%2,%3},{%4,%5,%6,%7},{%8,%9},{%0,%1,%2,%3};"                  \
        : "+f"(c[0]), "+f"(c[1]), "+f"(c[2]), "+f"(c[3])                      \
        : "r"(a.x), "r"(a.y), "r"(a.z), "r"(a.w), "r"(b.x), "r"(b.y))

// ---------------- misc kernels ------------------------------------------------
__global__ void rope_table_kernel() {
    int idx = blockIdx.x * blockDim.x + threadIdx.x;
    if (idx >= S * 32) return;
    int s = idx >> 5, i = idx & 31;
    double invf = exp(-((double)(2 * i) / (double)HD) * log(10000.0));
    float af = (float)s * (float)invf;
    g_cos[idx] = (float)cos((double)af);
    g_sin[idx] = (float)sin((double)af);
}

__global__ void embed_kernel(const float* __restrict__ embed, const int* __restrict__ ids) {
    int idx = blockIdx.x * blockDim.x + threadIdx.x;
    int s = idx / (D / 4), c = idx % (D / 4);
    ((float4*)(g_h + (size_t)s * D))[c] = ((const float4*)(embed + (size_t)ids[s] * D))[c];
}

__global__ void rmsnorm_kernel(const float* __restrict__ X, const float* __restrict__ w,
                               float* __restrict__ Y) {
    int row = blockIdx.x;
    const float* x = X + (size_t)row * D;
    float ss = 0.f;
    for (int i = threadIdx.x; i < D; i += blockDim.x) { float v = x[i]; ss = fmaf(v, v, ss); }
    __shared__ float sred[32];
    #pragma unroll
    for (int off = 16; off; off >>= 1) ss += __shfl_xor_sync(0xffffffffu, ss, off);
    int wid = threadIdx.x >> 5, lid = threadIdx.x & 31;
    if (lid == 0) sred[wid] = ss;
    __syncthreads();
    if (wid == 0) {
        ss = (lid < (int)(blockDim.x >> 5)) ? sred[lid] : 0.f;
        #pragma unroll
        for (int off = 16; off; off >>= 1) ss += __shfl_xor_sync(0xffffffffu, ss, off);
        if (lid == 0) sred[0] = ss;
    }
    __syncthreads();
    float inv = rsqrtf(sred[0] / (float)D + EPSV);
    for (int i = threadIdx.x; i < D; i += blockDim.x)
        Y[(size_t)row * D + i] = w[i] * (x[i] * inv);
}

__global__ void rope_kernel(float* __restrict__ X, int nheads) {
    int idx = blockIdx.x * blockDim.x + threadIdx.x;
    if (idx >= S * nheads * 32) return;
    int i = idx & 31, h = (idx >> 5) % nheads, s = idx / (32 * nheads);
    float c = g_cos[s * 32 + i], sn = g_sin[s * 32 + i];
    float* p = X + (size_t)s * nheads * HD + h * HD;
    float x1 = p[i], x2 = p[i + 32];
    p[i] = x1 * c - x2 * sn;
    p[i + 32] = x2 * c + x1 * sn;
}

__global__ void silu_mul_kernel() {
    int idx = blockIdx.x * blockDim.x + threadIdx.x;
    float4 g = ((const float4*)g_gate)[idx];
    float4 u = ((const float4*)g_up)[idx];
    g.x = g.x / (1.f + expf(-g.x)) * u.x;
    g.y = g.y / (1.f + expf(-g.y)) * u.y;
    g.z = g.z / (1.f + expf(-g.z)) * u.z;
    g.w = g.w / (1.f + expf(-g.w)) * u.w;
    ((float4*)g_gate)[idx] = g;
}

// ---------------- weight prep: W[K][N] -> frag layout hi/lo -------------------
// smem-staged: coalesced LDG, scatter-STS, linear uint4 STG.
// grid (N/128, K/8), block 256
__global__ void wprep_kernel(const float* __restrict__ W, uint32_t* __restrict__ hi,
                             uint32_t* __restrict__ lo, int K, int N) {
    __shared__ uint32_t sh[1024];
    __shared__ uint32_t sl[1024];
    int pan = blockIdx.x, kb = blockIdx.y;
    int r = threadIdx.x & 7;               // k within 8-block
    int n0 = (threadIdx.x >> 3) * 4;       // n within 128
    float4 v = *(const float4*)(W + (size_t)(kb * 8 + r) * N + pan * 128 + n0);
    float f[4] = {v.x, v.y, v.z, v.w};
    #pragma unroll
    for (int j = 0; j < 4; j++) {
        int n = n0 + j;
        int pos = ((n >> 3) << 6) + ((n & 7) << 3) + ((r & 3) << 1) + (r >> 2);
        uint32_t h = f2tf32(f[j]);
        sh[pos] = h;
        sl[pos] = f2tf32(f[j] - __uint_as_float(h));
    }
    __syncthreads();
    size_t base = (size_t)((uint32_t)(pan * (K >> 3) + kb)) * 1024;
    int e = threadIdx.x * 4;
    *(uint4*)(hi + base + e) = *(const uint4*)(sh + e);
    *(uint4*)(lo + base + e) = *(const uint4*)(sl + e);
}

// ---------------- activation prep: A[M][K] -> frag layout hi/lo ---------------
// smem-staged; grid (M/128, K/8), block 256
__global__ void asplit_kernel(const float* __restrict__ A, int K) {
    __shared__ uint32_t sh[1024];
    __shared__ uint32_t sl[1024];
    int mt = blockIdx.x, kb = blockIdx.y;
    int m = threadIdx.x >> 1;
    int k0 = (threadIdx.x & 1) * 4;
    float4 v = *(const float4*)(A + (size_t)(mt * 128 + m) * K + kb * 8 + k0);
    float f[4] = {v.x, v.y, v.z, v.w};
    #pragma unroll
    for (int j = 0; j < 4; j++) {
        int k = k0 + j;
        int lane = ((m & 7) << 2) + (k & 3);
        int reg = ((m >> 3) & 1) + 2 * ((k >> 2) & 1);
        int pos = ((m >> 4) << 7) + lane * 4 + reg;
        uint32_t h = f2tf32(f[j]);
        sh[pos] = h;
        sl[pos] = f2tf32(f[j] - __uint_as_float(h));
    }
    __syncthreads();
    size_t base = (size_t)((uint32_t)(mt * (K >> 3) + kb)) * 1024;
    int e = threadIdx.x * 4;
    *(uint4*)(g_a_hi + base + e) = *(const uint4*)(sh + e);
    *(uint4*)(g_a_lo + base + e) = *(const uint4*)(sl + e);
}

// ---------------- 3xTF32 GEMM, 3-stage cp.async pipeline ----------------------
// block 128x128, BK=16, 256 thr / 8 warps, warp tile 64x32, 2 CTAs/SM
struct GemmSeg {
    const uint32_t* Bhi; const uint32_t* Blo;
    const float* bias; float* C; int N; int nx;
};
// smem: 3 stages x [Ahi 2048 | Alo 2048 | Bhi 2048 | Blo 2048] uint32 = 98304 B
#define SMEM7 98304

__global__ void __launch_bounds__(256, 2)
mm7_kernel(GemmSeg s0, GemmSeg s1, GemmSeg s2, int K, int mode) {
    extern __shared__ __align__(128) uint32_t sm[];

    int bx = blockIdx.x;
    const uint32_t *Bhi, *Blo;
    const float* bias; float* Cp; int N;
    if (bx < s0.nx) { Bhi = s0.Bhi; Blo = s0.Blo; bias = s0.bias; Cp = s0.C; N = s0.N; }
    else if (bx < s0.nx + s1.nx) { bx -= s0.nx; Bhi = s1.Bhi; Blo = s1.Blo; bias = s1.bias; Cp = s1.C; N = s1.N; }
    else { bx -= s0.nx + s1.nx; Bhi = s2.Bhi; Blo = s2.Blo; bias = s2.bias; Cp = s2.C; N = s2.N; }
    const int pan = bx;
    const int mt = blockIdx.y;

    const int tid = threadIdx.x;
    const int lane = tid & 31;
    const int warp = tid >> 5;
    const int wm = warp & 1;       // 64-row half
    const int wn = warp >> 1;      // 32-col quarter (0..3)

    const uint32_t smb = smem_u32(sm);
    const int KB8 = K >> 3;

    float acc[4][4][4];
    #pragma unroll
    for (int i = 0; i < 4; i++)
        #pragma unroll
        for (int j = 0; j < 4; j++)
            #pragma unroll
            for (int r = 0; r < 4; r++) acc[i][j][r] = 0.f;

    auto copy_tile = [&](int t, int buf) {
        const uint32_t* srcA_hi = g_a_hi + ((size_t)(mt * KB8 + 2 * t)) * 1024;
        const uint32_t* srcA_lo = g_a_lo + ((size_t)(mt * KB8 + 2 * t)) * 1024;
        const uint32_t* srcB_hi = Bhi + ((size_t)(pan * KB8 + 2 * t)) * 1024;
        const uint32_t* srcB_lo = Blo + ((size_t)(pan * KB8 + 2 * t)) * 1024;
        uint32_t dst = smb + buf * 32768;
        #pragma unroll
        for (int j = 0; j < 2; j++) {
            int e = (tid + j * 256) * 4;
            cp_async16(dst + e * 4,         srcA_hi + e);
            cp_async16(dst + 8192 + e * 4,  srcA_lo + e);
            cp_async16(dst + 16384 + e * 4, srcB_hi + e);
            cp_async16(dst + 24576 + e * 4, srcB_lo + e);
        }
        cp_commit();
    };

    const int ntiles = K >> 4;
    copy_tile(0, 0);
    if (ntiles > 1) copy_tile(1, 1);

    int buf_idx = 0;
    for (int t = 0; t < ntiles; t++) {
        if (t + 1 < ntiles) cp_wait<1>(); else cp_wait<0>();
        __syncthreads();
        // safe to overwrite buffer (t+2)%3 == (t-1)%3: all warps passed the
        // barrier above, hence finished compute of tile t-1.
        if (t + 2 < ntiles) {
            int b2 = buf_idx + 2; if (b2 >= 3) b2 -= 3;
            copy_tile(t + 2, b2);
        }

        const uint32_t* buf = sm + buf_idx * 8192;
        const uint32_t* Ahi_s = buf;
        const uint32_t* Alo_s = buf + 2048;
        const uint32_t* Bhi_s = buf + 4096;
        const uint32_t* Blo_s = buf + 6144;

        #pragma unroll
        for (int ks = 0; ks < 2; ks++) {
            uint4 af[4];
            uint2 bf[4], bl[4];
            #pragma unroll
            for (int mf = 0; mf < 4; mf++)
                af[mf] = *(const uint4*)&Ahi_s[((ks * 8) + wm * 4 + mf) * 128 + lane * 4];
            #pragma unroll
            for (int nf = 0; nf < 4; nf++)
                bf[nf] = *(const uint2*)&Bhi_s[((ks * 16) + wn * 4 + nf) * 64 + lane * 2];
            #pragma unroll
            for (int mf = 0; mf < 4; mf++)
                #pragma unroll
                for (int nf = 0; nf < 4; nf++)
                    MMA_TF32(acc[mf][nf], af[mf], bf[nf]);
            #pragma unroll
            for (int nf = 0; nf < 4; nf++)
                bl[nf] = *(const uint2*)&Blo_s[((ks * 16) + wn * 4 + nf) * 64 + lane * 2];
            #pragma unroll
            for (int mf = 0; mf < 4; mf++)
                #pragma unroll
                for (int nf = 0; nf < 4; nf++)
                    MMA_TF32(acc[mf][nf], af[mf], bl[nf]);
            #pragma unroll
            for (int mf = 0; mf < 4; mf++)
                af[mf] = *(const uint4*)&Alo_s[((ks * 8) + wm * 4 + mf) * 128 + lane * 4];
            #pragma unroll
            for (int mf = 0; mf < 4; mf++)
                #pragma unroll
                for (int nf = 0; nf < 4; nf++)
                    MMA_TF32(acc[mf][nf], af[mf], bf[nf]);
        }
        buf_idx++; if (buf_idx == 3) buf_idx = 0;
    }

    const int g = lane >> 2, tg = lane & 3;
    const int col0 = pan * 128;
    #pragma unroll
    for (int nf = 0; nf < 4; nf++) {
        int cc = col0 + wn * 32 + nf * 8 + tg * 2;
        float b0 = 0.f, b1 = 0.f;
        if (mode == 0 && bias) { b0 = bias[cc]; b1 = bias[cc + 1]; }
        #pragma unroll
        for (int mf = 0; mf < 4; mf++) {
            int rr = mt * 128 + wm * 64 + mf * 16 + g;
            float2* p0 = (float2*)&Cp[(size_t)rr * N + cc];
            float2* p1 = (float2*)&Cp[(size_t)(rr + 8) * N + cc];
            if (mode == 0) {
                *p0 = make_float2(acc[mf][nf][0] + b0, acc[mf][nf][1] + b1);
                *p1 = make_float2(acc[mf][nf][2] + b0, acc[mf][nf][3] + b1);
            } else {
                float2 o0 = *p0, o1 = *p1;
                o0.x += acc[mf][nf][0]; o0.y += acc[mf][nf][1];
                o1.x += acc[mf][nf][2]; o1.y += acc[mf][nf][3];
                *p0 = o0; *p1 = o1;
            }
        }
    }
}

// ---------------- attention: 2 heads (same KV group) per block ----------------
#define AKV 64
__global__ void __launch_bounds__(256)
attn_kernel() {
    __shared__ float Ks[AKV][HD];
    __shared__ float Vs[AKV][HD];
    const int hq = blockIdx.y * 2 + (threadIdx.x >> 7);   // heads 2y, 2y+1
    const int kvh = hq >> 2;                              // same for both halves
    const int tid128 = threadIdx.x & 127;
    const int row = blockIdx.x * 128 + tid128;

    float qr[HD];
    #pragma unroll
    for (int d = 0; d < HD; d += 4) {
        float4 t = *(const float4*)&g_q[(size_t)row * (HQ * HD) + hq * HD + d];
        qr[d] = t.x; qr[d + 1] = t.y; qr[d + 2] = t.z; qr[d + 3] = t.w;
    }
    float o[HD];
    #pragma unroll
    for (int d = 0; d < HD; d++) o[d] = 0.f;
    float m = -INFINITY, l = 0.f;

    const int kend = (blockIdx.x + 1) * 128;
    for (int j0 = 0; j0 < kend; j0 += AKV) {
        __syncthreads();
        for (int t = threadIdx.x; t < AKV * (HD / 4); t += 256) {
            int r = t / (HD / 4), c = (t % (HD / 4)) * 4;
            size_t g = (size_t)(j0 + r) * (KVH * HD) + kvh * HD + c;
            *(float4*)&Ks[r][c] = *(const float4*)&g_k[g];
            *(float4*)&Vs[r][c] = *(const float4*)&g_v[g];
        }
        __syncthreads();
        int jmax = row + 1 - j0;
        if (jmax > AKV) jmax = AKV;
        for (int j = 0; j < jmax; j++) {
            float s0 = 0.f, s1 = 0.f, s2 = 0.f, s3 = 0.f;
            #pragma unroll
            for (int d = 0; d < HD; d += 4) {
                float4 k4 = *(const float4*)&Ks[j][d];
                s0 = fmaf(qr[d], k4.x, s0);
                s1 = fmaf(qr[d + 1], k4.y, s1);
                s2 = fmaf(qr[d + 2], k4.z, s2);
                s3 = fmaf(qr[d + 3], k4.w, s3);
            }
            float s = ((s0 + s1) + (s2 + s3)) * 0.125f;
            if (s > m) {
                float corr = expf(m - s);
                l *= corr;
                #pragma unroll
                for (int d = 0; d < HD; d++) o[d] *= corr;
                m = s;
            }
            float p = expf(s - m);
            l += p;
            #pragma unroll
            for (int d = 0; d < HD; d += 4) {
                float4 vv = *(const float4*)&Vs[j][d];
                o[d] = fmaf(p, vv.x, o[d]);
                o[d + 1] = fmaf(p, vv.y, o[d + 1]);
                o[d + 2] = fmaf(p, vv.z, o[d + 2]);
                o[d + 3] = fmaf(p, vv.w, o[d + 3]);
            }
        }
    }
    float inv = 1.f / l;
    #pragma unroll
    for (int d = 0; d < HD; d += 4) {
        float4 t = make_float4(o[d] * inv, o[d + 1] * inv, o[d + 2] * inv, o[d + 3] * inv);
        *(float4*)&g_o[(size_t)row * (HQ * HD) + hq * HD + d] = t;
    }
}

// ---------------- host side ---------------------------------------------------
static GemmSeg mkseg(const uint32_t* bh, const uint32_t* bl, const float* bias,
                     float* C, int N, int nx) {
    GemmSeg s; s.Bhi = bh; s.Blo = bl; s.bias = bias; s.C = C; s.N = N; s.nx = nx; return s;
}

extern "C" void kernel_launch(void* const* d_in, const int* in_sizes, int n_in,
                              void* d_out, int out_size) {
    const float* embed  = (const float*)d_in[0];
    const float* ln1    = (const float*)d_in[1];
    const float* qw     = (const float*)d_in[2];
    const float* qb     = (const float*)d_in[3];
    const float* kw     = (const float*)d_in[4];
    const float* kb     = (const float*)d_in[5];
    const float* vw     = (const float*)d_in[6];
    const float* vb     = (const float*)d_in[7];
    const float* ow     = (const float*)d_in[8];
    const float* ln2    = (const float*)d_in[9];
    const float* gw     = (const float*)d_in[10];
    const float* uw     = (const float*)d_in[11];
    const float* dw     = (const float*)d_in[12];
    const float* norm_w = (const float*)d_in[13];
    const float* lm_w   = (const float*)d_in[14];
    const int*   ids    = (const int*)d_in[15];
    float* out = (float*)d_out;

    float *p_h, *p_x, *p_q, *p_k, *p_v, *p_o, *p_gate, *p_up;
    uint32_t *p_whi, *p_wlo;
    cudaGetSymbolAddress((void**)&p_h, g_h);
    cudaGetSymbolAddress((void**)&p_x, g_x);
    cudaGetSymbolAddress((void**)&p_q, g_q);
    cudaGetSymbolAddress((void**)&p_k, g_k);
    cudaGetSymbolAddress((void**)&p_v, g_v);
    cudaGetSymbolAddress((void**)&p_o, g_o);
    cudaGetSymbolAddress((void**)&p_gate, g_gate);
    cudaGetSymbolAddress((void**)&p_up, g_up);
    cudaGetSymbolAddress((void**)&p_whi, g_wt_hi);
    cudaGetSymbolAddress((void**)&p_wlo, g_wt_lo);

    static bool attr_done = false;
    if (!attr_done) {
        cudaFuncSetAttribute(mm7_kernel, cudaFuncAttributeMaxDynamicSharedMemorySize, SMEM7);
        attr_done = true;
    }

    // weight prep: frag layout + hi/lo split  (grid: (N/128, K/8))
    for (int l = 0; l < LAYERS; l++) {
        size_t lo = (size_t)l * LSZ;
        wprep_kernel<<<dim3(8, 128), 256>>>(qw + (size_t)l * 1048576, p_whi + lo + OQW, p_wlo + lo + OQW, 1024, 1024);
        wprep_kernel<<<dim3(2, 128), 256>>>(kw + (size_t)l * 262144, p_whi + lo + OKW, p_wlo + lo + OKW, 1024, 256);
        wprep_kernel<<<dim3(2, 128), 256>>>(vw + (size_t)l * 262144, p_whi + lo + OVW, p_wlo + lo + OVW, 1024, 256);
        wprep_kernel<<<dim3(8, 128), 256>>>(ow + (size_t)l * 1048576, p_whi + lo + OOW, p_wlo + lo + OOW, 1024, 1024);
        wprep_kernel<<<dim3(32, 128), 256>>>(gw + (size_t)l * 4194304, p_whi + lo + OGW, p_wlo + lo + OGW, 1024, 4096);
        wprep_kernel<<<dim3(32, 128), 256>>>(uw + (size_t)l * 4194304, p_whi + lo + OUW, p_wlo + lo + OUW, 1024, 4096);
        wprep_kernel<<<dim3(8, 512), 256>>>(dw + (size_t)l * 4194304, p_whi + lo + ODW, p_wlo + lo + ODW, 4096, 1024);
    }
    wprep_kernel<<<dim3(250, 128), 256>>>(lm_w, p_whi + OLM, p_wlo + OLM, 1024, 32000);

    GemmSeg z = mkseg(nullptr, nullptr, nullptr, nullptr, 0, 0);

    rope_table_kernel<<<(S * 32 + 255) / 256, 256>>>();
    embed_kernel<<<(S * D / 4) / 256, 256>>>(embed, ids);

    for (int l = 0; l < LAYERS; l++) {
        size_t lo = (size_t)l * LSZ;
        rmsnorm_kernel<<<S, 256>>>(p_h, ln1 + (size_t)l * D, p_x);
        asplit_kernel<<<dim3(16, 128), 256>>>(p_x, 1024);
        {
            GemmSeg sq = mkseg(p_whi + lo + OQW, p_wlo + lo + OQW, qb + (size_t)l * HQ * HD, p_q, HQ * HD, 8);
            GemmSeg sk = mkseg(p_whi + lo + OKW, p_wlo + lo + OKW, kb + (size_t)l * KVH * HD, p_k, KVH * HD, 2);
            GemmSeg sv = mkseg(p_whi + lo + OVW, p_wlo + lo + OVW, vb + (size_t)l * KVH * HD, p_v, KVH * HD, 2);
            mm7_kernel<<<dim3(12, 16), 256, SMEM7>>>(sq, sk, sv, D, 0);
        }
        rope_kernel<<<(S * HQ * 32) / 256, 256>>>(p_q, HQ);
        rope_kernel<<<(S * KVH * 32) / 256, 256>>>(p_k, KVH);
        attn_kernel<<<dim3(S / 128, HQ / 2), 256>>>();
        asplit_kernel<<<dim3(16, 128), 256>>>(p_o, 1024);
        {
            GemmSeg so = mkseg(p_whi + lo + OOW, p_wlo + lo + OOW, nullptr, p_h, D, 8);
            mm7_kernel<<<dim3(8, 16), 256, SMEM7>>>(so, z, z, HQ * HD, 1);
        }
        rmsnorm_kernel<<<S, 256>>>(p_h, ln2 + (size_t)l * D, p_x);
        asplit_kernel<<<dim3(16, 128), 256>>>(p_x, 1024);
        {
            GemmSeg sg = mkseg(p_whi + lo + OGW, p_wlo + lo + OGW, nullptr, p_gate, II, 32);
            GemmSeg su = mkseg(p_whi + lo + OUW, p_wlo + lo + OUW, nullptr, p_up, II, 32);
            mm7_kernel<<<dim3(64, 16), 256, SMEM7>>>(sg, su, z, D, 0);
        }
        silu_mul_kernel<<<(S * II / 4) / 256, 256>>>();
        asplit_kernel<<<dim3(16, 512), 256>>>(p_gate, 4096);
        {
            GemmSeg sd = mkseg(p_whi + lo + ODW, p_wlo + lo + ODW, nullptr, p_h, D, 8);
            mm7_kernel<<<dim3(8, 16), 256, SMEM7>>>(sd, z, z, II, 1);
        }
    }

    rmsnorm_kernel<<<S, 256>>>(p_h, norm_w, p_x);
    asplit_kernel<<<dim3(16, 128), 256>>>(p_x, 1024);
    {
        GemmSeg sl = mkseg(p_whi + OLM, p_wlo + OLM, nullptr, out, VV, 250);
        mm7_kernel<<<dim3(250, 16), 256, SMEM7>>>(sl, z, z, D, 0);
    }
}

// round 11
// speedup vs baseline: 1.3440x; 1.0069x over previous
#include <cuda_runtime.h>
#include <math.h>
#include <stdint.h>

#define LAYERS 4
#define S 2048
#define D 1024
#define HQ 16
#define KVH 4
#define HD 64
#define II 4096
#define VV 32000
#define EPSV 1e-6f

__device__ float g_h[S * D];
__device__ float g_x[S * D];
__device__ float g_q[S * HQ * HD];
__device__ float g_k[S * KVH * HD];
__device__ float g_v[S * KVH * HD];
__device__ float g_o[S * HQ * HD];
__device__ float g_gate[S * II];
__device__ float g_up[S * II];
__device__ float g_cos[S * 32];
__device__ float g_sin[S * 32];

// weights in mma-frag layout, hi/lo tf32: [pan][kb][nb(16)][64]
#define OQW  0
#define OKW  1048576
#define OVW  1310720
#define OOW  1572864
#define OGW  2621440
#define OUW  6815744
#define ODW  11010048
#define LSZ  15204352
#define OLM  60817408
#define WTOT 93585408
__device__ uint32_t g_wt_hi[WTOT];
__device__ uint32_t g_wt_lo[WTOT];

// activations in mma-frag layout, hi/lo: [mt][kb][mb(8)][128]
#define AMAX (S * II)
__device__ uint32_t g_a_hi[AMAX];
__device__ uint32_t g_a_lo[AMAX];

__device__ __forceinline__ uint32_t f2tf32(float f) {
    uint32_t u; asm("cvt.rna.tf32.f32 %0, %1;" : "=r"(u) : "f"(f)); return u;
}
__device__ __forceinline__ uint32_t smem_u32(const void* p) {
    uint32_t a;
    asm("{ .reg .u64 t; cvta.to.shared.u64 t, %1; cvt.u32.u64 %0, t; }" : "=r"(a) : "l"(p));
    return a;
}
__device__ __forceinline__ void cp_async16(uint32_t dst, const void* src) {
    asm volatile("cp.async.cg.shared.global [%0], [%1], 16;" :: "r"(dst), "l"(src) : "memory");
}
__device__ __forceinline__ void cp_commit() {
    asm volatile("cp.async.commit_group;" ::: "memory");
}
template <int N>
__device__ __forceinline__ void cp_wait() {
    asm volatile("cp.async.wait_group %0;" :: "n"(N) : "memory");
}

#define MMA_TF32(c, a, b)                                                     \
    asm volatile(                                                             \
        "mma.sync.aligned.m16n8k8.row.col.f32.tf32.tf32.f32 "                 \
        "{%0,%1,%2,%3},{%4,%5,%6,%7},{%8,%9},{%0,%1,%2,%3};"                  \
        : "+f"(c[0]), "+f"(c[1]), "+f"(c[2]), "+f"(c[3])                      \
        : "r"(a.x), "r"(a.y), "r"(a.z), "r"(a.w), "r"(b.x), "r"(b.y))

// ---------------- misc kernels ------------------------------------------------
__global__ void rope_table_kernel() {
    int idx = blockIdx.x * blockDim.x + threadIdx.x;
    if (idx >= S * 32) return;
    int s = idx >> 5, i = idx & 31;
    double invf = exp(-((double)(2 * i) / (double)HD) * log(10000.0));
    float af = (float)s * (float)invf;
    g_cos[idx] = (float)cos((double)af);
    g_sin[idx] = (float)sin((double)af);
}

__global__ void embed_kernel(const float* __restrict__ embed, const int* __restrict__ ids) {
    int idx = blockIdx.x * blockDim.x + threadIdx.x;
    int s = idx / (D / 4), c = idx % (D / 4);
    ((float4*)(g_h + (size_t)s * D))[c] = ((const float4*)(embed + (size_t)ids[s] * D))[c];
}

__global__ void rmsnorm_kernel(const float* __restrict__ X, const float* __restrict__ w,
                               float* __restrict__ Y) {
    int row = blockIdx.x;
    const float* x = X + (size_t)row * D;
    float ss = 0.f;
    for (int i = threadIdx.x; i < D; i += blockDim.x) { float v = x[i]; ss = fmaf(v, v, ss); }
    __shared__ float sred[32];
    #pragma unroll
    for (int off = 16; off; off >>= 1) ss += __shfl_xor_sync(0xffffffffu, ss, off);
    int wid = threadIdx.x >> 5, lid = threadIdx.x & 31;
    if (lid == 0) sred[wid] = ss;
    __syncthreads();
    if (wid == 0) {
        ss = (lid < (int)(blockDim.x >> 5)) ? sred[lid] : 0.f;
        #pragma unroll
        for (int off = 16; off; off >>= 1) ss += __shfl_xor_sync(0xffffffffu, ss, off);
        if (lid == 0) sred[0] = ss;
    }
    __syncthreads();
    float inv = rsqrtf(sred[0] / (float)D + EPSV);
    for (int i = threadIdx.x; i < D; i += blockDim.x)
        Y[(size_t)row * D + i] = w[i] * (x[i] * inv);
}

__global__ void rope_kernel(float* __restrict__ X, int nheads) {
    int idx = blockIdx.x * blockDim.x + threadIdx.x;
    if (idx >= S * nheads * 32) return;
    int i = idx & 31, h = (idx >> 5) % nheads, s = idx / (32 * nheads);
    float c = g_cos[s * 32 + i], sn = g_sin[s * 32 + i];
    float* p = X + (size_t)s * nheads * HD + h * HD;
    float x1 = p[i], x2 = p[i + 32];
    p[i] = x1 * c - x2 * sn;
    p[i + 32] = x2 * c + x1 * sn;
}

// ---------------- weight prep: W[K][N] -> frag layout hi/lo -------------------
// grid (N/128, K/8), block 256
__global__ void wprep_kernel(const float* __restrict__ W, uint32_t* __restrict__ hi,
                             uint32_t* __restrict__ lo, int K, int N) {
    __shared__ uint32_t sh[1024];
    __shared__ uint32_t sl[1024];
    int pan = blockIdx.x, kb = blockIdx.y;
    int r = threadIdx.x & 7;
    int n0 = (threadIdx.x >> 3) * 4;
    float4 v = *(const float4*)(W + (size_t)(kb * 8 + r) * N + pan * 128 + n0);
    float f[4] = {v.x, v.y, v.z, v.w};
    #pragma unroll
    for (int j = 0; j < 4; j++) {
        int n = n0 + j;
        int pos = ((n >> 3) << 6) + ((n & 7) << 3) + ((r & 3) << 1) + (r >> 2);
        uint32_t h = f2tf32(f[j]);
        sh[pos] = h;
        sl[pos] = f2tf32(f[j] - __uint_as_float(h));
    }
    __syncthreads();
    size_t base = (size_t)((uint32_t)(pan * (K >> 3) + kb)) * 1024;
    int e = threadIdx.x * 4;
    *(uint4*)(hi + base + e) = *(const uint4*)(sh + e);
    *(uint4*)(lo + base + e) = *(const uint4*)(sl + e);
}

// ---------------- activation prep: A[M][K] -> frag layout hi/lo ---------------
// MODE 0: plain A ; MODE 1: A = silu(gate) * up  (gate=A, up=U)
// grid (M/128, K/8), block 256
template <int MODE>
__global__ void asplit_kernel(const float* __restrict__ A, const float* __restrict__ U,
                              int K) {
    __shared__ uint32_t sh[1024];
    __shared__ uint32_t sl[1024];
    int mt = blockIdx.x, kb = blockIdx.y;
    int m = threadIdx.x >> 1;
    int k0 = (threadIdx.x & 1) * 4;
    size_t gofs = (size_t)(mt * 128 + m) * K + kb * 8 + k0;
    float4 v = *(const float4*)(A + gofs);
    float f[4] = {v.x, v.y, v.z, v.w};
    if (MODE == 1) {
        float4 u = *(const float4*)(U + gofs);
        float uu[4] = {u.x, u.y, u.z, u.w};
        #pragma unroll
        for (int j = 0; j < 4; j++)
            f[j] = f[j] / (1.f + __expf(-f[j])) * uu[j];
    }
    #pragma unroll
    for (int j = 0; j < 4; j++) {
        int k = k0 + j;
        int lane = ((m & 7) << 2) + (k & 3);
        int reg = ((m >> 3) & 1) + 2 * ((k >> 2) & 1);
        int pos = ((m >> 4) << 7) + lane * 4 + reg;
        uint32_t h = f2tf32(f[j]);
        sh[pos] = h;
        sl[pos] = f2tf32(f[j] - __uint_as_float(h));
    }
    __syncthreads();
    size_t base = (size_t)((uint32_t)(mt * (K >> 3) + kb)) * 1024;
    int e = threadIdx.x * 4;
    *(uint4*)(g_a_hi + base + e) = *(const uint4*)(sh + e);
    *(uint4*)(g_a_lo + base + e) = *(const uint4*)(sl + e);
}

// ---------------- 3xTF32 GEMM, 3-stage cp.async pipeline ----------------------
struct GemmSeg {
    const uint32_t* Bhi; const uint32_t* Blo;
    const float* bias; float* C; int N; int nx;
};
#define SMEM7 98304

__global__ void __launch_bounds__(256, 2)
mm7_kernel(GemmSeg s0, GemmSeg s1, GemmSeg s2, int K, int mode) {
    extern __shared__ __align__(128) uint32_t sm[];

    int bx = blockIdx.x;
    const uint32_t *Bhi, *Blo;
    const float* bias; float* Cp; int N;
    if (bx < s0.nx) { Bhi = s0.Bhi; Blo = s0.Blo; bias = s0.bias; Cp = s0.C; N = s0.N; }
    else if (bx < s0.nx + s1.nx) { bx -= s0.nx; Bhi = s1.Bhi; Blo = s1.Blo; bias = s1.bias; Cp = s1.C; N = s1.N; }
    else { bx -= s0.nx + s1.nx; Bhi = s2.Bhi; Blo = s2.Blo; bias = s2.bias; Cp = s2.C; N = s2.N; }
    const int pan = bx;
    const int mt = blockIdx.y;

    const int tid = threadIdx.x;
    const int lane = tid & 31;
    const int warp = tid >> 5;
    const int wm = warp & 1;
    const int wn = warp >> 1;

    const uint32_t smb = smem_u32(sm);
    const int KB8 = K >> 3;

    float acc[4][4][4];
    #pragma unroll
    for (int i = 0; i < 4; i++)
        #pragma unroll
        for (int j = 0; j < 4; j++)
            #pragma unroll
            for (int r = 0; r < 4; r++) acc[i][j][r] = 0.f;

    auto copy_tile = [&](int t, int buf) {
        const uint32_t* srcA_hi = g_a_hi + ((size_t)(mt * KB8 + 2 * t)) * 1024;
        const uint32_t* srcA_lo = g_a_lo + ((size_t)(mt * KB8 + 2 * t)) * 1024;
        const uint32_t* srcB_hi = Bhi + ((size_t)(pan * KB8 + 2 * t)) * 1024;
        const uint32_t* srcB_lo = Blo + ((size_t)(pan * KB8 + 2 * t)) * 1024;
        uint32_t dst = smb + buf * 32768;
        #pragma unroll
        for (int j = 0; j < 2; j++) {
            int e = (tid + j * 256) * 4;
            cp_async16(dst + e * 4,         srcA_hi + e);
            cp_async16(dst + 8192 + e * 4,  srcA_lo + e);
            cp_async16(dst + 16384 + e * 4, srcB_hi + e);
            cp_async16(dst + 24576 + e * 4, srcB_lo + e);
        }
        cp_commit();
    };

    const int ntiles = K >> 4;
    copy_tile(0, 0);
    if (ntiles > 1) copy_tile(1, 1);

    int buf_idx = 0;
    for (int t = 0; t < ntiles; t++) {
        if (t + 1 < ntiles) cp_wait<1>(); else cp_wait<0>();
        __syncthreads();
        if (t + 2 < ntiles) {
            int b2 = buf_idx + 2; if (b2 >= 3) b2 -= 3;
            copy_tile(t + 2, b2);
        }

        const uint32_t* buf = sm + buf_idx * 8192;
        const uint32_t* Ahi_s = buf;
        const uint32_t* Alo_s = buf + 2048;
        const uint32_t* Bhi_s = buf + 4096;
        const uint32_t* Blo_s = buf + 6144;

        #pragma unroll
        for (int ks = 0; ks < 2; ks++) {
            uint4 af[4];
            uint2 bf[4], bl[4];
            #pragma unroll
            for (int mf = 0; mf < 4; mf++)
                af[mf] = *(const uint4*)&Ahi_s[((ks * 8) + wm * 4 + mf) * 128 + lane * 4];
            #pragma unroll
            for (int nf = 0; nf < 4; nf++)
                bf[nf] = *(const uint2*)&Bhi_s[((ks * 16) + wn * 4 + nf) * 64 + lane * 2];
            #pragma unroll
            for (int mf = 0; mf < 4; mf++)
                #pragma unroll
                for (int nf = 0; nf < 4; nf++)
                    MMA_TF32(acc[mf][nf], af[mf], bf[nf]);
            #pragma unroll
            for (int nf = 0; nf < 4; nf++)
                bl[nf] = *(const uint2*)&Blo_s[((ks * 16) + wn * 4 + nf) * 64 + lane * 2];
            #pragma unroll
            for (int mf = 0; mf < 4; mf++)
                #pragma unroll
                for (int nf = 0; nf < 4; nf++)
                    MMA_TF32(acc[mf][nf], af[mf], bl[nf]);
            #pragma unroll
            for (int mf = 0; mf < 4; mf++)
                af[mf] = *(const uint4*)&Alo_s[((ks * 8) + wm * 4 + mf) * 128 + lane * 4];
            #pragma unroll
            for (int mf = 0; mf < 4; mf++)
                #pragma unroll
                for (int nf = 0; nf < 4; nf++)
                    MMA_TF32(acc[mf][nf], af[mf], bf[nf]);
        }
        buf_idx++; if (buf_idx == 3) buf_idx = 0;
    }

    const int g = lane >> 2, tg = lane & 3;
    const int col0 = pan * 128;
    #pragma unroll
    for (int nf = 0; nf < 4; nf++) {
        int cc = col0 + wn * 32 + nf * 8 + tg * 2;
        float b0 = 0.f, b1 = 0.f;
        if (mode == 0 && bias) { b0 = bias[cc]; b1 = bias[cc + 1]; }
        #pragma unroll
        for (int mf = 0; mf < 4; mf++) {
            int rr = mt * 128 + wm * 64 + mf * 16 + g;
            float2* p0 = (float2*)&Cp[(size_t)rr * N + cc];
            float2* p1 = (float2*)&Cp[(size_t)(rr + 8) * N + cc];
            if (mode == 0) {
                *p0 = make_float2(acc[mf][nf][0] + b0, acc[mf][nf][1] + b1);
                *p1 = make_float2(acc[mf][nf][2] + b0, acc[mf][nf][3] + b1);
            } else {
                float2 o0 = *p0, o1 = *p1;
                o0.x += acc[mf][nf][0]; o0.y += acc[mf][nf][1];
                o1.x += acc[mf][nf][2]; o1.y += acc[mf][nf][3];
                *p0 = o0; *p1 = o1;
            }
        }
    }
}

// ---------------- attention: 2 heads (same KV group) per block ----------------
#define AKV 64
__global__ void __launch_bounds__(256)
attn_kernel() {
    __shared__ float Ks[AKV][HD];
    __shared__ float Vs[AKV][HD];
    const int hq = blockIdx.y * 2 + (threadIdx.x >> 7);
    const int kvh = hq >> 2;
    const int tid128 = threadIdx.x & 127;
    const int row = blockIdx.x * 128 + tid128;

    float qr[HD];
    #pragma unroll
    for (int d = 0; d < HD; d += 4) {
        float4 t = *(const float4*)&g_q[(size_t)row * (HQ * HD) + hq * HD + d];
        qr[d] = t.x * 0.125f; qr[d + 1] = t.y * 0.125f;
        qr[d + 2] = t.z * 0.125f; qr[d + 3] = t.w * 0.125f;
    }
    float o[HD];
    #pragma unroll
    for (int d = 0; d < HD; d++) o[d] = 0.f;
    float m = -INFINITY, l = 0.f;

    const int kend = (blockIdx.x + 1) * 128;
    for (int j0 = 0; j0 < kend; j0 += AKV) {
        __syncthreads();
        for (int t = threadIdx.x; t < AKV * (HD / 4); t += 256) {
            int r = t / (HD / 4), c = (t % (HD / 4)) * 4;
            size_t g = (size_t)(j0 + r) * (KVH * HD) + kvh * HD + c;
            *(float4*)&Ks[r][c] = *(const float4*)&g_k[g];
            *(float4*)&Vs[r][c] = *(const float4*)&g_v[g];
        }
        __syncthreads();
        int jmax = row + 1 - j0;
        if (jmax > AKV) jmax = AKV;
        for (int j = 0; j < jmax; j++) {
            float s0 = 0.f, s1 = 0.f, s2 = 0.f, s3 = 0.f;
            #pragma unroll
            for (int d = 0; d < HD; d += 4) {
                float4 k4 = *(const float4*)&Ks[j][d];
                s0 = fmaf(qr[d], k4.x, s0);
                s1 = fmaf(qr[d + 1], k4.y, s1);
                s2 = fmaf(qr[d + 2], k4.z, s2);
                s3 = fmaf(qr[d + 3], k4.w, s3);
            }
            float s = (s0 + s1) + (s2 + s3);
            if (s > m) {
                float corr = __expf(m - s);   // exp(-inf)=0 first key
                l *= corr;
                #pragma unroll
                for (int d = 0; d < HD; d++) o[d] *= corr;
                m = s;
            }
            float p = __expf(s - m);
            l += p;
            #pragma unroll
            for (int d = 0; d < HD; d += 4) {
                float4 vv = *(const float4*)&Vs[j][d];
                o[d] = fmaf(p, vv.x, o[d]);
                o[d + 1] = fmaf(p, vv.y, o[d + 1]);
                o[d + 2] = fmaf(p, vv.z, o[d + 2]);
                o[d + 3] = fmaf(p, vv.w, o[d + 3]);
            }
        }
    }
    float inv = 1.f / l;
    #pragma unroll
    for (int d = 0; d < HD; d += 4) {
        float4 t = make_float4(o[d] * inv, o[d + 1] * inv, o[d + 2] * inv, o[d + 3] * inv);
        *(float4*)&g_o[(size_t)row * (HQ * HD) + hq * HD + d] = t;
    }
}

// ---------------- host side ---------------------------------------------------
static GemmSeg mkseg(const uint32_t* bh, const uint32_t* bl, const float* bias,
                     float* C, int N, int nx) {
    GemmSeg s; s.Bhi = bh; s.Blo = bl; s.bias = bias; s.C = C; s.N = N; s.nx = nx; return s;
}

extern "C" void kernel_launch(void* const* d_in, const int* in_sizes, int n_in,
                              void* d_out, int out_size) {
    const float* embed  = (const float*)d_in[0];
    const float* ln1    = (const float*)d_in[1];
    const float* qw     = (const float*)d_in[2];
    const float* qb     = (const float*)d_in[3];
    const float* kw     = (const float*)d_in[4];
    const float* kb     = (const float*)d_in[5];
    const float* vw     = (const float*)d_in[6];
    const float* vb     = (const float*)d_in[7];
    const float* ow     = (const float*)d_in[8];
    const float* ln2    = (const float*)d_in[9];
    const float* gw     = (const float*)d_in[10];
    const float* uw     = (const float*)d_in[11];
    const float* dw     = (const float*)d_in[12];
    const float* norm_w = (const float*)d_in[13];
    const float* lm_w   = (const float*)d_in[14];
    const int*   ids    = (const int*)d_in[15];
    float* out = (float*)d_out;

    float *p_h, *p_x, *p_q, *p_k, *p_v, *p_o, *p_gate, *p_up;
    uint32_t *p_whi, *p_wlo;
    cudaGetSymbolAddress((void**)&p_h, g_h);
    cudaGetSymbolAddress((void**)&p_x, g_x);
    cudaGetSymbolAddress((void**)&p_q, g_q);
    cudaGetSymbolAddress((void**)&p_k, g_k);
    cudaGetSymbolAddress((void**)&p_v, g_v);
    cudaGetSymbolAddress((void**)&p_o, g_o);
    cudaGetSymbolAddress((void**)&p_gate, g_gate);
    cudaGetSymbolAddress((void**)&p_up, g_up);
    cudaGetSymbolAddress((void**)&p_whi, g_wt_hi);
    cudaGetSymbolAddress((void**)&p_wlo, g_wt_lo);

    static bool attr_done = false;
    if (!attr_done) {
        cudaFuncSetAttribute(mm7_kernel, cudaFuncAttributeMaxDynamicSharedMemorySize, SMEM7);
        attr_done = true;
    }

    // weight prep: frag layout + hi/lo split  (grid: (N/128, K/8))
    for (int l = 0; l < LAYERS; l++) {
        size_t lo = (size_t)l * LSZ;
        wprep_kernel<<<dim3(8, 128), 256>>>(qw + (size_t)l * 1048576, p_whi + lo + OQW, p_wlo + lo + OQW, 1024, 1024);
        wprep_kernel<<<dim3(2, 128), 256>>>(kw + (size_t)l * 262144, p_whi + lo + OKW, p_wlo + lo + OKW, 1024, 256);
        wprep_kernel<<<dim3(2, 128), 256>>>(vw + (size_t)l * 262144, p_whi + lo + OVW, p_wlo + lo + OVW, 1024, 256);
        wprep_kernel<<<dim3(8, 128), 256>>>(ow + (size_t)l * 1048576, p_whi + lo + OOW, p_wlo + lo + OOW, 1024, 1024);
        wprep_kernel<<<dim3(32, 128), 256>>>(gw + (size_t)l * 4194304, p_whi + lo + OGW, p_wlo + lo + OGW, 1024, 4096);
        wprep_kernel<<<dim3(32, 128), 256>>>(uw + (size_t)l * 4194304, p_whi + lo + OUW, p_wlo + lo + OUW, 1024, 4096);
        wprep_kernel<<<dim3(8, 512), 256>>>(dw + (size_t)l * 4194304, p_whi + lo + ODW, p_wlo + lo + ODW, 4096, 1024);
    }
    wprep_kernel<<<dim3(250, 128), 256>>>(lm_w, p_whi + OLM, p_wlo + OLM, 1024, 32000);

    GemmSeg z = mkseg(nullptr, nullptr, nullptr, nullptr, 0, 0);

    rope_table_kernel<<<(S * 32 + 255) / 256, 256>>>();
    embed_kernel<<<(S * D / 4) / 256, 256>>>(embed, ids);

    for (int l = 0; l < LAYERS; l++) {
        size_t lo = (size_t)l * LSZ;
        rmsnorm_kernel<<<S, 256>>>(p_h, ln1 + (size_t)l * D, p_x);
        asplit_kernel<0><<<dim3(16, 128), 256>>>(p_x, nullptr, 1024);
        {
            GemmSeg sq = mkseg(p_whi + lo + OQW, p_wlo + lo + OQW, qb + (size_t)l * HQ * HD, p_q, HQ * HD, 8);
            GemmSeg sk = mkseg(p_whi + lo + OKW, p_wlo + lo + OKW, kb + (size_t)l * KVH * HD, p_k, KVH * HD, 2);
            GemmSeg sv = mkseg(p_whi + lo + OVW, p_wlo + lo + OVW, vb + (size_t)l * KVH * HD, p_v, KVH * HD, 2);
            mm7_kernel<<<dim3(12, 16), 256, SMEM7>>>(sq, sk, sv, D, 0);
        }
        rope_kernel<<<(S * HQ * 32) / 256, 256>>>(p_q, HQ);
        rope_kernel<<<(S * KVH * 32) / 256, 256>>>(p_k, KVH);
        attn_kernel<<<dim3(S / 128, HQ / 2), 256>>>();
        asplit_kernel<0><<<dim3(16, 128), 256>>>(p_o, nullptr, 1024);
        {
            GemmSeg so = mkseg(p_whi + lo + OOW, p_wlo + lo + OOW, nullptr, p_h, D, 8);
            mm7_kernel<<<dim3(8, 16), 256, SMEM7>>>(so, z, z, HQ * HD, 1);
        }
        rmsnorm_kernel<<<S, 256>>>(p_h, ln2 + (size_t)l * D, p_x);
        asplit_kernel<0><<<dim3(16, 128), 256>>>(p_x, nullptr, 1024);
        {
            GemmSeg sg = mkseg(p_whi + lo + OGW, p_wlo + lo + OGW, nullptr, p_gate, II, 32);
            GemmSeg su = mkseg(p_whi + lo + OUW, p_wlo + lo + OUW, nullptr, p_up, II, 32);
            mm7_kernel<<<dim3(64, 16), 256, SMEM7>>>(sg, su, z, D, 0);
        }
        // fused silu(gate)*up + frag split
        asplit_kernel<1><<<dim3(16, 512), 256>>>(p_gate, p_up, 4096);
        {
            GemmSeg sd = mkseg(p_whi + lo + ODW, p_wlo + lo + ODW, nullptr, p_h, D, 8);
            mm7_kernel<<<dim3(8, 16), 256, SMEM7>>>(sd, z, z, II, 1);
        }
    }

    rmsnorm_kernel<<<S, 256>>>(p_h, norm_w, p_x);
    asplit_kernel<0><<<dim3(16, 128), 256>>>(p_x, nullptr, 1024);
    {
        GemmSeg sl = mkseg(p_whi + OLM, p_wlo + OLM, nullptr, out, VV, 250);
        mm7_kernel<<<dim3(250, 16), 256, SMEM7>>>(sl, z, z, D, 0);
    }
}

// round 12
// speedup vs baseline: 1.3707x; 1.0199x over previous
#include <cuda_runtime.h>
#include <math.h>
#include <stdint.h>

#define LAYERS 4
#define S 2048
#define D 1024
#define HQ 16
#define KVH 4
#define HD 64
#define II 4096
#define VV 32000
#define EPSV 1e-6f

__device__ float g_h[S * D];
__device__ float g_x[S * D];
__device__ float g_q[S * HQ * HD];
__device__ float g_k[S * KVH * HD];
__device__ float g_v[S * KVH * HD];
__device__ float g_o[S * HQ * HD];
__device__ float g_gate[S * II];
__device__ float g_up[S * II];
__device__ float g_cos[S * 32];
__device__ float g_sin[S * 32];

// weights in mma-frag layout, hi/lo tf32: [pan][kb][nb(16)][64]
#define OQW  0
#define OKW  1048576
#define OVW  1310720
#define OOW  1572864
#define OGW  2621440
#define OUW  6815744
#define ODW  11010048
#define LSZ  15204352
#define OLM  60817408
#define WTOT 93585408
__device__ uint32_t g_wt_hi[WTOT];
__device__ uint32_t g_wt_lo[WTOT];

// activations in mma-frag layout, hi/lo: [mt][kb][mb(8)][128]
#define AMAX (S * II)
__device__ uint32_t g_a_hi[AMAX];
__device__ uint32_t g_a_lo[AMAX];

__device__ __forceinline__ uint32_t f2tf32(float f) {
    uint32_t u; asm("cvt.rna.tf32.f32 %0, %1;" : "=r"(u) : "f"(f)); return u;
}
__device__ __forceinline__ uint32_t smem_u32(const void* p) {
    uint32_t a;
    asm("{ .reg .u64 t; cvta.to.shared.u64 t, %1; cvt.u32.u64 %0, t; }" : "=r"(a) : "l"(p));
    return a;
}
__device__ __forceinline__ void cp_async16(uint32_t dst, const void* src) {
    asm volatile("cp.async.cg.shared.global [%0], [%1], 16;" :: "r"(dst), "l"(src) : "memory");
}
__device__ __forceinline__ void cp_commit() {
    asm volatile("cp.async.commit_group;" ::: "memory");
}
template <int N>
__device__ __forceinline__ void cp_wait() {
    asm volatile("cp.async.wait_group %0;" :: "n"(N) : "memory");
}

#define MMA_TF32(c, a, b)                                                     \
    asm volatile(                                                             \
        "mma.sync.aligned.m16n8k8.row.col.f32.tf32.tf32.f32 "                 \
        "{%0,%1,%2,%3},{%4,%5,%6,%7},{%8,%9},{%0,%1,%2,%3};"                  \
        : "+f"(c[0]), "+f"(c[1]), "+f"(c[2]), "+f"(c[3])                      \
        : "r"(a.x), "r"(a.y), "r"(a.z), "r"(a.w), "r"(b.x), "r"(b.y))

// ---------------- misc kernels ------------------------------------------------
__global__ void rope_table_kernel() {
    int idx = blockIdx.x * blockDim.x + threadIdx.x;
    if (idx >= S * 32) return;
    int s = idx >> 5, i = idx & 31;
    double invf = exp(-((double)(2 * i) / (double)HD) * log(10000.0));
    float af = (float)s * (float)invf;
    g_cos[idx] = (float)cos((double)af);
    g_sin[idx] = (float)sin((double)af);
}

__global__ void embed_kernel(const float* __restrict__ embed, const int* __restrict__ ids) {
    int idx = blockIdx.x * blockDim.x + threadIdx.x;
    int s = idx / (D / 4), c = idx % (D / 4);
    ((float4*)(g_h + (size_t)s * D))[c] = ((const float4*)(embed + (size_t)ids[s] * D))[c];
}

__global__ void rmsnorm_kernel(const float* __restrict__ X, const float* __restrict__ w,
                               float* __restrict__ Y) {
    int row = blockIdx.x;
    const float* x = X + (size_t)row * D;
    float ss = 0.f;
    for (int i = threadIdx.x; i < D; i += blockDim.x) { float v = x[i]; ss = fmaf(v, v, ss); }
    __shared__ float sred[32];
    #pragma unroll
    for (int off = 16; off; off >>= 1) ss += __shfl_xor_sync(0xffffffffu, ss, off);
    int wid = threadIdx.x >> 5, lid = threadIdx.x & 31;
    if (lid == 0) sred[wid] = ss;
    __syncthreads();
    if (wid == 0) {
        ss = (lid < (int)(blockDim.x >> 5)) ? sred[lid] : 0.f;
        #pragma unroll
        for (int off = 16; off; off >>= 1) ss += __shfl_xor_sync(0xffffffffu, ss, off);
        if (lid == 0) sred[0] = ss;
    }
    __syncthreads();
    float inv = rsqrtf(sred[0] / (float)D + EPSV);
    for (int i = threadIdx.x; i < D; i += blockDim.x)
        Y[(size_t)row * D + i] = w[i] * (x[i] * inv);
}

__global__ void rope_kernel(float* __restrict__ X, int nheads) {
    int idx = blockIdx.x * blockDim.x + threadIdx.x;
    if (idx >= S * nheads * 32) return;
    int i = idx & 31, h = (idx >> 5) % nheads, s = idx / (32 * nheads);
    float c = g_cos[s * 32 + i], sn = g_sin[s * 32 + i];
    float* p = X + (size_t)s * nheads * HD + h * HD;
    float x1 = p[i], x2 = p[i + 32];
    p[i] = x1 * c - x2 * sn;
    p[i + 32] = x2 * c + x1 * sn;
}

// ---------------- weight prep: W[K][N] -> frag layout hi/lo -------------------
// processes 4 consecutive k-blocks per CTA. grid (N/128, K/32), block 256
__global__ void wprep_kernel(const float* __restrict__ W, uint32_t* __restrict__ hi,
                             uint32_t* __restrict__ lo, int K, int N) {
    __shared__ uint32_t sh[1024];
    __shared__ uint32_t sl[1024];
    int pan = blockIdx.x;
    int r = threadIdx.x & 7;
    int n0 = (threadIdx.x >> 3) * 4;
    #pragma unroll
    for (int i = 0; i < 4; i++) {
        int kb = blockIdx.y * 4 + i;
        float4 v = *(const float4*)(W + (size_t)(kb * 8 + r) * N + pan * 128 + n0);
        float f[4] = {v.x, v.y, v.z, v.w};
        #pragma unroll
        for (int j = 0; j < 4; j++) {
            int n = n0 + j;
            int pos = ((n >> 3) << 6) + ((n & 7) << 3) + ((r & 3) << 1) + (r >> 2);
            uint32_t h = f2tf32(f[j]);
            sh[pos] = h;
            sl[pos] = f2tf32(f[j] - __uint_as_float(h));
        }
        __syncthreads();
        size_t base = (size_t)((uint32_t)(pan * (K >> 3) + kb)) * 1024;
        int e = threadIdx.x * 4;
        *(uint4*)(hi + base + e) = *(const uint4*)(sh + e);
        *(uint4*)(lo + base + e) = *(const uint4*)(sl + e);
        __syncthreads();
    }
}

// ---------------- activation prep: A[M][K] -> frag layout hi/lo ---------------
// MODE 0: plain A ; MODE 1: A = silu(gate) * up. 4 k-blocks per CTA.
// grid (M/128, K/32), block 256
template <int MODE>
__global__ void asplit_kernel(const float* __restrict__ A, const float* __restrict__ U,
                              int K) {
    __shared__ uint32_t sh[1024];
    __shared__ uint32_t sl[1024];
    int mt = blockIdx.x;
    int m = threadIdx.x >> 1;
    int k0 = (threadIdx.x & 1) * 4;
    #pragma unroll
    for (int i = 0; i < 4; i++) {
        int kb = blockIdx.y * 4 + i;
        size_t gofs = (size_t)(mt * 128 + m) * K + kb * 8 + k0;
        float4 v = *(const float4*)(A + gofs);
        float f[4] = {v.x, v.y, v.z, v.w};
        if (MODE == 1) {
            float4 u = *(const float4*)(U + gofs);
            float uu[4] = {u.x, u.y, u.z, u.w};
            #pragma unroll
            for (int j = 0; j < 4; j++)
                f[j] = f[j] / (1.f + __expf(-f[j])) * uu[j];
        }
        #pragma unroll
        for (int j = 0; j < 4; j++) {
            int k = k0 + j;
            int lane = ((m & 7) << 2) + (k & 3);
            int reg = ((m >> 3) & 1) + 2 * ((k >> 2) & 1);
            int pos = ((m >> 4) << 7) + lane * 4 + reg;
            uint32_t h = f2tf32(f[j]);
            sh[pos] = h;
            sl[pos] = f2tf32(f[j] - __uint_as_float(h));
        }
        __syncthreads();
        size_t base = (size_t)((uint32_t)(mt * (K >> 3) + kb)) * 1024;
        int e = threadIdx.x * 4;
        *(uint4*)(g_a_hi + base + e) = *(const uint4*)(sh + e);
        *(uint4*)(g_a_lo + base + e) = *(const uint4*)(sl + e);
        __syncthreads();
    }
}

// ---------------- 3xTF32 GEMM, 3-stage cp.async pipeline, split-K -------------
// mode 0: C = acc + bias ; mode 1: C += acc ; mode 2: atomicAdd (split-K accum)
struct GemmSeg {
    const uint32_t* Bhi; const uint32_t* Blo;
    const float* bias; float* C; int N; int nx;
};
#define SMEM7 98304

__global__ void __launch_bounds__(256, 2)
mm7_kernel(GemmSeg s0, GemmSeg s1, GemmSeg s2, int K, int mode) {
    extern __shared__ __align__(128) uint32_t sm[];

    int bx = blockIdx.x;
    const uint32_t *Bhi, *Blo;
    const float* bias; float* Cp; int N;
    if (bx < s0.nx) { Bhi = s0.Bhi; Blo = s0.Blo; bias = s0.bias; Cp = s0.C; N = s0.N; }
    else if (bx < s0.nx + s1.nx) { bx -= s0.nx; Bhi = s1.Bhi; Blo = s1.Blo; bias = s1.bias; Cp = s1.C; N = s1.N; }
    else { bx -= s0.nx + s1.nx; Bhi = s2.Bhi; Blo = s2.Blo; bias = s2.bias; Cp = s2.C; N = s2.N; }
    const int pan = bx;
    const int mt = blockIdx.y;

    const int tid = threadIdx.x;
    const int lane = tid & 31;
    const int warp = tid >> 5;
    const int wm = warp & 1;
    const int wn = warp >> 1;

    const uint32_t smb = smem_u32(sm);
    const int KB8 = K >> 3;
    const int KB8z = KB8 / (int)gridDim.z;       // k8-blocks this split handles
    const int kb0 = blockIdx.z * KB8z;

    float acc[4][4][4];
    #pragma unroll
    for (int i = 0; i < 4; i++)
        #pragma unroll
        for (int j = 0; j < 4; j++)
            #pragma unroll
            for (int r = 0; r < 4; r++) acc[i][j][r] = 0.f;

    auto copy_tile = [&](int t, int buf) {
        const uint32_t* srcA_hi = g_a_hi + ((size_t)(mt * KB8 + kb0 + 2 * t)) * 1024;
        const uint32_t* srcA_lo = g_a_lo + ((size_t)(mt * KB8 + kb0 + 2 * t)) * 1024;
        const uint32_t* srcB_hi = Bhi + ((size_t)(pan * KB8 + kb0 + 2 * t)) * 1024;
        const uint32_t* srcB_lo = Blo + ((size_t)(pan * KB8 + kb0 + 2 * t)) * 1024;
        uint32_t dst = smb + buf * 32768;
        #pragma unroll
        for (int j = 0; j < 2; j++) {
            int e = (tid + j * 256) * 4;
            cp_async16(dst + e * 4,         srcA_hi + e);
            cp_async16(dst + 8192 + e * 4,  srcA_lo + e);
            cp_async16(dst + 16384 + e * 4, srcB_hi + e);
            cp_async16(dst + 24576 + e * 4, srcB_lo + e);
        }
        cp_commit();
    };

    const int ntiles = KB8z >> 1;
    copy_tile(0, 0);
    if (ntiles > 1) copy_tile(1, 1);

    int buf_idx = 0;
    for (int t = 0; t < ntiles; t++) {
        if (t + 1 < ntiles) cp_wait<1>(); else cp_wait<0>();
        __syncthreads();
        if (t + 2 < ntiles) {
            int b2 = buf_idx + 2; if (b2 >= 3) b2 -= 3;
            copy_tile(t + 2, b2);
        }

        const uint32_t* buf = sm + buf_idx * 8192;
        const uint32_t* Ahi_s = buf;
        const uint32_t* Alo_s = buf + 2048;
        const uint32_t* Bhi_s = buf + 4096;
        const uint32_t* Blo_s = buf + 6144;

        #pragma unroll
        for (int ks = 0; ks < 2; ks++) {
            uint4 af[4];
            uint2 bf[4], bl[4];
            #pragma unroll
            for (int mf = 0; mf < 4; mf++)
                af[mf] = *(const uint4*)&Ahi_s[((ks * 8) + wm * 4 + mf) * 128 + lane * 4];
            #pragma unroll
            for (int nf = 0; nf < 4; nf++)
                bf[nf] = *(const uint2*)&Bhi_s[((ks * 16) + wn * 4 + nf) * 64 + lane * 2];
            #pragma unroll
            for (int mf = 0; mf < 4; mf++)
                #pragma unroll
                for (int nf = 0; nf < 4; nf++)
                    MMA_TF32(acc[mf][nf], af[mf], bf[nf]);
            #pragma unroll
            for (int nf = 0; nf < 4; nf++)
                bl[nf] = *(const uint2*)&Blo_s[((ks * 16) + wn * 4 + nf) * 64 + lane * 2];
            #pragma unroll
            for (int mf = 0; mf < 4; mf++)
                #pragma unroll
                for (int nf = 0; nf < 4; nf++)
                    MMA_TF32(acc[mf][nf], af[mf], bl[nf]);
            #pragma unroll
            for (int mf = 0; mf < 4; mf++)
                af[mf] = *(const uint4*)&Alo_s[((ks * 8) + wm * 4 + mf) * 128 + lane * 4];
            #pragma unroll
            for (int mf = 0; mf < 4; mf++)
                #pragma unroll
                for (int nf = 0; nf < 4; nf++)
                    MMA_TF32(acc[mf][nf], af[mf], bf[nf]);
        }
        buf_idx++; if (buf_idx == 3) buf_idx = 0;
    }

    const int g = lane >> 2, tg = lane & 3;
    const int col0 = pan * 128;
    #pragma unroll
    for (int nf = 0; nf < 4; nf++) {
        int cc = col0 + wn * 32 + nf * 8 + tg * 2;
        float b0 = 0.f, b1 = 0.f;
        if (mode == 0 && bias) { b0 = bias[cc]; b1 = bias[cc + 1]; }
        #pragma unroll
        for (int mf = 0; mf < 4; mf++) {
            int rr = mt * 128 + wm * 64 + mf * 16 + g;
            float* c0 = &Cp[(size_t)rr * N + cc];
            float* c1 = &Cp[(size_t)(rr + 8) * N + cc];
            if (mode == 0) {
                *(float2*)c0 = make_float2(acc[mf][nf][0] + b0, acc[mf][nf][1] + b1);
                *(float2*)c1 = make_float2(acc[mf][nf][2] + b0, acc[mf][nf][3] + b1);
            } else if (mode == 1) {
                float2 o0 = *(float2*)c0, o1 = *(float2*)c1;
                o0.x += acc[mf][nf][0]; o0.y += acc[mf][nf][1];
                o1.x += acc[mf][nf][2]; o1.y += acc[mf][nf][3];
                *(float2*)c0 = o0; *(float2*)c1 = o1;
            } else {
                atomicAdd(c0,     acc[mf][nf][0]);
                atomicAdd(c0 + 1, acc[mf][nf][1]);
                atomicAdd(c1,     acc[mf][nf][2]);
                atomicAdd(c1 + 1, acc[mf][nf][3]);
            }
        }
    }
}

// ---------------- attention: 2 heads (same KV group) per block ----------------
#define AKV 64
__global__ void __launch_bounds__(256)
attn_kernel() {
    __shared__ float Ks[AKV][HD];
    __shared__ float Vs[AKV][HD];
    const int hq = blockIdx.y * 2 + (threadIdx.x >> 7);
    const int kvh = hq >> 2;
    const int tid128 = threadIdx.x & 127;
    const int row = blockIdx.x * 128 + tid128;

    float qr[HD];
    #pragma unroll
    for (int d = 0; d < HD; d += 4) {
        float4 t = *(const float4*)&g_q[(size_t)row * (HQ * HD) + hq * HD + d];
        qr[d] = t.x * 0.125f; qr[d + 1] = t.y * 0.125f;
        qr[d + 2] = t.z * 0.125f; qr[d + 3] = t.w * 0.125f;
    }
    float o[HD];
    #pragma unroll
    for (int d = 0; d < HD; d++) o[d] = 0.f;
    float m = -INFINITY, l = 0.f;

    const int kend = (blockIdx.x + 1) * 128;
    for (int j0 = 0; j0 < kend; j0 += AKV) {
        __syncthreads();
        for (int t = threadIdx.x; t < AKV * (HD / 4); t += 256) {
            int r = t / (HD / 4), c = (t % (HD / 4)) * 4;
            size_t g = (size_t)(j0 + r) * (KVH * HD) + kvh * HD + c;
            *(float4*)&Ks[r][c] = *(const float4*)&g_k[g];
            *(float4*)&Vs[r][c] = *(const float4*)&g_v[g];
        }
        __syncthreads();
        int jmax = row + 1 - j0;
        if (jmax > AKV) jmax = AKV;
        for (int j = 0; j < jmax; j++) {
            float s0 = 0.f, s1 = 0.f, s2 = 0.f, s3 = 0.f;
            #pragma unroll
            for (int d = 0; d < HD; d += 4) {
                float4 k4 = *(const float4*)&Ks[j][d];
                s0 = fmaf(qr[d], k4.x, s0);
                s1 = fmaf(qr[d + 1], k4.y, s1);
                s2 = fmaf(qr[d + 2], k4.z, s2);
                s3 = fmaf(qr[d + 3], k4.w, s3);
            }
            float s = (s0 + s1) + (s2 + s3);
            if (s > m) {
                float corr = __expf(m - s);
                l *= corr;
                #pragma unroll
                for (int d = 0; d < HD; d++) o[d] *= corr;
                m = s;
            }
            float p = __expf(s - m);
            l += p;
            #pragma unroll
            for (int d = 0; d < HD; d += 4) {
                float4 vv = *(const float4*)&Vs[j][d];
                o[d] = fmaf(p, vv.x, o[d]);
                o[d + 1] = fmaf(p, vv.y, o[d + 1]);
                o[d + 2] = fmaf(p, vv.z, o[d + 2]);
                o[d + 3] = fmaf(p, vv.w, o[d + 3]);
            }
        }
    }
    float inv = 1.f / l;
    #pragma unroll
    for (int d = 0; d < HD; d += 4) {
        float4 t = make_float4(o[d] * inv, o[d + 1] * inv, o[d + 2] * inv, o[d + 3] * inv);
        *(float4*)&g_o[(size_t)row * (HQ * HD) + hq * HD + d] = t;
    }
}

// ---------------- host side ---------------------------------------------------
static GemmSeg mkseg(const uint32_t* bh, const uint32_t* bl, const float* bias,
                     float* C, int N, int nx) {
    GemmSeg s; s.Bhi = bh; s.Blo = bl; s.bias = bias; s.C = C; s.N = N; s.nx = nx; return s;
}

extern "C" void kernel_launch(void* const* d_in, const int* in_sizes, int n_in,
                              void* d_out, int out_size) {
    const float* embed  = (const float*)d_in[0];
    const float* ln1    = (const float*)d_in[1];
    const float* qw     = (const float*)d_in[2];
    const float* qb     = (const float*)d_in[3];
    const float* kw     = (const float*)d_in[4];
    const float* kb     = (const float*)d_in[5];
    const float* vw     = (const float*)d_in[6];
    const float* vb     = (const float*)d_in[7];
    const float* ow     = (const float*)d_in[8];
    const float* ln2    = (const float*)d_in[9];
    const float* gw     = (const float*)d_in[10];
    const float* uw     = (const float*)d_in[11];
    const float* dw     = (const float*)d_in[12];
    const float* norm_w = (const float*)d_in[13];
    const float* lm_w   = (const float*)d_in[14];
    const int*   ids    = (const int*)d_in[15];
    float* out = (float*)d_out;

    float *p_h, *p_x, *p_q, *p_k, *p_v, *p_o, *p_gate, *p_up;
    uint32_t *p_whi, *p_wlo;
    cudaGetSymbolAddress((void**)&p_h, g_h);
    cudaGetSymbolAddress((void**)&p_x, g_x);
    cudaGetSymbolAddress((void**)&p_q, g_q);
    cudaGetSymbolAddress((void**)&p_k, g_k);
    cudaGetSymbolAddress((void**)&p_v, g_v);
    cudaGetSymbolAddress((void**)&p_o, g_o);
    cudaGetSymbolAddress((void**)&p_gate, g_gate);
    cudaGetSymbolAddress((void**)&p_up, g_up);
    cudaGetSymbolAddress((void**)&p_whi, g_wt_hi);
    cudaGetSymbolAddress((void**)&p_wlo, g_wt_lo);

    static bool attr_done = false;
    if (!attr_done) {
        cudaFuncSetAttribute(mm7_kernel, cudaFuncAttributeMaxDynamicSharedMemorySize, SMEM7);
        attr_done = true;
    }

    // weight prep: frag layout + hi/lo split  (grid: (N/128, K/32))
    for (int l = 0; l < LAYERS; l++) {
        size_t lo = (size_t)l * LSZ;
        wprep_kernel<<<dim3(8, 32), 256>>>(qw + (size_t)l * 1048576, p_whi + lo + OQW, p_wlo + lo + OQW, 1024, 1024);
        wprep_kernel<<<dim3(2, 32), 256>>>(kw + (size_t)l * 262144, p_whi + lo + OKW, p_wlo + lo + OKW, 1024, 256);
        wprep_kernel<<<dim3(2, 32), 256>>>(vw + (size_t)l * 262144, p_whi + lo + OVW, p_wlo + lo + OVW, 1024, 256);
        wprep_kernel<<<dim3(8, 32), 256>>>(ow + (size_t)l * 1048576, p_whi + lo + OOW, p_wlo + lo + OOW, 1024, 1024);
        wprep_kernel<<<dim3(32, 32), 256>>>(gw + (size_t)l * 4194304, p_whi + lo + OGW, p_wlo + lo + OGW, 1024, 4096);
        wprep_kernel<<<dim3(32, 32), 256>>>(uw + (size_t)l * 4194304, p_whi + lo + OUW, p_wlo + lo + OUW, 1024, 4096);
        wprep_kernel<<<dim3(8, 128), 256>>>(dw + (size_t)l * 4194304, p_whi + lo + ODW, p_wlo + lo + ODW, 4096, 1024);
    }
    wprep_kernel<<<dim3(250, 32), 256>>>(lm_w, p_whi + OLM, p_wlo + OLM, 1024, 32000);

    GemmSeg z = mkseg(nullptr, nullptr, nullptr, nullptr, 0, 0);

    rope_table_kernel<<<(S * 32 + 255) / 256, 256>>>();
    embed_kernel<<<(S * D / 4) / 256, 256>>>(embed, ids);

    for (int l = 0; l < LAYERS; l++) {
        size_t lo = (size_t)l * LSZ;
        rmsnorm_kernel<<<S, 256>>>(p_h, ln1 + (size_t)l * D, p_x);
        asplit_kernel<0><<<dim3(16, 32), 256>>>(p_x, nullptr, 1024);
        {
            GemmSeg sq = mkseg(p_whi + lo + OQW, p_wlo + lo + OQW, qb + (size_t)l * HQ * HD, p_q, HQ * HD, 8);
            GemmSeg sk = mkseg(p_whi + lo + OKW, p_wlo + lo + OKW, kb + (size_t)l * KVH * HD, p_k, KVH * HD, 2);
            GemmSeg sv = mkseg(p_whi + lo + OVW, p_wlo + lo + OVW, vb + (size_t)l * KVH * HD, p_v, KVH * HD, 2);
            mm7_kernel<<<dim3(12, 16, 1), 256, SMEM7>>>(sq, sk, sv, D, 0);
        }
        rope_kernel<<<(S * HQ * 32) / 256, 256>>>(p_q, HQ);
        rope_kernel<<<(S * KVH * 32) / 256, 256>>>(p_k, KVH);
        attn_kernel<<<dim3(S / 128, HQ / 2), 256>>>();
        asplit_kernel<0><<<dim3(16, 32), 256>>>(p_o, nullptr, 1024);
        {
            // O projection: h += o @ ow, split-K=2, atomicAdd accumulation
            GemmSeg so = mkseg(p_whi + lo + OOW, p_wlo + lo + OOW, nullptr, p_h, D, 8);
            mm7_kernel<<<dim3(8, 16, 2), 256, SMEM7>>>(so, z, z, HQ * HD, 2);
        }
        rmsnorm_kernel<<<S, 256>>>(p_h, ln2 + (size_t)l * D, p_x);
        asplit_kernel<0><<<dim3(16, 32), 256>>>(p_x, nullptr, 1024);
        {
            GemmSeg sg = mkseg(p_whi + lo + OGW, p_wlo + lo + OGW, nullptr, p_gate, II, 32);
            GemmSeg su = mkseg(p_whi + lo + OUW, p_wlo + lo + OUW, nullptr, p_up, II, 32);
            mm7_kernel<<<dim3(64, 16, 1), 256, SMEM7>>>(sg, su, z, D, 0);
        }
        // fused silu(gate)*up + frag split
        asplit_kernel<1><<<dim3(16, 128), 256>>>(p_gate, p_up, 4096);
        {
            // down projection: h += act @ dw, split-K=2, atomicAdd accumulation
            GemmSeg sd = mkseg(p_whi + lo + ODW, p_wlo + lo + ODW, nullptr, p_h, D, 8);
            mm7_kernel<<<dim3(8, 16, 2), 256, SMEM7>>>(sd, z, z, II, 2);
        }
    }

    rmsnorm_kernel<<<S, 256>>>(p_h, norm_w, p_x);
    asplit_kernel<0><<<dim3(16, 32), 256>>>(p_x, nullptr, 1024);
    {
        GemmSeg sl = mkseg(p_whi + OLM, p_wlo + OLM, nullptr, out, VV, 250);
        mm7_kernel<<<dim3(250, 16, 1), 256, SMEM7>>>(sl, z, z, D, 0);
    }
}

// round 13
// speedup vs baseline: 1.4457x; 1.0547x over previous
#include <cuda_runtime.h>
#include <math.h>
#include <stdint.h>

#define LAYERS 4
#define S 2048
#define D 1024
#define HQ 16
#define KVH 4
#define HD 64
#define II 4096
#define VV 32000
#define EPSV 1e-6f

__device__ float g_h[S * D];
__device__ float g_x[S * D];
__device__ float g_q[S * HQ * HD];
__device__ float g_k[S * KVH * HD];
__device__ float g_v[S * KVH * HD];
__device__ float g_o[S * HQ * HD];
__device__ float g_gate[S * II];
__device__ float g_up[S * II];
__device__ float g_cos[S * 32];
__device__ float g_sin[S * 32];

// weights in mma-frag layout, hi/lo tf32: [pan][kb][nb(16)][64]
#define OQW  0
#define OKW  1048576
#define OVW  1310720
#define OOW  1572864
#define OGW  2621440
#define OUW  6815744
#define ODW  11010048
#define LSZ  15204352
#define OLM  60817408
#define WTOT 93585408
__device__ uint32_t g_wt_hi[WTOT];
__device__ uint32_t g_wt_lo[WTOT];

// activations in mma-frag layout, hi/lo: [mt][kb][mb(8)][128]
#define AMAX (S * II)
__device__ uint32_t g_a_hi[AMAX];
__device__ uint32_t g_a_lo[AMAX];

__device__ __forceinline__ uint32_t f2tf32(float f) {
    uint32_t u; asm("cvt.rna.tf32.f32 %0, %1;" : "=r"(u) : "f"(f)); return u;
}
__device__ __forceinline__ uint32_t smem_u32(const void* p) {
    uint32_t a;
    asm("{ .reg .u64 t; cvta.to.shared.u64 t, %1; cvt.u32.u64 %0, t; }" : "=r"(a) : "l"(p));
    return a;
}
__device__ __forceinline__ void cp_async16(uint32_t dst, const void* src) {
    asm volatile("cp.async.cg.shared.global [%0], [%1], 16;" :: "r"(dst), "l"(src) : "memory");
}
__device__ __forceinline__ void cp_commit() {
    asm volatile("cp.async.commit_group;" ::: "memory");
}
template <int N>
__device__ __forceinline__ void cp_wait() {
    asm volatile("cp.async.wait_group %0;" :: "n"(N) : "memory");
}

#define MMA_TF32(c, a, b)                                                     \
    asm volatile(                                                             \
        "mma.sync.aligned.m16n8k8.row.col.f32.tf32.tf32.f32 "                 \
        "{%0,%1,%2,%3},{%4,%5,%6,%7},{%8,%9},{%0,%1,%2,%3};"                  \
        : "+f"(c[0]), "+f"(c[1]), "+f"(c[2]), "+f"(c[3])                      \
        : "r"(a.x), "r"(a.y), "r"(a.z), "r"(a.w), "r"(b.x), "r"(b.y))

// ---------------- misc kernels ------------------------------------------------
__global__ void rope_table_kernel() {
    int idx = blockIdx.x * blockDim.x + threadIdx.x;
    if (idx >= S * 32) return;
    int s = idx >> 5, i = idx & 31;
    double invf = exp(-((double)(2 * i) / (double)HD) * log(10000.0));
    float af = (float)s * (float)invf;
    g_cos[idx] = (float)cos((double)af);
    g_sin[idx] = (float)sin((double)af);
}

__global__ void embed_kernel(const float* __restrict__ embed, const int* __restrict__ ids) {
    int idx = blockIdx.x * blockDim.x + threadIdx.x;
    int s = idx / (D / 4), c = idx % (D / 4);
    ((float4*)(g_h + (size_t)s * D))[c] = ((const float4*)(embed + (size_t)ids[s] * D))[c];
}

__global__ void rmsnorm_kernel(const float* __restrict__ X, const float* __restrict__ w,
                               float* __restrict__ Y) {
    int row = blockIdx.x;
    const float* x = X + (size_t)row * D;
    float ss = 0.f;
    for (int i = threadIdx.x; i < D; i += blockDim.x) { float v = x[i]; ss = fmaf(v, v, ss); }
    __shared__ float sred[32];
    #pragma unroll
    for (int off = 16; off; off >>= 1) ss += __shfl_xor_sync(0xffffffffu, ss, off);
    int wid = threadIdx.x >> 5, lid = threadIdx.x & 31;
    if (lid == 0) sred[wid] = ss;
    __syncthreads();
    if (wid == 0) {
        ss = (lid < (int)(blockDim.x >> 5)) ? sred[lid] : 0.f;
        #pragma unroll
        for (int off = 16; off; off >>= 1) ss += __shfl_xor_sync(0xffffffffu, ss, off);
        if (lid == 0) sred[0] = ss;
    }
    __syncthreads();
    float inv = rsqrtf(sred[0] / (float)D + EPSV);
    for (int i = threadIdx.x; i < D; i += blockDim.x)
        Y[(size_t)row * D + i] = w[i] * (x[i] * inv);
}

__global__ void rope_kernel(float* __restrict__ X, int nheads) {
    int idx = blockIdx.x * blockDim.x + threadIdx.x;
    if (idx >= S * nheads * 32) return;
    int i = idx & 31, h = (idx >> 5) % nheads, s = idx / (32 * nheads);
    float c = g_cos[s * 32 + i], sn = g_sin[s * 32 + i];
    float* p = X + (size_t)s * nheads * HD + h * HD;
    float x1 = p[i], x2 = p[i + 32];
    p[i] = x1 * c - x2 * sn;
    p[i + 32] = x2 * c + x1 * sn;
}

// ---------------- weight prep: W[K][N] -> frag layout hi/lo -------------------
// 4 consecutive k-blocks per CTA. grid (N/128, K/32), block 256
__global__ void wprep_kernel(const float* __restrict__ W, uint32_t* __restrict__ hi,
                             uint32_t* __restrict__ lo, int K, int N) {
    __shared__ uint32_t sh[1024];
    __shared__ uint32_t sl[1024];
    int pan = blockIdx.x;
    int r = threadIdx.x & 7;
    int n0 = (threadIdx.x >> 3) * 4;
    #pragma unroll
    for (int i = 0; i < 4; i++) {
        int kb = blockIdx.y * 4 + i;
        float4 v = *(const float4*)(W + (size_t)(kb * 8 + r) * N + pan * 128 + n0);
        float f[4] = {v.x, v.y, v.z, v.w};
        #pragma unroll
        for (int j = 0; j < 4; j++) {
            int n = n0 + j;
            int pos = ((n >> 3) << 6) + ((n & 7) << 3) + ((r & 3) << 1) + (r >> 2);
            uint32_t h = f2tf32(f[j]);
            sh[pos] = h;
            sl[pos] = f2tf32(f[j] - __uint_as_float(h));
        }
        __syncthreads();
        size_t base = (size_t)((uint32_t)(pan * (K >> 3) + kb)) * 1024;
        int e = threadIdx.x * 4;
        *(uint4*)(hi + base + e) = *(const uint4*)(sh + e);
        *(uint4*)(lo + base + e) = *(const uint4*)(sl + e);
        __syncthreads();
    }
}

// ---------------- activation prep: A[M][K] -> frag layout hi/lo ---------------
// MODE 0: plain A ; MODE 1: A = silu(gate) * up. 4 k-blocks per CTA.
template <int MODE>
__global__ void asplit_kernel(const float* __restrict__ A, const float* __restrict__ U,
                              int K) {
    __shared__ uint32_t sh[1024];
    __shared__ uint32_t sl[1024];
    int mt = blockIdx.x;
    int m = threadIdx.x >> 1;
    int k0 = (threadIdx.x & 1) * 4;
    #pragma unroll
    for (int i = 0; i < 4; i++) {
        int kb = blockIdx.y * 4 + i;
        size_t gofs = (size_t)(mt * 128 + m) * K + kb * 8 + k0;
        float4 v = *(const float4*)(A + gofs);
        float f[4] = {v.x, v.y, v.z, v.w};
        if (MODE == 1) {
            float4 u = *(const float4*)(U + gofs);
            float uu[4] = {u.x, u.y, u.z, u.w};
            #pragma unroll
            for (int j = 0; j < 4; j++)
                f[j] = f[j] / (1.f + __expf(-f[j])) * uu[j];
        }
        #pragma unroll
        for (int j = 0; j < 4; j++) {
            int k = k0 + j;
            int lane = ((m & 7) << 2) + (k & 3);
            int reg = ((m >> 3) & 1) + 2 * ((k >> 2) & 1);
            int pos = ((m >> 4) << 7) + lane * 4 + reg;
            uint32_t h = f2tf32(f[j]);
            sh[pos] = h;
            sl[pos] = f2tf32(f[j] - __uint_as_float(h));
        }
        __syncthreads();
        size_t base = (size_t)((uint32_t)(mt * (K >> 3) + kb)) * 1024;
        int e = threadIdx.x * 4;
        *(uint4*)(g_a_hi + base + e) = *(const uint4*)(sh + e);
        *(uint4*)(g_a_lo + base + e) = *(const uint4*)(sl + e);
        __syncthreads();
    }
}

// ---------------- 3x/2x TF32 GEMM, 3-stage cp.async pipeline, split-K ---------
// PASSES=3: hi*hi + hi*loB + loA*hi ; PASSES=2: hi*hi + loA*hi (skips Blo I/O)
// mode 0: C = acc + bias ; mode 1: C += acc ; mode 2: atomicAdd (split-K)
struct GemmSeg {
    const uint32_t* Bhi; const uint32_t* Blo;
    const float* bias; float* C; int N; int nx;
};
#define SMEM7 98304

template <int PASSES>
__global__ void __launch_bounds__(256, 2)
mm7_kernel(GemmSeg s0, GemmSeg s1, GemmSeg s2, int K, int mode) {
    extern __shared__ __align__(128) uint32_t sm[];

    int bx = blockIdx.x;
    const uint32_t *Bhi, *Blo;
    const float* bias; float* Cp; int N;
    if (bx < s0.nx) { Bhi = s0.Bhi; Blo = s0.Blo; bias = s0.bias; Cp = s0.C; N = s0.N; }
    else if (bx < s0.nx + s1.nx) { bx -= s0.nx; Bhi = s1.Bhi; Blo = s1.Blo; bias = s1.bias; Cp = s1.C; N = s1.N; }
    else { bx -= s0.nx + s1.nx; Bhi = s2.Bhi; Blo = s2.Blo; bias = s2.bias; Cp = s2.C; N = s2.N; }
    const int pan = bx;
    const int mt = blockIdx.y;

    const int tid = threadIdx.x;
    const int lane = tid & 31;
    const int warp = tid >> 5;
    const int wm = warp & 1;
    const int wn = warp >> 1;

    const uint32_t smb = smem_u32(sm);
    const int KB8 = K >> 3;
    const int KB8z = KB8 / (int)gridDim.z;
    const int kb0 = blockIdx.z * KB8z;

    float acc[4][4][4];
    #pragma unroll
    for (int i = 0; i < 4; i++)
        #pragma unroll
        for (int j = 0; j < 4; j++)
            #pragma unroll
            for (int r = 0; r < 4; r++) acc[i][j][r] = 0.f;

    auto copy_tile = [&](int t, int buf) {
        const uint32_t* srcA_hi = g_a_hi + ((size_t)(mt * KB8 + kb0 + 2 * t)) * 1024;
        const uint32_t* srcA_lo = g_a_lo + ((size_t)(mt * KB8 + kb0 + 2 * t)) * 1024;
        const uint32_t* srcB_hi = Bhi + ((size_t)(pan * KB8 + kb0 + 2 * t)) * 1024;
        const uint32_t* srcB_lo = Blo + ((size_t)(pan * KB8 + kb0 + 2 * t)) * 1024;
        uint32_t dst = smb + buf * 32768;
        #pragma unroll
        for (int j = 0; j < 2; j++) {
            int e = (tid + j * 256) * 4;
            cp_async16(dst + e * 4,         srcA_hi + e);
            cp_async16(dst + 8192 + e * 4,  srcA_lo + e);
            cp_async16(dst + 16384 + e * 4, srcB_hi + e);
            if (PASSES == 3)
                cp_async16(dst + 24576 + e * 4, srcB_lo + e);
        }
        cp_commit();
    };

    const int ntiles = KB8z >> 1;
    copy_tile(0, 0);
    if (ntiles > 1) copy_tile(1, 1);

    int buf_idx = 0;
    for (int t = 0; t < ntiles; t++) {
        if (t + 1 < ntiles) cp_wait<1>(); else cp_wait<0>();
        __syncthreads();
        if (t + 2 < ntiles) {
            int b2 = buf_idx + 2; if (b2 >= 3) b2 -= 3;
            copy_tile(t + 2, b2);
        }

        const uint32_t* buf = sm + buf_idx * 8192;
        const uint32_t* Ahi_s = buf;
        const uint32_t* Alo_s = buf + 2048;
        const uint32_t* Bhi_s = buf + 4096;
        const uint32_t* Blo_s = buf + 6144;

        #pragma unroll
        for (int ks = 0; ks < 2; ks++) {
            uint4 af[4];
            uint2 bf[4];
            #pragma unroll
            for (int mf = 0; mf < 4; mf++)
                af[mf] = *(const uint4*)&Ahi_s[((ks * 8) + wm * 4 + mf) * 128 + lane * 4];
            #pragma unroll
            for (int nf = 0; nf < 4; nf++)
                bf[nf] = *(const uint2*)&Bhi_s[((ks * 16) + wn * 4 + nf) * 64 + lane * 2];
            // pass 1: hi*hi
            #pragma unroll
            for (int mf = 0; mf < 4; mf++)
                #pragma unroll
                for (int nf = 0; nf < 4; nf++)
                    MMA_TF32(acc[mf][nf], af[mf], bf[nf]);
            // pass 2: hi*lo(B)  (PASSES==3 only)
            if (PASSES == 3) {
                uint2 bl[4];
                #pragma unroll
                for (int nf = 0; nf < 4; nf++)
                    bl[nf] = *(const uint2*)&Blo_s[((ks * 16) + wn * 4 + nf) * 64 + lane * 2];
                #pragma unroll
                for (int mf = 0; mf < 4; mf++)
                    #pragma unroll
                    for (int nf = 0; nf < 4; nf++)
                        MMA_TF32(acc[mf][nf], af[mf], bl[nf]);
            }
            // pass 3: lo(A)*hi
            #pragma unroll
            for (int mf = 0; mf < 4; mf++)
                af[mf] = *(const uint4*)&Alo_s[((ks * 8) + wm * 4 + mf) * 128 + lane * 4];
            #pragma unroll
            for (int mf = 0; mf < 4; mf++)
                #pragma unroll
                for (int nf = 0; nf < 4; nf++)
                    MMA_TF32(acc[mf][nf], af[mf], bf[nf]);
        }
        buf_idx++; if (buf_idx == 3) buf_idx = 0;
    }

    const int g = lane >> 2, tg = lane & 3;
    const int col0 = pan * 128;
    #pragma unroll
    for (int nf = 0; nf < 4; nf++) {
        int cc = col0 + wn * 32 + nf * 8 + tg * 2;
        float b0 = 0.f, b1 = 0.f;
        if (mode == 0 && bias) { b0 = bias[cc]; b1 = bias[cc + 1]; }
        #pragma unroll
        for (int mf = 0; mf < 4; mf++) {
            int rr = mt * 128 + wm * 64 + mf * 16 + g;
            float* c0 = &Cp[(size_t)rr * N + cc];
            float* c1 = &Cp[(size_t)(rr + 8) * N + cc];
            if (mode == 0) {
                *(float2*)c0 = make_float2(acc[mf][nf][0] + b0, acc[mf][nf][1] + b1);
                *(float2*)c1 = make_float2(acc[mf][nf][2] + b0, acc[mf][nf][3] + b1);
            } else if (mode == 1) {
                float2 o0 = *(float2*)c0, o1 = *(float2*)c1;
                o0.x += acc[mf][nf][0]; o0.y += acc[mf][nf][1];
                o1.x += acc[mf][nf][2]; o1.y += acc[mf][nf][3];
                *(float2*)c0 = o0; *(float2*)c1 = o1;
            } else {
                atomicAdd(c0,     acc[mf][nf][0]);
                atomicAdd(c0 + 1, acc[mf][nf][1]);
                atomicAdd(c1,     acc[mf][nf][2]);
                atomicAdd(c1 + 1, acc[mf][nf][3]);
            }
        }
    }
}

// ---------------- attention: 2 heads (same KV group) per block ----------------
#define AKV 64
__global__ void __launch_bounds__(256)
attn_kernel() {
    __shared__ float Ks[AKV][HD];
    __shared__ float Vs[AKV][HD];
    const int hq = blockIdx.y * 2 + (threadIdx.x >> 7);
    const int kvh = hq >> 2;
    const int tid128 = threadIdx.x & 127;
    const int row = blockIdx.x * 128 + tid128;

    float qr[HD];
    #pragma unroll
    for (int d = 0; d < HD; d += 4) {
        float4 t = *(const float4*)&g_q[(size_t)row * (HQ * HD) + hq * HD + d];
        qr[d] = t.x * 0.125f; qr[d + 1] = t.y * 0.125f;
        qr[d + 2] = t.z * 0.125f; qr[d + 3] = t.w * 0.125f;
    }
    float o[HD];
    #pragma unroll
    for (int d = 0; d < HD; d++) o[d] = 0.f;
    float m = -INFINITY, l = 0.f;

    const int kend = (blockIdx.x + 1) * 128;
    for (int j0 = 0; j0 < kend; j0 += AKV) {
        __syncthreads();
        for (int t = threadIdx.x; t < AKV * (HD / 4); t += 256) {
            int r = t / (HD / 4), c = (t % (HD / 4)) * 4;
            size_t g = (size_t)(j0 + r) * (KVH * HD) + kvh * HD + c;
            *(float4*)&Ks[r][c] = *(const float4*)&g_k[g];
            *(float4*)&Vs[r][c] = *(const float4*)&g_v[g];
        }
        __syncthreads();
        int jmax = row + 1 - j0;
        if (jmax > AKV) jmax = AKV;
        for (int j = 0; j < jmax; j++) {
            float s0 = 0.f, s1 = 0.f, s2 = 0.f, s3 = 0.f;
            #pragma unroll
            for (int d = 0; d < HD; d += 4) {
                float4 k4 = *(const float4*)&Ks[j][d];
                s0 = fmaf(qr[d], k4.x, s0);
                s1 = fmaf(qr[d + 1], k4.y, s1);
                s2 = fmaf(qr[d + 2], k4.z, s2);
                s3 = fmaf(qr[d + 3], k4.w, s3);
            }
            float s = (s0 + s1) + (s2 + s3);
            if (s > m) {
                float corr = __expf(m - s);
                l *= corr;
                #pragma unroll
                for (int d = 0; d < HD; d++) o[d] *= corr;
                m = s;
            }
            float p = __expf(s - m);
            l += p;
            #pragma unroll
            for (int d = 0; d < HD; d += 4) {
                float4 vv = *(const float4*)&Vs[j][d];
                o[d] = fmaf(p, vv.x, o[d]);
                o[d + 1] = fmaf(p, vv.y, o[d + 1]);
                o[d + 2] = fmaf(p, vv.z, o[d + 2]);
                o[d + 3] = fmaf(p, vv.w, o[d + 3]);
            }
        }
    }
    float inv = 1.f / l;
    #pragma unroll
    for (int d = 0; d < HD; d += 4) {
        float4 t = make_float4(o[d] * inv, o[d + 1] * inv, o[d + 2] * inv, o[d + 3] * inv);
        *(float4*)&g_o[(size_t)row * (HQ * HD) + hq * HD + d] = t;
    }
}

// ---------------- host side ---------------------------------------------------
static GemmSeg mkseg(const uint32_t* bh, const uint32_t* bl, const float* bias,
                     float* C, int N, int nx) {
    GemmSeg s; s.Bhi = bh; s.Blo = bl; s.bias = bias; s.C = C; s.N = N; s.nx = nx; return s;
}

extern "C" void kernel_launch(void* const* d_in, const int* in_sizes, int n_in,
                              void* d_out, int out_size) {
    const float* embed  = (const float*)d_in[0];
    const float* ln1    = (const float*)d_in[1];
    const float* qw     = (const float*)d_in[2];
    const float* qb     = (const float*)d_in[3];
    const float* kw     = (const float*)d_in[4];
    const float* kb     = (const float*)d_in[5];
    const float* vw     = (const float*)d_in[6];
    const float* vb     = (const float*)d_in[7];
    const float* ow     = (const float*)d_in[8];
    const float* ln2    = (const float*)d_in[9];
    const float* gw     = (const float*)d_in[10];
    const float* uw     = (const float*)d_in[11];
    const float* dw     = (const float*)d_in[12];
    const float* norm_w = (const float*)d_in[13];
    const float* lm_w   = (const float*)d_in[14];
    const int*   ids    = (const int*)d_in[15];
    float* out = (float*)d_out;

    float *p_h, *p_x, *p_q, *p_k, *p_v, *p_o, *p_gate, *p_up;
    uint32_t *p_whi, *p_wlo;
    cudaGetSymbolAddress((void**)&p_h, g_h);
    cudaGetSymbolAddress((void**)&p_x, g_x);
    cudaGetSymbolAddress((void**)&p_q, g_q);
    cudaGetSymbolAddress((void**)&p_k, g_k);
    cudaGetSymbolAddress((void**)&p_v, g_v);
    cudaGetSymbolAddress((void**)&p_o, g_o);
    cudaGetSymbolAddress((void**)&p_gate, g_gate);
    cudaGetSymbolAddress((void**)&p_up, g_up);
    cudaGetSymbolAddress((void**)&p_whi, g_wt_hi);
    cudaGetSymbolAddress((void**)&p_wlo, g_wt_lo);

    static bool attr_done = false;
    if (!attr_done) {
        cudaFuncSetAttribute(mm7_kernel<3>, cudaFuncAttributeMaxDynamicSharedMemorySize, SMEM7);
        cudaFuncSetAttribute(mm7_kernel<2>, cudaFuncAttributeMaxDynamicSharedMemorySize, SMEM7);
        attr_done = true;
    }

    // weight prep
    for (int l = 0; l < LAYERS; l++) {
        size_t lo = (size_t)l * LSZ;
        wprep_kernel<<<dim3(8, 32), 256>>>(qw + (size_t)l * 1048576, p_whi + lo + OQW, p_wlo + lo + OQW, 1024, 1024);
        wprep_kernel<<<dim3(2, 32), 256>>>(kw + (size_t)l * 262144, p_whi + lo + OKW, p_wlo + lo + OKW, 1024, 256);
        wprep_kernel<<<dim3(2, 32), 256>>>(vw + (size_t)l * 262144, p_whi + lo + OVW, p_wlo + lo + OVW, 1024, 256);
        wprep_kernel<<<dim3(8, 32), 256>>>(ow + (size_t)l * 1048576, p_whi + lo + OOW, p_wlo + lo + OOW, 1024, 1024);
        wprep_kernel<<<dim3(32, 32), 256>>>(gw + (size_t)l * 4194304, p_whi + lo + OGW, p_wlo + lo + OGW, 1024, 4096);
        wprep_kernel<<<dim3(32, 32), 256>>>(uw + (size_t)l * 4194304, p_whi + lo + OUW, p_wlo + lo + OUW, 1024, 4096);
        wprep_kernel<<<dim3(8, 128), 256>>>(dw + (size_t)l * 4194304, p_whi + lo + ODW, p_wlo + lo + ODW, 4096, 1024);
    }
    wprep_kernel<<<dim3(250, 32), 256>>>(lm_w, p_whi + OLM, p_wlo + OLM, 1024, 32000);

    GemmSeg z = mkseg(nullptr, nullptr, nullptr, nullptr, 0, 0);

    rope_table_kernel<<<(S * 32 + 255) / 256, 256>>>();
    embed_kernel<<<(S * D / 4) / 256, 256>>>(embed, ids);

    for (int l = 0; l < LAYERS; l++) {
        size_t lo = (size_t)l * LSZ;
        rmsnorm_kernel<<<S, 256>>>(p_h, ln1 + (size_t)l * D, p_x);
        asplit_kernel<0><<<dim3(16, 32), 256>>>(p_x, nullptr, 1024);
        {
            GemmSeg sq = mkseg(p_whi + lo + OQW, p_wlo + lo + OQW, qb + (size_t)l * HQ * HD, p_q, HQ * HD, 8);
            GemmSeg sk = mkseg(p_whi + lo + OKW, p_wlo + lo + OKW, kb + (size_t)l * KVH * HD, p_k, KVH * HD, 2);
            GemmSeg sv = mkseg(p_whi + lo + OVW, p_wlo + lo + OVW, vb + (size_t)l * KVH * HD, p_v, KVH * HD, 2);
            mm7_kernel<3><<<dim3(12, 16, 1), 256, SMEM7>>>(sq, sk, sv, D, 0);
        }
        rope_kernel<<<(S * HQ * 32) / 256, 256>>>(p_q, HQ);
        rope_kernel<<<(S * KVH * 32) / 256, 256>>>(p_k, KVH);
        attn_kernel<<<dim3(S / 128, HQ / 2), 256>>>();
        asplit_kernel<0><<<dim3(16, 32), 256>>>(p_o, nullptr, 1024);
        {
            GemmSeg so = mkseg(p_whi + lo + OOW, p_wlo + lo + OOW, nullptr, p_h, D, 8);
            mm7_kernel<3><<<dim3(8, 16, 2), 256, SMEM7>>>(so, z, z, HQ * HD, 2);
        }
        rmsnorm_kernel<<<S, 256>>>(p_h, ln2 + (size_t)l * D, p_x);
        asplit_kernel<0><<<dim3(16, 32), 256>>>(p_x, nullptr, 1024);
        {
            GemmSeg sg = mkseg(p_whi + lo + OGW, p_wlo + lo + OGW, nullptr, p_gate, II, 32);
            GemmSeg su = mkseg(p_whi + lo + OUW, p_wlo + lo + OUW, nullptr, p_up, II, 32);
            mm7_kernel<3><<<dim3(64, 16, 1), 256, SMEM7>>>(sg, su, z, D, 0);
        }
        asplit_kernel<1><<<dim3(16, 128), 256>>>(p_gate, p_up, 4096);
        {
            GemmSeg sd = mkseg(p_whi + lo + ODW, p_wlo + lo + ODW, nullptr, p_h, D, 8);
            mm7_kernel<3><<<dim3(8, 16, 2), 256, SMEM7>>>(sd, z, z, II, 2);
        }
    }

    rmsnorm_kernel<<<S, 256>>>(p_h, norm_w, p_x);
    asplit_kernel<0><<<dim3(16, 32), 256>>>(p_x, nullptr, 1024);
    {
        // LM head: final op, no error compounding -> 2-pass tf32 (hi*hi + loA*hi)
        GemmSeg sl = mkseg(p_whi + OLM, p_wlo + OLM, nullptr, out, VV, 250);
        mm7_kernel<2><<<dim3(250, 16, 1), 256, SMEM7>>>(sl, z, z, D, 0);
    }
}

// round 14
// speedup vs baseline: 1.5488x; 1.0713x over previous
#include <cuda_runtime.h>
#include <math.h>
#include <stdint.h>

#define LAYERS 4
#define S 2048
#define D 1024
#define HQ 16
#define KVH 4
#define HD 64
#define II 4096
#define VV 32000
#define EPSV 1e-6f

__device__ float g_h[S * D];
__device__ float g_q[S * HQ * HD];
__device__ float g_k[S * KVH * HD];
__device__ float g_v[S * KVH * HD];
__device__ float g_o[S * HQ * HD];
__device__ float g_gate[S * II];
__device__ float g_up[S * II];
__device__ float g_cos[S * 32];
__device__ float g_sin[S * 32];
__device__ float g_rms[S];

// weights in mma-frag layout, hi/lo tf32: [pan][kb][nb(16)][64]
#define OQW  0
#define OKW  1048576
#define OVW  1310720
#define OOW  1572864
#define OGW  2621440
#define OUW  6815744
#define ODW  11010048
#define LSZ  15204352
#define OLM  60817408
#define WTOT 93585408
__device__ uint32_t g_wt_hi[WTOT];
__device__ uint32_t g_wt_lo[WTOT];

// activations in mma-frag layout, hi/lo: [mt][kb][mb(8)][128]
#define AMAX (S * II)
__device__ uint32_t g_a_hi[AMAX];
__device__ uint32_t g_a_lo[AMAX];

__device__ __forceinline__ uint32_t f2tf32(float f) {
    uint32_t u; asm("cvt.rna.tf32.f32 %0, %1;" : "=r"(u) : "f"(f)); return u;
}
__device__ __forceinline__ uint32_t smem_u32(const void* p) {
    uint32_t a;
    asm("{ .reg .u64 t; cvta.to.shared.u64 t, %1; cvt.u32.u64 %0, t; }" : "=r"(a) : "l"(p));
    return a;
}
__device__ __forceinline__ void cp_async16(uint32_t dst, const void* src) {
    asm volatile("cp.async.cg.shared.global [%0], [%1], 16;" :: "r"(dst), "l"(src) : "memory");
}
__device__ __forceinline__ void cp_commit() {
    asm volatile("cp.async.commit_group;" ::: "memory");
}
template <int N>
__device__ __forceinline__ void cp_wait() {
    asm volatile("cp.async.wait_group %0;" :: "n"(N) : "memory");
}

#define MMA_TF32(c, a, b)                                                     \
    asm volatile(                                                             \
        "mma.sync.aligned.m16n8k8.row.col.f32.tf32.tf32.f32 "                 \
        "{%0,%1,%2,%3},{%4,%5,%6,%7},{%8,%9},{%0,%1,%2,%3};"                  \
        : "+f"(c[0]), "+f"(c[1]), "+f"(c[2]), "+f"(c[3])                      \
        : "r"(a.x), "r"(a.y), "r"(a.z), "r"(a.w), "r"(b.x), "r"(b.y))

// ---------------- misc kernels ------------------------------------------------
__global__ void rope_table_kernel() {
    int idx = blockIdx.x * blockDim.x + threadIdx.x;
    if (idx >= S * 32) return;
    int s = idx >> 5, i = idx & 31;
    double invf = exp(-((double)(2 * i) / (double)HD) * log(10000.0));
    float af = (float)s * (float)invf;
    g_cos[idx] = (float)cos((double)af);
    g_sin[idx] = (float)sin((double)af);
}

__global__ void embed_kernel(const float* __restrict__ embed, const int* __restrict__ ids) {
    int idx = blockIdx.x * blockDim.x + threadIdx.x;
    int s = idx / (D / 4), c = idx % (D / 4);
    ((float4*)(g_h + (size_t)s * D))[c] = ((const float4*)(embed + (size_t)ids[s] * D))[c];
}

// per-row rms scale only (inv stored in g_rms; apply fused into asplit<2>)
__global__ void rms_scale_kernel(const float* __restrict__ X) {
    int row = blockIdx.x;
    const float* x = X + (size_t)row * D;
    float ss = 0.f;
    for (int i = threadIdx.x; i < D; i += blockDim.x) { float v = x[i]; ss = fmaf(v, v, ss); }
    __shared__ float sred[32];
    #pragma unroll
    for (int off = 16; off; off >>= 1) ss += __shfl_xor_sync(0xffffffffu, ss, off);
    int wid = threadIdx.x >> 5, lid = threadIdx.x & 31;
    if (lid == 0) sred[wid] = ss;
    __syncthreads();
    if (wid == 0) {
        ss = (lid < (int)(blockDim.x >> 5)) ? sred[lid] : 0.f;
        #pragma unroll
        for (int off = 16; off; off >>= 1) ss += __shfl_xor_sync(0xffffffffu, ss, off);
        if (lid == 0) g_rms[row] = rsqrtf(ss / (float)D + EPSV);
    }
}

__global__ void rope_kernel(float* __restrict__ X, int nheads) {
    int idx = blockIdx.x * blockDim.x + threadIdx.x;
    if (idx >= S * nheads * 32) return;
    int i = idx & 31, h = (idx >> 5) % nheads, s = idx / (32 * nheads);
    float c = g_cos[s * 32 + i], sn = g_sin[s * 32 + i];
    float* p = X + (size_t)s * nheads * HD + h * HD;
    float x1 = p[i], x2 = p[i + 32];
    p[i] = x1 * c - x2 * sn;
    p[i + 32] = x2 * c + x1 * sn;
}

// ---------------- weight prep: W[K][N] -> frag layout hi(/lo) -----------------
// WLO=false for weights consumed by 2-pass GEMMs (lo never read).
template <bool WLO>
__global__ void wprep_kernel(const float* __restrict__ W, uint32_t* __restrict__ hi,
                             uint32_t* __restrict__ lo, int K, int N) {
    __shared__ uint32_t sh[1024];
    __shared__ uint32_t sl[1024];
    int pan = blockIdx.x;
    int r = threadIdx.x & 7;
    int n0 = (threadIdx.x >> 3) * 4;
    #pragma unroll
    for (int i = 0; i < 4; i++) {
        int kb = blockIdx.y * 4 + i;
        float4 v = *(const float4*)(W + (size_t)(kb * 8 + r) * N + pan * 128 + n0);
        float f[4] = {v.x, v.y, v.z, v.w};
        #pragma unroll
        for (int j = 0; j < 4; j++) {
            int n = n0 + j;
            int pos = ((n >> 3) << 6) + ((n & 7) << 3) + ((r & 3) << 1) + (r >> 2);
            uint32_t h = f2tf32(f[j]);
            sh[pos] = h;
            if (WLO) sl[pos] = f2tf32(f[j] - __uint_as_float(h));
        }
        __syncthreads();
        size_t base = (size_t)((uint32_t)(pan * (K >> 3) + kb)) * 1024;
        int e = threadIdx.x * 4;
        *(uint4*)(hi + base + e) = *(const uint4*)(sh + e);
        if (WLO) *(uint4*)(lo + base + e) = *(const uint4*)(sl + e);
        __syncthreads();
    }
}

// ---------------- activation prep: A[M][K] -> frag layout hi/lo ---------------
// MODE 0: plain ; MODE 1: silu(A)*U ; MODE 2: rmsnorm-apply w[col]*A*g_rms[row]
template <int MODE>
__global__ void asplit_kernel(const float* __restrict__ A, const float* __restrict__ U,
                              const float* __restrict__ w, int K) {
    __shared__ uint32_t sh[1024];
    __shared__ uint32_t sl[1024];
    int mt = blockIdx.x;
    int m = threadIdx.x >> 1;
    int k0 = (threadIdx.x & 1) * 4;
    float rscale = (MODE == 2) ? g_rms[mt * 128 + m] : 0.f;
    #pragma unroll
    for (int i = 0; i < 4; i++) {
        int kb = blockIdx.y * 4 + i;
        size_t gofs = (size_t)(mt * 128 + m) * K + kb * 8 + k0;
        float4 v = *(const float4*)(A + gofs);
        float f[4] = {v.x, v.y, v.z, v.w};
        if (MODE == 1) {
            float4 u = *(const float4*)(U + gofs);
            float uu[4] = {u.x, u.y, u.z, u.w};
            #pragma unroll
            for (int j = 0; j < 4; j++)
                f[j] = f[j] / (1.f + __expf(-f[j])) * uu[j];
        } else if (MODE == 2) {
            float4 ww = *(const float4*)(w + kb * 8 + k0);
            float wv[4] = {ww.x, ww.y, ww.z, ww.w};
            #pragma unroll
            for (int j = 0; j < 4; j++)
                f[j] = wv[j] * (f[j] * rscale);
        }
        #pragma unroll
        for (int j = 0; j < 4; j++) {
            int k = k0 + j;
            int lane = ((m & 7) << 2) + (k & 3);
            int reg = ((m >> 3) & 1) + 2 * ((k >> 2) & 1);
            int pos = ((m >> 4) << 7) + lane * 4 + reg;
            uint32_t h = f2tf32(f[j]);
            sh[pos] = h;
            sl[pos] = f2tf32(f[j] - __uint_as_float(h));
        }
        __syncthreads();
        size_t base = (size_t)((uint32_t)(mt * (K >> 3) + kb)) * 1024;
        int e = threadIdx.x * 4;
        *(uint4*)(g_a_hi + base + e) = *(const uint4*)(sh + e);
        *(uint4*)(g_a_lo + base + e) = *(const uint4*)(sl + e);
        __syncthreads();
    }
}

// ---------------- 3x/2x TF32 GEMM, 3-stage cp.async pipeline, split-K ---------
struct GemmSeg {
    const uint32_t* Bhi; const uint32_t* Blo;
    const float* bias; float* C; int N; int nx;
};
#define SMEM7 98304

template <int PASSES>
__global__ void __launch_bounds__(256, 2)
mm7_kernel(GemmSeg s0, GemmSeg s1, GemmSeg s2, int K, int mode) {
    extern __shared__ __align__(128) uint32_t sm[];

    int bx = blockIdx.x;
    const uint32_t *Bhi, *Blo;
    const float* bias; float* Cp; int N;
    if (bx < s0.nx) { Bhi = s0.Bhi; Blo = s0.Blo; bias = s0.bias; Cp = s0.C; N = s0.N; }
    else if (bx < s0.nx + s1.nx) { bx -= s0.nx; Bhi = s1.Bhi; Blo = s1.Blo; bias = s1.bias; Cp = s1.C; N = s1.N; }
    else { bx -= s0.nx + s1.nx; Bhi = s2.Bhi; Blo = s2.Blo; bias = s2.bias; Cp = s2.C; N = s2.N; }
    const int pan = bx;
    const int mt = blockIdx.y;

    const int tid = threadIdx.x;
    const int lane = tid & 31;
    const int warp = tid >> 5;
    const int wm = warp & 1;
    const int wn = warp >> 1;

    const uint32_t smb = smem_u32(sm);
    const int KB8 = K >> 3;
    const int KB8z = KB8 / (int)gridDim.z;
    const int kb0 = blockIdx.z * KB8z;

    float acc[4][4][4];
    #pragma unroll
    for (int i = 0; i < 4; i++)
        #pragma unroll
        for (int j = 0; j < 4; j++)
            #pragma unroll
            for (int r = 0; r < 4; r++) acc[i][j][r] = 0.f;

    auto copy_tile = [&](int t, int buf) {
        const uint32_t* srcA_hi = g_a_hi + ((size_t)(mt * KB8 + kb0 + 2 * t)) * 1024;
        const uint32_t* srcA_lo = g_a_lo + ((size_t)(mt * KB8 + kb0 + 2 * t)) * 1024;
        const uint32_t* srcB_hi = Bhi + ((size_t)(pan * KB8 + kb0 + 2 * t)) * 1024;
        const uint32_t* srcB_lo = Blo + ((size_t)(pan * KB8 + kb0 + 2 * t)) * 1024;
        uint32_t dst = smb + buf * 32768;
        #pragma unroll
        for (int j = 0; j < 2; j++) {
            int e = (tid + j * 256) * 4;
            cp_async16(dst + e * 4,         srcA_hi + e);
            cp_async16(dst + 8192 + e * 4,  srcA_lo + e);
            cp_async16(dst + 16384 + e * 4, srcB_hi + e);
            if (PASSES == 3)
                cp_async16(dst + 24576 + e * 4, srcB_lo + e);
        }
        cp_commit();
    };

    const int ntiles = KB8z >> 1;
    copy_tile(0, 0);
    if (ntiles > 1) copy_tile(1, 1);

    int buf_idx = 0;
    for (int t = 0; t < ntiles; t++) {
        if (t + 1 < ntiles) cp_wait<1>(); else cp_wait<0>();
        __syncthreads();
        if (t + 2 < ntiles) {
            int b2 = buf_idx + 2; if (b2 >= 3) b2 -= 3;
            copy_tile(t + 2, b2);
        }

        const uint32_t* buf = sm + buf_idx * 8192;
        const uint32_t* Ahi_s = buf;
        const uint32_t* Alo_s = buf + 2048;
        const uint32_t* Bhi_s = buf + 4096;
        const uint32_t* Blo_s = buf + 6144;

        #pragma unroll
        for (int ks = 0; ks < 2; ks++) {
            uint4 af[4];
            uint2 bf[4];
            #pragma unroll
            for (int mf = 0; mf < 4; mf++)
                af[mf] = *(const uint4*)&Ahi_s[((ks * 8) + wm * 4 + mf) * 128 + lane * 4];
            #pragma unroll
            for (int nf = 0; nf < 4; nf++)
                bf[nf] = *(const uint2*)&Bhi_s[((ks * 16) + wn * 4 + nf) * 64 + lane * 2];
            #pragma unroll
            for (int mf = 0; mf < 4; mf++)
                #pragma unroll
                for (int nf = 0; nf < 4; nf++)
                    MMA_TF32(acc[mf][nf], af[mf], bf[nf]);
            if (PASSES == 3) {
                uint2 bl[4];
                #pragma unroll
                for (int nf = 0; nf < 4; nf++)
                    bl[nf] = *(const uint2*)&Blo_s[((ks * 16) + wn * 4 + nf) * 64 + lane * 2];
                #pragma unroll
                for (int mf = 0; mf < 4; mf++)
                    #pragma unroll
                    for (int nf = 0; nf < 4; nf++)
                        MMA_TF32(acc[mf][nf], af[mf], bl[nf]);
            }
            #pragma unroll
            for (int mf = 0; mf < 4; mf++)
                af[mf] = *(const uint4*)&Alo_s[((ks * 8) + wm * 4 + mf) * 128 + lane * 4];
            #pragma unroll
            for (int mf = 0; mf < 4; mf++)
                #pragma unroll
                for (int nf = 0; nf < 4; nf++)
                    MMA_TF32(acc[mf][nf], af[mf], bf[nf]);
        }
        buf_idx++; if (buf_idx == 3) buf_idx = 0;
    }

    const int g = lane >> 2, tg = lane & 3;
    const int col0 = pan * 128;
    #pragma unroll
    for (int nf = 0; nf < 4; nf++) {
        int cc = col0 + wn * 32 + nf * 8 + tg * 2;
        float b0 = 0.f, b1 = 0.f;
        if (mode == 0 && bias) { b0 = bias[cc]; b1 = bias[cc + 1]; }
        #pragma unroll
        for (int mf = 0; mf < 4; mf++) {
            int rr = mt * 128 + wm * 64 + mf * 16 + g;
            float* c0 = &Cp[(size_t)rr * N + cc];
            float* c1 = &Cp[(size_t)(rr + 8) * N + cc];
            if (mode == 0) {
                *(float2*)c0 = make_float2(acc[mf][nf][0] + b0, acc[mf][nf][1] + b1);
                *(float2*)c1 = make_float2(acc[mf][nf][2] + b0, acc[mf][nf][3] + b1);
            } else if (mode == 1) {
                float2 o0 = *(float2*)c0, o1 = *(float2*)c1;
                o0.x += acc[mf][nf][0]; o0.y += acc[mf][nf][1];
                o1.x += acc[mf][nf][2]; o1.y += acc[mf][nf][3];
                *(float2*)c0 = o0; *(float2*)c1 = o1;
            } else {
                atomicAdd(c0,     acc[mf][nf][0]);
                atomicAdd(c0 + 1, acc[mf][nf][1]);
                atomicAdd(c1,     acc[mf][nf][2]);
                atomicAdd(c1 + 1, acc[mf][nf][3]);
            }
        }
    }
}

// ---------------- attention: 2 heads (same KV group) per block ----------------
#define AKV 64
__global__ void __launch_bounds__(256)
attn_kernel() {
    __shared__ float Ks[AKV][HD];
    __shared__ float Vs[AKV][HD];
    const int hq = blockIdx.y * 2 + (threadIdx.x >> 7);
    const int kvh = hq >> 2;
    const int tid128 = threadIdx.x & 127;
    const int row = blockIdx.x * 128 + tid128;

    float qr[HD];
    #pragma unroll
    for (int d = 0; d < HD; d += 4) {
        float4 t = *(const float4*)&g_q[(size_t)row * (HQ * HD) + hq * HD + d];
        qr[d] = t.x * 0.125f; qr[d + 1] = t.y * 0.125f;
        qr[d + 2] = t.z * 0.125f; qr[d + 3] = t.w * 0.125f;
    }
    float o[HD];
    #pragma unroll
    for (int d = 0; d < HD; d++) o[d] = 0.f;
    float m = -INFINITY, l = 0.f;

    const int kend = (blockIdx.x + 1) * 128;
    for (int j0 = 0; j0 < kend; j0 += AKV) {
        __syncthreads();
        for (int t = threadIdx.x; t < AKV * (HD / 4); t += 256) {
            int r = t / (HD / 4), c = (t % (HD / 4)) * 4;
            size_t g = (size_t)(j0 + r) * (KVH * HD) + kvh * HD + c;
            *(float4*)&Ks[r][c] = *(const float4*)&g_k[g];
            *(float4*)&Vs[r][c] = *(const float4*)&g_v[g];
        }
        __syncthreads();
        int jmax = row + 1 - j0;
        if (jmax > AKV) jmax = AKV;
        for (int j = 0; j < jmax; j++) {
            float s0 = 0.f, s1 = 0.f, s2 = 0.f, s3 = 0.f;
            #pragma unroll
            for (int d = 0; d < HD; d += 4) {
                float4 k4 = *(const float4*)&Ks[j][d];
                s0 = fmaf(qr[d], k4.x, s0);
                s1 = fmaf(qr[d + 1], k4.y, s1);
                s2 = fmaf(qr[d + 2], k4.z, s2);
                s3 = fmaf(qr[d + 3], k4.w, s3);
            }
            float s = (s0 + s1) + (s2 + s3);
            if (s > m) {
                float corr = __expf(m - s);
                l *= corr;
                #pragma unroll
                for (int d = 0; d < HD; d++) o[d] *= corr;
                m = s;
            }
            float p = __expf(s - m);
            l += p;
            #pragma unroll
            for (int d = 0; d < HD; d += 4) {
                float4 vv = *(const float4*)&Vs[j][d];
                o[d] = fmaf(p, vv.x, o[d]);
                o[d + 1] = fmaf(p, vv.y, o[d + 1]);
                o[d + 2] = fmaf(p, vv.z, o[d + 2]);
                o[d + 3] = fmaf(p, vv.w, o[d + 3]);
            }
        }
    }
    float inv = 1.f / l;
    #pragma unroll
    for (int d = 0; d < HD; d += 4) {
        float4 t = make_float4(o[d] * inv, o[d + 1] * inv, o[d + 2] * inv, o[d + 3] * inv);
        *(float4*)&g_o[(size_t)row * (HQ * HD) + hq * HD + d] = t;
    }
}

// ---------------- host side ---------------------------------------------------
static GemmSeg mkseg(const uint32_t* bh, const uint32_t* bl, const float* bias,
                     float* C, int N, int nx) {
    GemmSeg s; s.Bhi = bh; s.Blo = bl; s.bias = bias; s.C = C; s.N = N; s.nx = nx; return s;
}

extern "C" void kernel_launch(void* const* d_in, const int* in_sizes, int n_in,
                              void* d_out, int out_size) {
    const float* embed  = (const float*)d_in[0];
    const float* ln1    = (const float*)d_in[1];
    const float* qw     = (const float*)d_in[2];
    const float* qb     = (const float*)d_in[3];
    const float* kw     = (const float*)d_in[4];
    const float* kb     = (const float*)d_in[5];
    const float* vw     = (const float*)d_in[6];
    const float* vb     = (const float*)d_in[7];
    const float* ow     = (const float*)d_in[8];
    const float* ln2    = (const float*)d_in[9];
    const float* gw     = (const float*)d_in[10];
    const float* uw     = (const float*)d_in[11];
    const float* dw     = (const float*)d_in[12];
    const float* norm_w = (const float*)d_in[13];
    const float* lm_w   = (const float*)d_in[14];
    const int*   ids    = (const int*)d_in[15];
    float* out = (float*)d_out;

    float *p_h, *p_q, *p_k, *p_v, *p_o, *p_gate, *p_up;
    uint32_t *p_whi, *p_wlo;
    cudaGetSymbolAddress((void**)&p_h, g_h);
    cudaGetSymbolAddress((void**)&p_q, g_q);
    cudaGetSymbolAddress((void**)&p_k, g_k);
    cudaGetSymbolAddress((void**)&p_v, g_v);
    cudaGetSymbolAddress((void**)&p_o, g_o);
    cudaGetSymbolAddress((void**)&p_gate, g_gate);
    cudaGetSymbolAddress((void**)&p_up, g_up);
    cudaGetSymbolAddress((void**)&p_whi, g_wt_hi);
    cudaGetSymbolAddress((void**)&p_wlo, g_wt_lo);

    static bool attr_done = false;
    if (!attr_done) {
        cudaFuncSetAttribute(mm7_kernel<3>, cudaFuncAttributeMaxDynamicSharedMemorySize, SMEM7);
        cudaFuncSetAttribute(mm7_kernel<2>, cudaFuncAttributeMaxDynamicSharedMemorySize, SMEM7);
        attr_done = true;
    }

    // weight prep; gw/uw/lm consumed by 2-pass GEMMs -> skip lo writes
    for (int l = 0; l < LAYERS; l++) {
        size_t lo = (size_t)l * LSZ;
        wprep_kernel<true><<<dim3(8, 32), 256>>>(qw + (size_t)l * 1048576, p_whi + lo + OQW, p_wlo + lo + OQW, 1024, 1024);
        wprep_kernel<true><<<dim3(2, 32), 256>>>(kw + (size_t)l * 262144, p_whi + lo + OKW, p_wlo + lo + OKW, 1024, 256);
        wprep_kernel<true><<<dim3(2, 32), 256>>>(vw + (size_t)l * 262144, p_whi + lo + OVW, p_wlo + lo + OVW, 1024, 256);
        wprep_kernel<true><<<dim3(8, 32), 256>>>(ow + (size_t)l * 1048576, p_whi + lo + OOW, p_wlo + lo + OOW, 1024, 1024);
        wprep_kernel<false><<<dim3(32, 32), 256>>>(gw + (size_t)l * 4194304, p_whi + lo + OGW, p_wlo + lo + OGW, 1024, 4096);
        wprep_kernel<false><<<dim3(32, 32), 256>>>(uw + (size_t)l * 4194304, p_whi + lo + OUW, p_wlo + lo + OUW, 1024, 4096);
        wprep_kernel<true><<<dim3(8, 128), 256>>>(dw + (size_t)l * 4194304, p_whi + lo + ODW, p_wlo + lo + ODW, 4096, 1024);
    }
    wprep_kernel<false><<<dim3(250, 32), 256>>>(lm_w, p_whi + OLM, p_wlo + OLM, 1024, 32000);

    GemmSeg z = mkseg(nullptr, nullptr, nullptr, nullptr, 0, 0);

    rope_table_kernel<<<(S * 32 + 255) / 256, 256>>>();
    embed_kernel<<<(S * D / 4) / 256, 256>>>(embed, ids);

    for (int l = 0; l < LAYERS; l++) {
        size_t lo = (size_t)l * LSZ;
        rms_scale_kernel<<<S, 256>>>(p_h);
        asplit_kernel<2><<<dim3(16, 32), 256>>>(p_h, nullptr, ln1 + (size_t)l * D, 1024);
        {
            GemmSeg sq = mkseg(p_whi + lo + OQW, p_wlo + lo + OQW, qb + (size_t)l * HQ * HD, p_q, HQ * HD, 8);
            GemmSeg sk = mkseg(p_whi + lo + OKW, p_wlo + lo + OKW, kb + (size_t)l * KVH * HD, p_k, KVH * HD, 2);
            GemmSeg sv = mkseg(p_whi + lo + OVW, p_wlo + lo + OVW, vb + (size_t)l * KVH * HD, p_v, KVH * HD, 2);
            mm7_kernel<3><<<dim3(12, 16, 1), 256, SMEM7>>>(sq, sk, sv, D, 0);
        }
        rope_kernel<<<(S * HQ * 32) / 256, 256>>>(p_q, HQ);
        rope_kernel<<<(S * KVH * 32) / 256, 256>>>(p_k, KVH);
        attn_kernel<<<dim3(S / 128, HQ / 2), 256>>>();
        asplit_kernel<0><<<dim3(16, 32), 256>>>(p_o, nullptr, nullptr, 1024);
        {
            GemmSeg so = mkseg(p_whi + lo + OOW, p_wlo + lo + OOW, nullptr, p_h, D, 8);
            mm7_kernel<3><<<dim3(8, 16, 2), 256, SMEM7>>>(so, z, z, HQ * HD, 2);
        }
        rms_scale_kernel<<<S, 256>>>(p_h);
        asplit_kernel<2><<<dim3(16, 32), 256>>>(p_h, nullptr, ln2 + (size_t)l * D, 1024);
        {
            // gate+up: 2-pass tf32 (hi*hi + loA*hi) — error attenuated by residual
            GemmSeg sg = mkseg(p_whi + lo + OGW, p_wlo + lo + OGW, nullptr, p_gate, II, 32);
            GemmSeg su = mkseg(p_whi + lo + OUW, p_wlo + lo + OUW, nullptr, p_up, II, 32);
            mm7_kernel<2><<<dim3(64, 16, 1), 256, SMEM7>>>(sg, su, z, D, 0);
        }
        asplit_kernel<1><<<dim3(16, 128), 256>>>(p_gate, p_up, nullptr, 4096);
        {
            GemmSeg sd = mkseg(p_whi + lo + ODW, p_wlo + lo + ODW, nullptr, p_h, D, 8);
            mm7_kernel<3><<<dim3(8, 16, 2), 256, SMEM7>>>(sd, z, z, II, 2);
        }
    }

    rms_scale_kernel<<<S, 256>>>(p_h);
    asplit_kernel<2><<<dim3(16, 32), 256>>>(p_h, nullptr, norm_w, 1024);
    {
        // LM head: 2-pass tf32
        GemmSeg sl = mkseg(p_whi + OLM, p_wlo + OLM, nullptr, out, VV, 250);
        mm7_kernel<2><<<dim3(250, 16, 1), 256, SMEM7>>>(sl, z, z, D, 0);
    }
}

// round 15
// speedup vs baseline: 1.6811x; 1.0855x over previous
#include <cuda_runtime.h>
#include <math.h>
#include <stdint.h>

#define LAYERS 4
#define S 2048
#define D 1024
#define HQ 16
#define KVH 4
#define HD 64
#define II 4096
#define VV 32000
#define EPSV 1e-6f

__device__ float g_h[S * D];
__device__ float g_q[S * HQ * HD];
__device__ float g_k[S * KVH * HD];
__device__ float g_v[S * KVH * HD];
__device__ float g_o[S * HQ * HD];
__device__ float g_gate[S * II];
__device__ float g_up[S * II];
__device__ float g_cos[S * 32];
__device__ float g_sin[S * 32];
__device__ float g_rms[S];

// split-KV partial scratch
__device__ float g_po[2 * HQ * S * HD];
__device__ float g_pm[2 * HQ * S];
__device__ float g_pl[2 * HQ * S];

// weights in mma-frag layout, hi/lo tf32: [pan][kb][nb(16)][64]
#define OQW  0
#define OKW  1048576
#define OVW  1310720
#define OOW  1572864
#define OGW  2621440
#define OUW  6815744
#define ODW  11010048
#define LSZ  15204352
#define OLM  60817408
#define WTOT 93585408
__device__ uint32_t g_wt_hi[WTOT];
__device__ uint32_t g_wt_lo[WTOT];

// activations in mma-frag layout, hi/lo: [mt][kb][mb(8)][128]
#define AMAX (S * II)
__device__ uint32_t g_a_hi[AMAX];
__device__ uint32_t g_a_lo[AMAX];

__device__ __forceinline__ uint32_t f2tf32(float f) {
    uint32_t u; asm("cvt.rna.tf32.f32 %0, %1;" : "=r"(u) : "f"(f)); return u;
}
__device__ __forceinline__ uint32_t smem_u32(const void* p) {
    uint32_t a;
    asm("{ .reg .u64 t; cvta.to.shared.u64 t, %1; cvt.u32.u64 %0, t; }" : "=r"(a) : "l"(p));
    return a;
}
__device__ __forceinline__ void cp_async16(uint32_t dst, const void* src) {
    asm volatile("cp.async.cg.shared.global [%0], [%1], 16;" :: "r"(dst), "l"(src) : "memory");
}
__device__ __forceinline__ void cp_commit() {
    asm volatile("cp.async.commit_group;" ::: "memory");
}
template <int N>
__device__ __forceinline__ void cp_wait() {
    asm volatile("cp.async.wait_group %0;" :: "n"(N) : "memory");
}

#define MMA_TF32(c, a, b)                                                     \
    asm volatile(                                                             \
        "mma.sync.aligned.m16n8k8.row.col.f32.tf32.tf32.f32 "                 \
        "{%0,%1,%2,%3},{%4,%5,%6,%7},{%8,%9},{%0,%1,%2,%3};"                  \
        : "+f"(c[0]), "+f"(c[1]), "+f"(c[2]), "+f"(c[3])                      \
        : "r"(a.x), "r"(a.y), "r"(a.z), "r"(a.w), "r"(b.x), "r"(b.y))

// ---------------- misc kernels ------------------------------------------------
__global__ void rope_table_kernel() {
    int idx = blockIdx.x * blockDim.x + threadIdx.x;
    if (idx >= S * 32) return;
    int s = idx >> 5, i = idx & 31;
    double invf = exp(-((double)(2 * i) / (double)HD) * log(10000.0));
    float af = (float)s * (float)invf;
    g_cos[idx] = (float)cos((double)af);
    g_sin[idx] = (float)sin((double)af);
}

__global__ void embed_kernel(const float* __restrict__ embed, const int* __restrict__ ids) {
    int idx = blockIdx.x * blockDim.x + threadIdx.x;
    int s = idx / (D / 4), c = idx % (D / 4);
    ((float4*)(g_h + (size_t)s * D))[c] = ((const float4*)(embed + (size_t)ids[s] * D))[c];
}

__global__ void rms_scale_kernel(const float* __restrict__ X) {
    int row = blockIdx.x;
    const float* x = X + (size_t)row * D;
    float ss = 0.f;
    for (int i = threadIdx.x; i < D; i += blockDim.x) { float v = x[i]; ss = fmaf(v, v, ss); }
    __shared__ float sred[32];
    #pragma unroll
    for (int off = 16; off; off >>= 1) ss += __shfl_xor_sync(0xffffffffu, ss, off);
    int wid = threadIdx.x >> 5, lid = threadIdx.x & 31;
    if (lid == 0) sred[wid] = ss;
    __syncthreads();
    if (wid == 0) {
        ss = (lid < (int)(blockDim.x >> 5)) ? sred[lid] : 0.f;
        #pragma unroll
        for (int off = 16; off; off >>= 1) ss += __shfl_xor_sync(0xffffffffu, ss, off);
        if (lid == 0) g_rms[row] = rsqrtf(ss / (float)D + EPSV);
    }
}

__global__ void rope_kernel(float* __restrict__ X, int nheads) {
    int idx = blockIdx.x * blockDim.x + threadIdx.x;
    if (idx >= S * nheads * 32) return;
    int i = idx & 31, h = (idx >> 5) % nheads, s = idx / (32 * nheads);
    float c = g_cos[s * 32 + i], sn = g_sin[s * 32 + i];
    float* p = X + (size_t)s * nheads * HD + h * HD;
    float x1 = p[i], x2 = p[i + 32];
    p[i] = x1 * c - x2 * sn;
    p[i + 32] = x2 * c + x1 * sn;
}

// ---------------- weight prep: W[K][N] -> frag layout hi(/lo) -----------------
template <bool WLO>
__global__ void wprep_kernel(const float* __restrict__ W, uint32_t* __restrict__ hi,
                             uint32_t* __restrict__ lo, int K, int N) {
    __shared__ uint32_t sh[1024];
    __shared__ uint32_t sl[1024];
    int pan = blockIdx.x;
    int r = threadIdx.x & 7;
    int n0 = (threadIdx.x >> 3) * 4;
    #pragma unroll
    for (int i = 0; i < 4; i++) {
        int kb = blockIdx.y * 4 + i;
        float4 v = *(const float4*)(W + (size_t)(kb * 8 + r) * N + pan * 128 + n0);
        float f[4] = {v.x, v.y, v.z, v.w};
        #pragma unroll
        for (int j = 0; j < 4; j++) {
            int n = n0 + j;
            int pos = ((n >> 3) << 6) + ((n & 7) << 3) + ((r & 3) << 1) + (r >> 2);
            uint32_t h = f2tf32(f[j]);
            sh[pos] = h;
            if (WLO) sl[pos] = f2tf32(f[j] - __uint_as_float(h));
        }
        __syncthreads();
        size_t base = (size_t)((uint32_t)(pan * (K >> 3) + kb)) * 1024;
        int e = threadIdx.x * 4;
        *(uint4*)(hi + base + e) = *(const uint4*)(sh + e);
        if (WLO) *(uint4*)(lo + base + e) = *(const uint4*)(sl + e);
        __syncthreads();
    }
}

// ---------------- activation prep -----------------------------------------
// MODE 0: plain ; MODE 1: silu(A)*U ; MODE 2: rmsnorm-apply w[col]*A*g_rms[row]
template <int MODE>
__global__ void asplit_kernel(const float* __restrict__ A, const float* __restrict__ U,
                              const float* __restrict__ w, int K) {
    __shared__ uint32_t sh[1024];
    __shared__ uint32_t sl[1024];
    int mt = blockIdx.x;
    int m = threadIdx.x >> 1;
    int k0 = (threadIdx.x & 1) * 4;
    float rscale = (MODE == 2) ? g_rms[mt * 128 + m] : 0.f;
    #pragma unroll
    for (int i = 0; i < 4; i++) {
        int kb = blockIdx.y * 4 + i;
        size_t gofs = (size_t)(mt * 128 + m) * K + kb * 8 + k0;
        float4 v = *(const float4*)(A + gofs);
        float f[4] = {v.x, v.y, v.z, v.w};
        if (MODE == 1) {
            float4 u = *(const float4*)(U + gofs);
            float uu[4] = {u.x, u.y, u.z, u.w};
            #pragma unroll
            for (int j = 0; j < 4; j++)
                f[j] = f[j] / (1.f + __expf(-f[j])) * uu[j];
        } else if (MODE == 2) {
            float4 ww = *(const float4*)(w + kb * 8 + k0);
            float wv[4] = {ww.x, ww.y, ww.z, ww.w};
            #pragma unroll
            for (int j = 0; j < 4; j++)
                f[j] = wv[j] * (f[j] * rscale);
        }
        #pragma unroll
        for (int j = 0; j < 4; j++) {
            int k = k0 + j;
            int lane = ((m & 7) << 2) + (k & 3);
            int reg = ((m >> 3) & 1) + 2 * ((k >> 2) & 1);
            int pos = ((m >> 4) << 7) + lane * 4 + reg;
            uint32_t h = f2tf32(f[j]);
            sh[pos] = h;
            sl[pos] = f2tf32(f[j] - __uint_as_float(h));
        }
        __syncthreads();
        size_t base = (size_t)((uint32_t)(mt * (K >> 3) + kb)) * 1024;
        int e = threadIdx.x * 4;
        *(uint4*)(g_a_hi + base + e) = *(const uint4*)(sh + e);
        *(uint4*)(g_a_lo + base + e) = *(const uint4*)(sl + e);
        __syncthreads();
    }
}

// ---------------- 3x/2x TF32 GEMM, 3-stage cp.async pipeline, split-K ---------
struct GemmSeg {
    const uint32_t* Bhi; const uint32_t* Blo;
    const float* bias; float* C; int N; int nx;
};
#define SMEM7 98304

template <int PASSES>
__global__ void __launch_bounds__(256, 2)
mm7_kernel(GemmSeg s0, GemmSeg s1, GemmSeg s2, int K, int mode) {
    extern __shared__ __align__(128) uint32_t sm[];

    int bx = blockIdx.x;
    const uint32_t *Bhi, *Blo;
    const float* bias; float* Cp; int N;
    if (bx < s0.nx) { Bhi = s0.Bhi; Blo = s0.Blo; bias = s0.bias; Cp = s0.C; N = s0.N; }
    else if (bx < s0.nx + s1.nx) { bx -= s0.nx; Bhi = s1.Bhi; Blo = s1.Blo; bias = s1.bias; Cp = s1.C; N = s1.N; }
    else { bx -= s0.nx + s1.nx; Bhi = s2.Bhi; Blo = s2.Blo; bias = s2.bias; Cp = s2.C; N = s2.N; }
    const int pan = bx;
    const int mt = blockIdx.y;

    const int tid = threadIdx.x;
    const int lane = tid & 31;
    const int warp = tid >> 5;
    const int wm = warp & 1;
    const int wn = warp >> 1;

    const uint32_t smb = smem_u32(sm);
    const int KB8 = K >> 3;
    const int KB8z = KB8 / (int)gridDim.z;
    const int kb0 = blockIdx.z * KB8z;

    float acc[4][4][4];
    #pragma unroll
    for (int i = 0; i < 4; i++)
        #pragma unroll
        for (int j = 0; j < 4; j++)
            #pragma unroll
            for (int r = 0; r < 4; r++) acc[i][j][r] = 0.f;

    auto copy_tile = [&](int t, int buf) {
        const uint32_t* srcA_hi = g_a_hi + ((size_t)(mt * KB8 + kb0 + 2 * t)) * 1024;
        const uint32_t* srcA_lo = g_a_lo + ((size_t)(mt * KB8 + kb0 + 2 * t)) * 1024;
        const uint32_t* srcB_hi = Bhi + ((size_t)(pan * KB8 + kb0 + 2 * t)) * 1024;
        const uint32_t* srcB_lo = Blo + ((size_t)(pan * KB8 + kb0 + 2 * t)) * 1024;
        uint32_t dst = smb + buf * 32768;
        #pragma unroll
        for (int j = 0; j < 2; j++) {
            int e = (tid + j * 256) * 4;
            cp_async16(dst + e * 4,         srcA_hi + e);
            cp_async16(dst + 8192 + e * 4,  srcA_lo + e);
            cp_async16(dst + 16384 + e * 4, srcB_hi + e);
            if (PASSES == 3)
                cp_async16(dst + 24576 + e * 4, srcB_lo + e);
        }
        cp_commit();
    };

    const int ntiles = KB8z >> 1;
    copy_tile(0, 0);
    if (ntiles > 1) copy_tile(1, 1);

    int buf_idx = 0;
    for (int t = 0; t < ntiles; t++) {
        if (t + 1 < ntiles) cp_wait<1>(); else cp_wait<0>();
        __syncthreads();
        if (t + 2 < ntiles) {
            int b2 = buf_idx + 2; if (b2 >= 3) b2 -= 3;
            copy_tile(t + 2, b2);
        }

        const uint32_t* buf = sm + buf_idx * 8192;
        const uint32_t* Ahi_s = buf;
        const uint32_t* Alo_s = buf + 2048;
        const uint32_t* Bhi_s = buf + 4096;
        const uint32_t* Blo_s = buf + 6144;

        #pragma unroll
        for (int ks = 0; ks < 2; ks++) {
            uint4 af[4];
            uint2 bf[4];
            #pragma unroll
            for (int mf = 0; mf < 4; mf++)
                af[mf] = *(const uint4*)&Ahi_s[((ks * 8) + wm * 4 + mf) * 128 + lane * 4];
            #pragma unroll
            for (int nf = 0; nf < 4; nf++)
                bf[nf] = *(const uint2*)&Bhi_s[((ks * 16) + wn * 4 + nf) * 64 + lane * 2];
            #pragma unroll
            for (int mf = 0; mf < 4; mf++)
                #pragma unroll
                for (int nf = 0; nf < 4; nf++)
                    MMA_TF32(acc[mf][nf], af[mf], bf[nf]);
            if (PASSES == 3) {
                uint2 bl[4];
                #pragma unroll
                for (int nf = 0; nf < 4; nf++)
                    bl[nf] = *(const uint2*)&Blo_s[((ks * 16) + wn * 4 + nf) * 64 + lane * 2];
                #pragma unroll
                for (int mf = 0; mf < 4; mf++)
                    #pragma unroll
                    for (int nf = 0; nf < 4; nf++)
                        MMA_TF32(acc[mf][nf], af[mf], bl[nf]);
            }
            #pragma unroll
            for (int mf = 0; mf < 4; mf++)
                af[mf] = *(const uint4*)&Alo_s[((ks * 8) + wm * 4 + mf) * 128 + lane * 4];
            #pragma unroll
            for (int mf = 0; mf < 4; mf++)
                #pragma unroll
                for (int nf = 0; nf < 4; nf++)
                    MMA_TF32(acc[mf][nf], af[mf], bf[nf]);
        }
        buf_idx++; if (buf_idx == 3) buf_idx = 0;
    }

    const int g = lane >> 2, tg = lane & 3;
    const int col0 = pan * 128;
    #pragma unroll
    for (int nf = 0; nf < 4; nf++) {
        int cc = col0 + wn * 32 + nf * 8 + tg * 2;
        float b0 = 0.f, b1 = 0.f;
        if (mode == 0 && bias) { b0 = bias[cc]; b1 = bias[cc + 1]; }
        #pragma unroll
        for (int mf = 0; mf < 4; mf++) {
            int rr = mt * 128 + wm * 64 + mf * 16 + g;
            float* c0 = &Cp[(size_t)rr * N + cc];
            float* c1 = &Cp[(size_t)(rr + 8) * N + cc];
            if (mode == 0) {
                *(float2*)c0 = make_float2(acc[mf][nf][0] + b0, acc[mf][nf][1] + b1);
                *(float2*)c1 = make_float2(acc[mf][nf][2] + b0, acc[mf][nf][3] + b1);
            } else if (mode == 1) {
                float2 o0 = *(float2*)c0, o1 = *(float2*)c1;
                o0.x += acc[mf][nf][0]; o0.y += acc[mf][nf][1];
                o1.x += acc[mf][nf][2]; o1.y += acc[mf][nf][3];
                *(float2*)c0 = o0; *(float2*)c1 = o1;
            } else {
                atomicAdd(c0,     acc[mf][nf][0]);
                atomicAdd(c0 + 1, acc[mf][nf][1]);
                atomicAdd(c1,     acc[mf][nf][2]);
                atomicAdd(c1 + 1, acc[mf][nf][3]);
            }
        }
    }
}

// ---------------- attention, split-KV=2: partial (o, m, l) --------------------
#define AKV 64
__global__ void __launch_bounds__(256)
attn_part_kernel() {
    __shared__ float Ks[AKV][HD];
    __shared__ float Vs[AKV][HD];
    const int bx = blockIdx.x;
    const int hq = blockIdx.y * 2 + (threadIdx.x >> 7);
    const int kvh = hq >> 2;
    const int tid128 = threadIdx.x & 127;
    const int row = bx * 128 + tid128;
    const int z = blockIdx.z;

    const int nt = bx + 1;                 // 128-key tiles this q-block needs
    const int half0 = (nt + 1) >> 1;
    const int t0 = (z == 0) ? 0 : half0;
    const int t1 = (z == 0) ? half0 : nt;

    float o[HD];
    #pragma unroll
    for (int d = 0; d < HD; d++) o[d] = 0.f;
    float m = -INFINITY, l = 0.f;

    if (t1 > t0) {
        float qr[HD];
        #pragma unroll
        for (int d = 0; d < HD; d += 4) {
            float4 t = *(const float4*)&g_q[(size_t)row * (HQ * HD) + hq * HD + d];
            qr[d] = t.x * 0.125f; qr[d + 1] = t.y * 0.125f;
            qr[d + 2] = t.z * 0.125f; qr[d + 3] = t.w * 0.125f;
        }
        for (int j0 = t0 * 128; j0 < t1 * 128; j0 += AKV) {
            __syncthreads();
            for (int t = threadIdx.x; t < AKV * (HD / 4); t += 256) {
                int r = t / (HD / 4), c = (t % (HD / 4)) * 4;
                size_t g = (size_t)(j0 + r) * (KVH * HD) + kvh * HD + c;
                *(float4*)&Ks[r][c] = *(const float4*)&g_k[g];
                *(float4*)&Vs[r][c] = *(const float4*)&g_v[g];
            }
            __syncthreads();
            int jmax = row + 1 - j0;
            if (jmax > AKV) jmax = AKV;
            for (int j = 0; j < jmax; j++) {
                float s0 = 0.f, s1 = 0.f, s2 = 0.f, s3 = 0.f;
                #pragma unroll
                for (int d = 0; d < HD; d += 4) {
                    float4 k4 = *(const float4*)&Ks[j][d];
                    s0 = fmaf(qr[d], k4.x, s0);
                    s1 = fmaf(qr[d + 1], k4.y, s1);
                    s2 = fmaf(qr[d + 2], k4.z, s2);
                    s3 = fmaf(qr[d + 3], k4.w, s3);
                }
                float s = (s0 + s1) + (s2 + s3);
                if (s > m) {
                    float corr = __expf(m - s);
                    l *= corr;
                    #pragma unroll
                    for (int d = 0; d < HD; d++) o[d] *= corr;
                    m = s;
                }
                float p = __expf(s - m);
                l += p;
                #pragma unroll
                for (int d = 0; d < HD; d += 4) {
                    float4 vv = *(const float4*)&Vs[j][d];
                    o[d] = fmaf(p, vv.x, o[d]);
                    o[d + 1] = fmaf(p, vv.y, o[d + 1]);
                    o[d + 2] = fmaf(p, vv.z, o[d + 2]);
                    o[d + 3] = fmaf(p, vv.w, o[d + 3]);
                }
            }
        }
    }

    size_t pb = ((size_t)(z * HQ + hq) * S + row);
    g_pm[pb] = m;
    g_pl[pb] = l;
    #pragma unroll
    for (int d = 0; d < HD; d += 4)
        *(float4*)&g_po[pb * HD + d] = make_float4(o[d], o[d + 1], o[d + 2], o[d + 3]);
}

// merge 2 partials -> g_o[row][head][d]
__global__ void attn_merge_kernel() {
    int idx = blockIdx.x * blockDim.x + threadIdx.x;   // over HQ*S*HD/4
    int d4 = (idx % (HD / 4)) * 4;
    int rh = idx / (HD / 4);                            // hq*S + row
    int row = rh % S, hq = rh / S;
    size_t p0 = (size_t)rh;
    size_t p1 = (size_t)(HQ * S) + rh;
    float m0 = g_pm[p0], m1 = g_pm[p1];
    float l0 = g_pl[p0], l1 = g_pl[p1];
    float M = fmaxf(m0, m1);
    float s0 = __expf(m0 - M), s1 = __expf(m1 - M);
    float inv = 1.f / (l0 * s0 + l1 * s1);
    float4 a = *(const float4*)&g_po[p0 * HD + d4];
    float4 b = *(const float4*)&g_po[p1 * HD + d4];
    float4 r = make_float4((a.x * s0 + b.x * s1) * inv, (a.y * s0 + b.y * s1) * inv,
                           (a.z * s0 + b.z * s1) * inv, (a.w * s0 + b.w * s1) * inv);
    *(float4*)&g_o[(size_t)row * (HQ * HD) + hq * HD + d4] = r;
}

// ---------------- host side ---------------------------------------------------
static GemmSeg mkseg(const uint32_t* bh, const uint32_t* bl, const float* bias,
                     float* C, int N, int nx) {
    GemmSeg s; s.Bhi = bh; s.Blo = bl; s.bias = bias; s.C = C; s.N = N; s.nx = nx; return s;
}

extern "C" void kernel_launch(void* const* d_in, const int* in_sizes, int n_in,
                              void* d_out, int out_size) {
    const float* embed  = (const float*)d_in[0];
    const float* ln1    = (const float*)d_in[1];
    const float* qw     = (const float*)d_in[2];
    const float* qb     = (const float*)d_in[3];
    const float* kw     = (const float*)d_in[4];
    const float* kb     = (const float*)d_in[5];
    const float* vw     = (const float*)d_in[6];
    const float* vb     = (const float*)d_in[7];
    const float* ow     = (const float*)d_in[8];
    const float* ln2    = (const float*)d_in[9];
    const float* gw     = (const float*)d_in[10];
    const float* uw     = (const float*)d_in[11];
    const float* dw     = (const float*)d_in[12];
    const float* norm_w = (const float*)d_in[13];
    const float* lm_w   = (const float*)d_in[14];
    const int*   ids    = (const int*)d_in[15];
    float* out = (float*)d_out;

    float *p_h, *p_q, *p_k, *p_v, *p_o, *p_gate, *p_up;
    uint32_t *p_whi, *p_wlo;
    cudaGetSymbolAddress((void**)&p_h, g_h);
    cudaGetSymbolAddress((void**)&p_q, g_q);
    cudaGetSymbolAddress((void**)&p_k, g_k);
    cudaGetSymbolAddress((void**)&p_v, g_v);
    cudaGetSymbolAddress((void**)&p_o, g_o);
    cudaGetSymbolAddress((void**)&p_gate, g_gate);
    cudaGetSymbolAddress((void**)&p_up, g_up);
    cudaGetSymbolAddress((void**)&p_whi, g_wt_hi);
    cudaGetSymbolAddress((void**)&p_wlo, g_wt_lo);

    static bool attr_done = false;
    if (!attr_done) {
        cudaFuncSetAttribute(mm7_kernel<3>, cudaFuncAttributeMaxDynamicSharedMemorySize, SMEM7);
        cudaFuncSetAttribute(mm7_kernel<2>, cudaFuncAttributeMaxDynamicSharedMemorySize, SMEM7);
        attr_done = true;
    }

    for (int l = 0; l < LAYERS; l++) {
        size_t lo = (size_t)l * LSZ;
        wprep_kernel<true><<<dim3(8, 32), 256>>>(qw + (size_t)l * 1048576, p_whi + lo + OQW, p_wlo + lo + OQW, 1024, 1024);
        wprep_kernel<true><<<dim3(2, 32), 256>>>(kw + (size_t)l * 262144, p_whi + lo + OKW, p_wlo + lo + OKW, 1024, 256);
        wprep_kernel<true><<<dim3(2, 32), 256>>>(vw + (size_t)l * 262144, p_whi + lo + OVW, p_wlo + lo + OVW, 1024, 256);
        wprep_kernel<true><<<dim3(8, 32), 256>>>(ow + (size_t)l * 1048576, p_whi + lo + OOW, p_wlo + lo + OOW, 1024, 1024);
        wprep_kernel<false><<<dim3(32, 32), 256>>>(gw + (size_t)l * 4194304, p_whi + lo + OGW, p_wlo + lo + OGW, 1024, 4096);
        wprep_kernel<false><<<dim3(32, 32), 256>>>(uw + (size_t)l * 4194304, p_whi + lo + OUW, p_wlo + lo + OUW, 1024, 4096);
        wprep_kernel<true><<<dim3(8, 128), 256>>>(dw + (size_t)l * 4194304, p_whi + lo + ODW, p_wlo + lo + ODW, 4096, 1024);
    }
    wprep_kernel<false><<<dim3(250, 32), 256>>>(lm_w, p_whi + OLM, p_wlo + OLM, 1024, 32000);

    GemmSeg z = mkseg(nullptr, nullptr, nullptr, nullptr, 0, 0);

    rope_table_kernel<<<(S * 32 + 255) / 256, 256>>>();
    embed_kernel<<<(S * D / 4) / 256, 256>>>(embed, ids);

    for (int l = 0; l < LAYERS; l++) {
        size_t lo = (size_t)l * LSZ;
        rms_scale_kernel<<<S, 256>>>(p_h);
        asplit_kernel<2><<<dim3(16, 32), 256>>>(p_h, nullptr, ln1 + (size_t)l * D, 1024);
        {
            GemmSeg sq = mkseg(p_whi + lo + OQW, p_wlo + lo + OQW, qb + (size_t)l * HQ * HD, p_q, HQ * HD, 8);
            GemmSeg sk = mkseg(p_whi + lo + OKW, p_wlo + lo + OKW, kb + (size_t)l * KVH * HD, p_k, KVH * HD, 2);
            GemmSeg sv = mkseg(p_whi + lo + OVW, p_wlo + lo + OVW, vb + (size_t)l * KVH * HD, p_v, KVH * HD, 2);
            mm7_kernel<3><<<dim3(12, 16, 1), 256, SMEM7>>>(sq, sk, sv, D, 0);
        }
        rope_kernel<<<(S * HQ * 32) / 256, 256>>>(p_q, HQ);
        rope_kernel<<<(S * KVH * 32) / 256, 256>>>(p_k, KVH);
        attn_part_kernel<<<dim3(S / 128, HQ / 2, 2), 256>>>();
        attn_merge_kernel<<<(HQ * S * HD / 4) / 256, 256>>>();
        asplit_kernel<0><<<dim3(16, 32), 256>>>(p_o, nullptr, nullptr, 1024);
        {
            GemmSeg so = mkseg(p_whi + lo + OOW, p_wlo + lo + OOW, nullptr, p_h, D, 8);
            mm7_kernel<3><<<dim3(8, 16, 2), 256, SMEM7>>>(so, z, z, HQ * HD, 2);
        }
        rms_scale_kernel<<<S, 256>>>(p_h);
        asplit_kernel<2><<<dim3(16, 32), 256>>>(p_h, nullptr, ln2 + (size_t)l * D, 1024);
        {
            GemmSeg sg = mkseg(p_whi + lo + OGW, p_wlo + lo + OGW, nullptr, p_gate, II, 32);
            GemmSeg su = mkseg(p_whi + lo + OUW, p_wlo + lo + OUW, nullptr, p_up, II, 32);
            mm7_kernel<2><<<dim3(64, 16, 1), 256, SMEM7>>>(sg, su, z, D, 0);
        }
        asplit_kernel<1><<<dim3(16, 128), 256>>>(p_gate, p_up, nullptr, 4096);
        {
            GemmSeg sd = mkseg(p_whi + lo + ODW, p_wlo + lo + ODW, nullptr, p_h, D, 8);
            mm7_kernel<3><<<dim3(8, 16, 2), 256, SMEM7>>>(sd, z, z, II, 2);
        }
    }

    rms_scale_kernel<<<S, 256>>>(p_h);
    asplit_kernel<2><<<dim3(16, 32), 256>>>(p_h, nullptr, norm_w, 1024);
    {
        GemmSeg sl = mkseg(p_whi + OLM, p_wlo + OLM, nullptr, out, VV, 250);
        mm7_kernel<2><<<dim3(250, 16, 1), 256, SMEM7>>>(sl, z, z, D, 0);
    }
}

// round 16
// speedup vs baseline: 1.7382x; 1.0340x over previous
#include <cuda_runtime.h>
#include <math.h>
#include <stdint.h>

#define LAYERS 4
#define S 2048
#define D 1024
#define HQ 16
#define KVH 4
#define HD 64
#define II 4096
#define VV 32000
#define EPSV 1e-6f

__device__ float g_h[S * D];
__device__ float g_q[S * HQ * HD];
__device__ float g_k[S * KVH * HD];
__device__ float g_v[S * KVH * HD];
__device__ float g_o[S * HQ * HD];
__device__ float g_gate[S * II];
__device__ float g_up[S * II];
__device__ float g_cos[S * 32];
__device__ float g_sin[S * 32];
__device__ float g_rms[S];

// split-KV partial scratch (3 splits)
__device__ float g_po[3 * HQ * S * HD];
__device__ float g_pm[3 * HQ * S];
__device__ float g_pl[3 * HQ * S];

// weights in mma-frag layout, hi/lo tf32: [pan][kb][nb(16)][64]
#define OQW  0
#define OKW  1048576
#define OVW  1310720
#define OOW  1572864
#define OGW  2621440
#define OUW  6815744
#define ODW  11010048
#define LSZ  15204352
#define OLM  60817408
#define WTOT 93585408
__device__ uint32_t g_wt_hi[WTOT];
__device__ uint32_t g_wt_lo[WTOT];

// activations in mma-frag layout, hi/lo: [mt][kb][mb(8)][128]
#define AMAX (S * II)
__device__ uint32_t g_a_hi[AMAX];
__device__ uint32_t g_a_lo[AMAX];

__device__ __forceinline__ uint32_t f2tf32(float f) {
    uint32_t u; asm("cvt.rna.tf32.f32 %0, %1;" : "=r"(u) : "f"(f)); return u;
}
__device__ __forceinline__ uint32_t smem_u32(const void* p) {
    uint32_t a;
    asm("{ .reg .u64 t; cvta.to.shared.u64 t, %1; cvt.u32.u64 %0, t; }" : "=r"(a) : "l"(p));
    return a;
}
__device__ __forceinline__ void cp_async16(uint32_t dst, const void* src) {
    asm volatile("cp.async.cg.shared.global [%0], [%1], 16;" :: "r"(dst), "l"(src) : "memory");
}
__device__ __forceinline__ void cp_commit() {
    asm volatile("cp.async.commit_group;" ::: "memory");
}
template <int N>
__device__ __forceinline__ void cp_wait() {
    asm volatile("cp.async.wait_group %0;" :: "n"(N) : "memory");
}

#define MMA_TF32(c, a, b)                                                     \
    asm volatile(                                                             \
        "mma.sync.aligned.m16n8k8.row.col.f32.tf32.tf32.f32 "                 \
        "{%0,%1,%2,%3},{%4,%5,%6,%7},{%8,%9},{%0,%1,%2,%3};"                  \
        : "+f"(c[0]), "+f"(c[1]), "+f"(c[2]), "+f"(c[3])                      \
        : "r"(a.x), "r"(a.y), "r"(a.z), "r"(a.w), "r"(b.x), "r"(b.y))

// ---------------- misc kernels ------------------------------------------------
__global__ void rope_table_kernel() {
    int idx = blockIdx.x * blockDim.x + threadIdx.x;
    if (idx >= S * 32) return;
    int s = idx >> 5, i = idx & 31;
    double invf = exp(-((double)(2 * i) / (double)HD) * log(10000.0));
    float af = (float)s * (float)invf;
    g_cos[idx] = (float)cos((double)af);
    g_sin[idx] = (float)sin((double)af);
}

__global__ void embed_kernel(const float* __restrict__ embed, const int* __restrict__ ids) {
    int idx = blockIdx.x * blockDim.x + threadIdx.x;
    int s = idx / (D / 4), c = idx % (D / 4);
    ((float4*)(g_h + (size_t)s * D))[c] = ((const float4*)(embed + (size_t)ids[s] * D))[c];
}

__global__ void rms_scale_kernel(const float* __restrict__ X) {
    int row = blockIdx.x;
    const float* x = X + (size_t)row * D;
    float ss = 0.f;
    for (int i = threadIdx.x; i < D; i += blockDim.x) { float v = x[i]; ss = fmaf(v, v, ss); }
    __shared__ float sred[32];
    #pragma unroll
    for (int off = 16; off; off >>= 1) ss += __shfl_xor_sync(0xffffffffu, ss, off);
    int wid = threadIdx.x >> 5, lid = threadIdx.x & 31;
    if (lid == 0) sred[wid] = ss;
    __syncthreads();
    if (wid == 0) {
        ss = (lid < (int)(blockDim.x >> 5)) ? sred[lid] : 0.f;
        #pragma unroll
        for (int off = 16; off; off >>= 1) ss += __shfl_xor_sync(0xffffffffu, ss, off);
        if (lid == 0) g_rms[row] = rsqrtf(ss / (float)D + EPSV);
    }
}

__global__ void rope_kernel(float* __restrict__ X, int nheads) {
    int idx = blockIdx.x * blockDim.x + threadIdx.x;
    if (idx >= S * nheads * 32) return;
    int i = idx & 31, h = (idx >> 5) % nheads, s = idx / (32 * nheads);
    float c = g_cos[s * 32 + i], sn = g_sin[s * 32 + i];
    float* p = X + (size_t)s * nheads * HD + h * HD;
    float x1 = p[i], x2 = p[i + 32];
    p[i] = x1 * c - x2 * sn;
    p[i + 32] = x2 * c + x1 * sn;
}

// ---------------- weight prep: W[K][N] -> frag layout hi(/lo) -----------------
template <bool WLO>
__global__ void wprep_kernel(const float* __restrict__ W, uint32_t* __restrict__ hi,
                             uint32_t* __restrict__ lo, int K, int N) {
    __shared__ uint32_t sh[1024];
    __shared__ uint32_t sl[1024];
    int pan = blockIdx.x;
    int r = threadIdx.x & 7;
    int n0 = (threadIdx.x >> 3) * 4;
    #pragma unroll
    for (int i = 0; i < 4; i++) {
        int kb = blockIdx.y * 4 + i;
        float4 v = *(const float4*)(W + (size_t)(kb * 8 + r) * N + pan * 128 + n0);
        float f[4] = {v.x, v.y, v.z, v.w};
        #pragma unroll
        for (int j = 0; j < 4; j++) {
            int n = n0 + j;
            int pos = ((n >> 3) << 6) + ((n & 7) << 3) + ((r & 3) << 1) + (r >> 2);
            uint32_t h = f2tf32(f[j]);
            sh[pos] = h;
            if (WLO) sl[pos] = f2tf32(f[j] - __uint_as_float(h));
        }
        __syncthreads();
        size_t base = (size_t)((uint32_t)(pan * (K >> 3) + kb)) * 1024;
        int e = threadIdx.x * 4;
        *(uint4*)(hi + base + e) = *(const uint4*)(sh + e);
        if (WLO) *(uint4*)(lo + base + e) = *(const uint4*)(sl + e);
        __syncthreads();
    }
}

// ---------------- activation prep -----------------------------------------
// MODE 0: plain ; MODE 1: silu(A)*U ; MODE 2: rmsnorm-apply w[col]*A*g_rms[row]
template <int MODE>
__global__ void asplit_kernel(const float* __restrict__ A, const float* __restrict__ U,
                              const float* __restrict__ w, int K) {
    __shared__ uint32_t sh[1024];
    __shared__ uint32_t sl[1024];
    int mt = blockIdx.x;
    int m = threadIdx.x >> 1;
    int k0 = (threadIdx.x & 1) * 4;
    float rscale = (MODE == 2) ? g_rms[mt * 128 + m] : 0.f;
    #pragma unroll
    for (int i = 0; i < 4; i++) {
        int kb = blockIdx.y * 4 + i;
        size_t gofs = (size_t)(mt * 128 + m) * K + kb * 8 + k0;
        float4 v = *(const float4*)(A + gofs);
        float f[4] = {v.x, v.y, v.z, v.w};
        if (MODE == 1) {
            float4 u = *(const float4*)(U + gofs);
            float uu[4] = {u.x, u.y, u.z, u.w};
            #pragma unroll
            for (int j = 0; j < 4; j++)
                f[j] = f[j] / (1.f + __expf(-f[j])) * uu[j];
        } else if (MODE == 2) {
            float4 ww = *(const float4*)(w + kb * 8 + k0);
            float wv[4] = {ww.x, ww.y, ww.z, ww.w};
            #pragma unroll
            for (int j = 0; j < 4; j++)
                f[j] = wv[j] * (f[j] * rscale);
        }
        #pragma unroll
        for (int j = 0; j < 4; j++) {
            int k = k0 + j;
            int lane = ((m & 7) << 2) + (k & 3);
            int reg = ((m >> 3) & 1) + 2 * ((k >> 2) & 1);
            int pos = ((m >> 4) << 7) + lane * 4 + reg;
            uint32_t h = f2tf32(f[j]);
            sh[pos] = h;
            sl[pos] = f2tf32(f[j] - __uint_as_float(h));
        }
        __syncthreads();
        size_t base = (size_t)((uint32_t)(mt * (K >> 3) + kb)) * 1024;
        int e = threadIdx.x * 4;
        *(uint4*)(g_a_hi + base + e) = *(const uint4*)(sh + e);
        *(uint4*)(g_a_lo + base + e) = *(const uint4*)(sl + e);
        __syncthreads();
    }
}

// ---------------- 3x/2x TF32 GEMM, 3-stage cp.async pipeline, split-K ---------
struct GemmSeg {
    const uint32_t* Bhi; const uint32_t* Blo;
    const float* bias; float* C; int N; int nx;
};
#define SMEM7 98304

template <int PASSES>
__global__ void __launch_bounds__(256, 2)
mm7_kernel(GemmSeg s0, GemmSeg s1, GemmSeg s2, int K, int mode) {
    extern __shared__ __align__(128) uint32_t sm[];

    int bx = blockIdx.x;
    const uint32_t *Bhi, *Blo;
    const float* bias; float* Cp; int N;
    if (bx < s0.nx) { Bhi = s0.Bhi; Blo = s0.Blo; bias = s0.bias; Cp = s0.C; N = s0.N; }
    else if (bx < s0.nx + s1.nx) { bx -= s0.nx; Bhi = s1.Bhi; Blo = s1.Blo; bias = s1.bias; Cp = s1.C; N = s1.N; }
    else { bx -= s0.nx + s1.nx; Bhi = s2.Bhi; Blo = s2.Blo; bias = s2.bias; Cp = s2.C; N = s2.N; }
    const int pan = bx;
    const int mt = blockIdx.y;

    const int tid = threadIdx.x;
    const int lane = tid & 31;
    const int warp = tid >> 5;
    const int wm = warp & 1;
    const int wn = warp >> 1;

    const uint32_t smb = smem_u32(sm);
    const int KB8 = K >> 3;
    const int KB8z = KB8 / (int)gridDim.z;
    const int kb0 = blockIdx.z * KB8z;

    float acc[4][4][4];
    #pragma unroll
    for (int i = 0; i < 4; i++)
        #pragma unroll
        for (int j = 0; j < 4; j++)
            #pragma unroll
            for (int r = 0; r < 4; r++) acc[i][j][r] = 0.f;

    auto copy_tile = [&](int t, int buf) {
        const uint32_t* srcA_hi = g_a_hi + ((size_t)(mt * KB8 + kb0 + 2 * t)) * 1024;
        const uint32_t* srcA_lo = g_a_lo + ((size_t)(mt * KB8 + kb0 + 2 * t)) * 1024;
        const uint32_t* srcB_hi = Bhi + ((size_t)(pan * KB8 + kb0 + 2 * t)) * 1024;
        const uint32_t* srcB_lo = Blo + ((size_t)(pan * KB8 + kb0 + 2 * t)) * 1024;
        uint32_t dst = smb + buf * 32768;
        #pragma unroll
        for (int j = 0; j < 2; j++) {
            int e = (tid + j * 256) * 4;
            cp_async16(dst + e * 4,         srcA_hi + e);
            cp_async16(dst + 8192 + e * 4,  srcA_lo + e);
            cp_async16(dst + 16384 + e * 4, srcB_hi + e);
            if (PASSES == 3)
                cp_async16(dst + 24576 + e * 4, srcB_lo + e);
        }
        cp_commit();
    };

    const int ntiles = KB8z >> 1;
    copy_tile(0, 0);
    if (ntiles > 1) copy_tile(1, 1);

    int buf_idx = 0;
    for (int t = 0; t < ntiles; t++) {
        if (t + 1 < ntiles) cp_wait<1>(); else cp_wait<0>();
        __syncthreads();
        if (t + 2 < ntiles) {
            int b2 = buf_idx + 2; if (b2 >= 3) b2 -= 3;
            copy_tile(t + 2, b2);
        }

        const uint32_t* buf = sm + buf_idx * 8192;
        const uint32_t* Ahi_s = buf;
        const uint32_t* Alo_s = buf + 2048;
        const uint32_t* Bhi_s = buf + 4096;
        const uint32_t* Blo_s = buf + 6144;

        #pragma unroll
        for (int ks = 0; ks < 2; ks++) {
            uint4 af[4];
            uint2 bf[4];
            #pragma unroll
            for (int mf = 0; mf < 4; mf++)
                af[mf] = *(const uint4*)&Ahi_s[((ks * 8) + wm * 4 + mf) * 128 + lane * 4];
            #pragma unroll
            for (int nf = 0; nf < 4; nf++)
                bf[nf] = *(const uint2*)&Bhi_s[((ks * 16) + wn * 4 + nf) * 64 + lane * 2];
            #pragma unroll
            for (int mf = 0; mf < 4; mf++)
                #pragma unroll
                for (int nf = 0; nf < 4; nf++)
                    MMA_TF32(acc[mf][nf], af[mf], bf[nf]);
            if (PASSES == 3) {
                uint2 bl[4];
                #pragma unroll
                for (int nf = 0; nf < 4; nf++)
                    bl[nf] = *(const uint2*)&Blo_s[((ks * 16) + wn * 4 + nf) * 64 + lane * 2];
                #pragma unroll
                for (int mf = 0; mf < 4; mf++)
                    #pragma unroll
                    for (int nf = 0; nf < 4; nf++)
                        MMA_TF32(acc[mf][nf], af[mf], bl[nf]);
            }
            #pragma unroll
            for (int mf = 0; mf < 4; mf++)
                af[mf] = *(const uint4*)&Alo_s[((ks * 8) + wm * 4 + mf) * 128 + lane * 4];
            #pragma unroll
            for (int mf = 0; mf < 4; mf++)
                #pragma unroll
                for (int nf = 0; nf < 4; nf++)
                    MMA_TF32(acc[mf][nf], af[mf], bf[nf]);
        }
        buf_idx++; if (buf_idx == 3) buf_idx = 0;
    }

    const int g = lane >> 2, tg = lane & 3;
    const int col0 = pan * 128;
    #pragma unroll
    for (int nf = 0; nf < 4; nf++) {
        int cc = col0 + wn * 32 + nf * 8 + tg * 2;
        float b0 = 0.f, b1 = 0.f;
        if (mode == 0 && bias) { b0 = bias[cc]; b1 = bias[cc + 1]; }
        #pragma unroll
        for (int mf = 0; mf < 4; mf++) {
            int rr = mt * 128 + wm * 64 + mf * 16 + g;
            float* c0 = &Cp[(size_t)rr * N + cc];
            float* c1 = &Cp[(size_t)(rr + 8) * N + cc];
            if (mode == 0) {
                *(float2*)c0 = make_float2(acc[mf][nf][0] + b0, acc[mf][nf][1] + b1);
                *(float2*)c1 = make_float2(acc[mf][nf][2] + b0, acc[mf][nf][3] + b1);
            } else if (mode == 1) {
                float2 o0 = *(float2*)c0, o1 = *(float2*)c1;
                o0.x += acc[mf][nf][0]; o0.y += acc[mf][nf][1];
                o1.x += acc[mf][nf][2]; o1.y += acc[mf][nf][3];
                *(float2*)c0 = o0; *(float2*)c1 = o1;
            } else {
                atomicAdd(c0,     acc[mf][nf][0]);
                atomicAdd(c0 + 1, acc[mf][nf][1]);
                atomicAdd(c1,     acc[mf][nf][2]);
                atomicAdd(c1 + 1, acc[mf][nf][3]);
            }
        }
    }
}

// ---------------- attention, split-KV=3: partial (o, m, l) --------------------
#define AKV 64
__global__ void __launch_bounds__(256)
attn_part_kernel() {
    __shared__ float Ks[AKV][HD];
    __shared__ float Vs[AKV][HD];
    const int bx = blockIdx.x;
    const int hq = blockIdx.y * 2 + (threadIdx.x >> 7);
    const int kvh = hq >> 2;
    const int tid128 = threadIdx.x & 127;
    const int row = bx * 128 + tid128;
    const int z = blockIdx.z;

    const int nt = bx + 1;                 // 128-key tiles this q-block needs
    const int t0 = (nt * z) / 3;
    const int t1 = (nt * (z + 1)) / 3;

    float o[HD];
    #pragma unroll
    for (int d = 0; d < HD; d++) o[d] = 0.f;
    float m = -INFINITY, l = 0.f;

    if (t1 > t0) {
        float qr[HD];
        #pragma unroll
        for (int d = 0; d < HD; d += 4) {
            float4 t = *(const float4*)&g_q[(size_t)row * (HQ * HD) + hq * HD + d];
            qr[d] = t.x * 0.125f; qr[d + 1] = t.y * 0.125f;
            qr[d + 2] = t.z * 0.125f; qr[d + 3] = t.w * 0.125f;
        }
        for (int j0 = t0 * 128; j0 < t1 * 128; j0 += AKV) {
            __syncthreads();
            for (int t = threadIdx.x; t < AKV * (HD / 4); t += 256) {
                int r = t / (HD / 4), c = (t % (HD / 4)) * 4;
                size_t g = (size_t)(j0 + r) * (KVH * HD) + kvh * HD + c;
                *(float4*)&Ks[r][c] = *(const float4*)&g_k[g];
                *(float4*)&Vs[r][c] = *(const float4*)&g_v[g];
            }
            __syncthreads();
            int jmax = row + 1 - j0;
            if (jmax > AKV) jmax = AKV;
            for (int j = 0; j < jmax; j++) {
                float s0 = 0.f, s1 = 0.f, s2 = 0.f, s3 = 0.f;
                #pragma unroll
                for (int d = 0; d < HD; d += 4) {
                    float4 k4 = *(const float4*)&Ks[j][d];
                    s0 = fmaf(qr[d], k4.x, s0);
                    s1 = fmaf(qr[d + 1], k4.y, s1);
                    s2 = fmaf(qr[d + 2], k4.z, s2);
                    s3 = fmaf(qr[d + 3], k4.w, s3);
                }
                float s = (s0 + s1) + (s2 + s3);
                if (s > m) {
                    float corr = __expf(m - s);
                    l *= corr;
                    #pragma unroll
                    for (int d = 0; d < HD; d++) o[d] *= corr;
                    m = s;
                }
                float p = __expf(s - m);
                l += p;
                #pragma unroll
                for (int d = 0; d < HD; d += 4) {
                    float4 vv = *(const float4*)&Vs[j][d];
                    o[d] = fmaf(p, vv.x, o[d]);
                    o[d + 1] = fmaf(p, vv.y, o[d + 1]);
                    o[d + 2] = fmaf(p, vv.z, o[d + 2]);
                    o[d + 3] = fmaf(p, vv.w, o[d + 3]);
                }
            }
        }
    }

    size_t pb = ((size_t)(z * HQ + hq) * S + row);
    g_pm[pb] = m;
    g_pl[pb] = l;
    #pragma unroll
    for (int d = 0; d < HD; d += 4)
        *(float4*)&g_po[pb * HD + d] = make_float4(o[d], o[d + 1], o[d + 2], o[d + 3]);
}

// merge 3 partials -> g_o[row][head][d]
__global__ void attn_merge_kernel() {
    int idx = blockIdx.x * blockDim.x + threadIdx.x;   // over HQ*S*HD/4
    int d4 = (idx % (HD / 4)) * 4;
    int rh = idx / (HD / 4);                            // hq*S + row
    int row = rh % S, hq = rh / S;
    size_t p0 = (size_t)rh;
    size_t p1 = (size_t)(HQ * S) + rh;
    size_t p2 = (size_t)(2 * HQ * S) + rh;
    float m0 = g_pm[p0], m1 = g_pm[p1], m2 = g_pm[p2];
    float l0 = g_pl[p0], l1 = g_pl[p1], l2 = g_pl[p2];
    float M = fmaxf(fmaxf(m0, m1), m2);
    float s0 = __expf(m0 - M), s1 = __expf(m1 - M), s2 = __expf(m2 - M);
    float inv = 1.f / (l0 * s0 + l1 * s1 + l2 * s2);
    float4 a = *(const float4*)&g_po[p0 * HD + d4];
    float4 b = *(const float4*)&g_po[p1 * HD + d4];
    float4 c = *(const float4*)&g_po[p2 * HD + d4];
    float4 r = make_float4((a.x * s0 + b.x * s1 + c.x * s2) * inv,
                           (a.y * s0 + b.y * s1 + c.y * s2) * inv,
                           (a.z * s0 + b.z * s1 + c.z * s2) * inv,
                           (a.w * s0 + b.w * s1 + c.w * s2) * inv);
    *(float4*)&g_o[(size_t)row * (HQ * HD) + hq * HD + d4] = r;
}

// ---------------- host side ---------------------------------------------------
static GemmSeg mkseg(const uint32_t* bh, const uint32_t* bl, const float* bias,
                     float* C, int N, int nx) {
    GemmSeg s; s.Bhi = bh; s.Blo = bl; s.bias = bias; s.C = C; s.N = N; s.nx = nx; return s;
}

extern "C" void kernel_launch(void* const* d_in, const int* in_sizes, int n_in,
                              void* d_out, int out_size) {
    const float* embed  = (const float*)d_in[0];
    const float* ln1    = (const float*)d_in[1];
    const float* qw     = (const float*)d_in[2];
    const float* qb     = (const float*)d_in[3];
    const float* kw     = (const float*)d_in[4];
    const float* kb     = (const float*)d_in[5];
    const float* vw     = (const float*)d_in[6];
    const float* vb     = (const float*)d_in[7];
    const float* ow     = (const float*)d_in[8];
    const float* ln2    = (const float*)d_in[9];
    const float* gw     = (const float*)d_in[10];
    const float* uw     = (const float*)d_in[11];
    const float* dw     = (const float*)d_in[12];
    const float* norm_w = (const float*)d_in[13];
    const float* lm_w   = (const float*)d_in[14];
    const int*   ids    = (const int*)d_in[15];
    float* out = (float*)d_out;

    float *p_h, *p_q, *p_k, *p_v, *p_o, *p_gate, *p_up;
    uint32_t *p_whi, *p_wlo;
    cudaGetSymbolAddress((void**)&p_h, g_h);
    cudaGetSymbolAddress((void**)&p_q, g_q);
    cudaGetSymbolAddress((void**)&p_k, g_k);
    cudaGetSymbolAddress((void**)&p_v, g_v);
    cudaGetSymbolAddress((void**)&p_o, g_o);
    cudaGetSymbolAddress((void**)&p_gate, g_gate);
    cudaGetSymbolAddress((void**)&p_up, g_up);
    cudaGetSymbolAddress((void**)&p_whi, g_wt_hi);
    cudaGetSymbolAddress((void**)&p_wlo, g_wt_lo);

    static bool attr_done = false;
    if (!attr_done) {
        cudaFuncSetAttribute(mm7_kernel<3>, cudaFuncAttributeMaxDynamicSharedMemorySize, SMEM7);
        cudaFuncSetAttribute(mm7_kernel<2>, cudaFuncAttributeMaxDynamicSharedMemorySize, SMEM7);
        attr_done = true;
    }

    // weight prep; ow/gw/uw/lm consumed by 2-pass GEMMs -> skip lo writes
    for (int l = 0; l < LAYERS; l++) {
        size_t lo = (size_t)l * LSZ;
        wprep_kernel<true><<<dim3(8, 32), 256>>>(qw + (size_t)l * 1048576, p_whi + lo + OQW, p_wlo + lo + OQW, 1024, 1024);
        wprep_kernel<true><<<dim3(2, 32), 256>>>(kw + (size_t)l * 262144, p_whi + lo + OKW, p_wlo + lo + OKW, 1024, 256);
        wprep_kernel<true><<<dim3(2, 32), 256>>>(vw + (size_t)l * 262144, p_whi + lo + OVW, p_wlo + lo + OVW, 1024, 256);
        wprep_kernel<false><<<dim3(8, 32), 256>>>(ow + (size_t)l * 1048576, p_whi + lo + OOW, p_wlo + lo + OOW, 1024, 1024);
        wprep_kernel<false><<<dim3(32, 32), 256>>>(gw + (size_t)l * 4194304, p_whi + lo + OGW, p_wlo + lo + OGW, 1024, 4096);
        wprep_kernel<false><<<dim3(32, 32), 256>>>(uw + (size_t)l * 4194304, p_whi + lo + OUW, p_wlo + lo + OUW, 1024, 4096);
        wprep_kernel<true><<<dim3(8, 128), 256>>>(dw + (size_t)l * 4194304, p_whi + lo + ODW, p_wlo + lo + ODW, 4096, 1024);
    }
    wprep_kernel<false><<<dim3(250, 32), 256>>>(lm_w, p_whi + OLM, p_wlo + OLM, 1024, 32000);

    GemmSeg z = mkseg(nullptr, nullptr, nullptr, nullptr, 0, 0);

    rope_table_kernel<<<(S * 32 + 255) / 256, 256>>>();
    embed_kernel<<<(S * D / 4) / 256, 256>>>(embed, ids);

    for (int l = 0; l < LAYERS; l++) {
        size_t lo = (size_t)l * LSZ;
        rms_scale_kernel<<<S, 256>>>(p_h);
        asplit_kernel<2><<<dim3(16, 32), 256>>>(p_h, nullptr, ln1 + (size_t)l * D, 1024);
        {
            GemmSeg sq = mkseg(p_whi + lo + OQW, p_wlo + lo + OQW, qb + (size_t)l * HQ * HD, p_q, HQ * HD, 8);
            GemmSeg sk = mkseg(p_whi + lo + OKW, p_wlo + lo + OKW, kb + (size_t)l * KVH * HD, p_k, KVH * HD, 2);
            GemmSeg sv = mkseg(p_whi + lo + OVW, p_wlo + lo + OVW, vb + (size_t)l * KVH * HD, p_v, KVH * HD, 2);
            mm7_kernel<3><<<dim3(12, 16, 1), 256, SMEM7>>>(sq, sk, sv, D, 0);
        }
        rope_kernel<<<(S * HQ * 32) / 256, 256>>>(p_q, HQ);
        rope_kernel<<<(S * KVH * 32) / 256, 256>>>(p_k, KVH);
        attn_part_kernel<<<dim3(S / 128, HQ / 2, 3), 256>>>();
        attn_merge_kernel<<<(HQ * S * HD / 4) / 256, 256>>>();
        asplit_kernel<0><<<dim3(16, 32), 256>>>(p_o, nullptr, nullptr, 1024);
        {
            // O projection: 2-pass (hi*hi + loA*hi), split-K=2 atomic accum
            GemmSeg so = mkseg(p_whi + lo + OOW, p_wlo + lo + OOW, nullptr, p_h, D, 8);
            mm7_kernel<2><<<dim3(8, 16, 2), 256, SMEM7>>>(so, z, z, HQ * HD, 2);
        }
        rms_scale_kernel<<<S, 256>>>(p_h);
        asplit_kernel<2><<<dim3(16, 32), 256>>>(p_h, nullptr, ln2 + (size_t)l * D, 1024);
        {
            GemmSeg sg = mkseg(p_whi + lo + OGW, p_wlo + lo + OGW, nullptr, p_gate, II, 32);
            GemmSeg su = mkseg(p_whi + lo + OUW, p_wlo + lo + OUW, nullptr, p_up, II, 32);
            mm7_kernel<2><<<dim3(64, 16, 1), 256, SMEM7>>>(sg, su, z, D, 0);
        }
        asplit_kernel<1><<<dim3(16, 128), 256>>>(p_gate, p_up, nullptr, 4096);
        {
            GemmSeg sd = mkseg(p_whi + lo + ODW, p_wlo + lo + ODW, nullptr, p_h, D, 8);
            mm7_kernel<3><<<dim3(8, 16, 2), 256, SMEM7>>>(sd, z, z, II, 2);
        }
    }

    rms_scale_kernel<<<S, 256>>>(p_h);
    asplit_kernel<2><<<dim3(16, 32), 256>>>(p_h, nullptr, norm_w, 1024);
    {
        GemmSeg sl = mkseg(p_whi + OLM, p_wlo + OLM, nullptr, out, VV, 250);
        mm7_kernel<2><<<dim3(250, 16, 1), 256, SMEM7>>>(sl, z, z, D, 0);
    }
}